// round 6
// baseline (speedup 1.0000x reference)
#include <cuda_runtime.h>
#include <math.h>

// ---------------------------------------------------------------------------
// Problem constants
// ---------------------------------------------------------------------------
#define B_SZ 8
#define S_LEN 1024
#define D_MODEL 1024
#define N_HEADS 16
#define D_K 64
#define D_FF 4096
#define M_ROWS (B_SZ * S_LEN)   // 8192

// ---------------------------------------------------------------------------
// Scratch (device globals — allocation-free rule)
// ---------------------------------------------------------------------------
__device__ float g_q[(size_t)M_ROWS * D_MODEL];
__device__ float g_k[(size_t)M_ROWS * D_MODEL];
__device__ float g_v[(size_t)M_ROWS * D_MODEL];
__device__ float g_ctx[(size_t)M_ROWS * D_MODEL];
__device__ float g_mid[(size_t)M_ROWS * D_FF];

// ---------------------------------------------------------------------------
// GEMM: C[M,N] = A[M,K] @ W[K,N] + bias (optional ReLU)
// 128x128 tile, BK=16, 256 threads, 8x8 microtile
// ---------------------------------------------------------------------------
#define BM 128
#define BN 128
#define BK 16
#define TM 8
#define TN 8

template <bool RELU>
__global__ __launch_bounds__(256)
void gemm_bias(const float* __restrict__ A, const float* __restrict__ W,
               const float* __restrict__ bias, float* __restrict__ C,
               int M, int N, int K)
{
    __shared__ float As[BK][BM + 4];
    __shared__ float Bs[BK][BN];

    const int tid = threadIdx.x;
    const int m0 = blockIdx.y * BM;
    const int n0 = blockIdx.x * BN;
    const int tm = (tid >> 4) * TM;   // 0..120
    const int tn = (tid & 15) * TN;   // 0..120

    float acc[TM][TN];
#pragma unroll
    for (int i = 0; i < TM; i++)
#pragma unroll
        for (int j = 0; j < TN; j++) acc[i][j] = 0.f;

    for (int kt = 0; kt < K; kt += BK) {
        // load A tile (128 x 16) transposed into As[k][m]
#pragma unroll
        for (int t = 0; t < 2; t++) {
            int idx = tid + t * 256;        // 0..511
            int r = idx >> 2;               // 0..127
            int c4 = idx & 3;               // 0..3 (group of 4 k's)
            float4 v = *(const float4*)(A + (size_t)(m0 + r) * K + kt + c4 * 4);
            As[c4 * 4 + 0][r] = v.x;
            As[c4 * 4 + 1][r] = v.y;
            As[c4 * 4 + 2][r] = v.z;
            As[c4 * 4 + 3][r] = v.w;
        }
        // load B tile (16 x 128) straight
#pragma unroll
        for (int t = 0; t < 2; t++) {
            int idx = tid + t * 256;        // 0..511
            int r = idx >> 5;               // 0..15
            int c4 = idx & 31;              // 0..31
            *(float4*)(&Bs[r][c4 * 4]) =
                *(const float4*)(W + (size_t)(kt + r) * N + n0 + c4 * 4);
        }
        __syncthreads();

#pragma unroll
        for (int k = 0; k < BK; k++) {
            float a[TM], b[TN];
            *(float4*)(a)     = *(const float4*)(&As[k][tm]);
            *(float4*)(a + 4) = *(const float4*)(&As[k][tm + 4]);
            *(float4*)(b)     = *(const float4*)(&Bs[k][tn]);
            *(float4*)(b + 4) = *(const float4*)(&Bs[k][tn + 4]);
#pragma unroll
            for (int i = 0; i < TM; i++)
#pragma unroll
                for (int j = 0; j < TN; j++)
                    acc[i][j] = fmaf(a[i], b[j], acc[i][j]);
        }
        __syncthreads();
    }

    // epilogue: + bias (, ReLU), vectorized store
    float bv[TN];
    *(float4*)(bv)     = *(const float4*)(bias + n0 + tn);
    *(float4*)(bv + 4) = *(const float4*)(bias + n0 + tn + 4);
#pragma unroll
    for (int i = 0; i < TM; i++) {
        float4 o0, o1;
        o0.x = acc[i][0] + bv[0]; o0.y = acc[i][1] + bv[1];
        o0.z = acc[i][2] + bv[2]; o0.w = acc[i][3] + bv[3];
        o1.x = acc[i][4] + bv[4]; o1.y = acc[i][5] + bv[5];
        o1.z = acc[i][6] + bv[6]; o1.w = acc[i][7] + bv[7];
        if (RELU) {
            o0.x = fmaxf(o0.x, 0.f); o0.y = fmaxf(o0.y, 0.f);
            o0.z = fmaxf(o0.z, 0.f); o0.w = fmaxf(o0.w, 0.f);
            o1.x = fmaxf(o1.x, 0.f); o1.y = fmaxf(o1.y, 0.f);
            o1.z = fmaxf(o1.z, 0.f); o1.w = fmaxf(o1.w, 0.f);
        }
        size_t off = (size_t)(m0 + tm + i) * N + n0 + tn;
        *(float4*)(C + off)     = o0;
        *(float4*)(C + off + 4) = o1;
    }
}

// ---------------------------------------------------------------------------
// Flash-style causal attention (strict lower-triangular: key j < query i),
// first query row of each (b,h) zeroed (reference's zero_pad).
// Q,K,V,O layout: [b, s, h*64 + d] (row = b*1024+s, col = h*64+d).
// One CTA = 64 queries of one (b,h); loops key blocks kb = 0..qtile.
// ---------------------------------------------------------------------------
#define ATT_PAD 68   // 64 + 4 pad, keeps float4 alignment

__global__ __launch_bounds__(256)
void attention_kernel(const float* __restrict__ Q, const float* __restrict__ K,
                      const float* __restrict__ V, float* __restrict__ O)
{
    extern __shared__ float smem[];
    float* QsT = smem;                          // [64][68] (d-major: QsT[d][q])
    float* KsT = QsT + 64 * ATT_PAD;            // [64][68] (d-major: KsT[d][key])
    float* Vs  = KsT + 64 * ATT_PAD;            // [64][68] (key-major: Vs[key][d])
    float* Ss  = Vs  + 64 * ATT_PAD;            // [64][68] scores/probs row-major
    float* m_s = Ss + 64 * ATT_PAD;             // [64]
    float* l_s = m_s + 64;                      // [64]
    float* corr_s = l_s + 64;                   // [64]

    const int tid = threadIdx.x;
    const int qtile = blockIdx.x;               // 0..15
    const int bh = blockIdx.y;                  // 0..127
    const int b = bh >> 4;
    const int h = bh & 15;
    const int q0 = qtile * 64;

    const float* Qb = Q + (size_t)b * S_LEN * D_MODEL + h * D_K;
    const float* Kb = K + (size_t)b * S_LEN * D_MODEL + h * D_K;
    const float* Vb = V + (size_t)b * S_LEN * D_MODEL + h * D_K;
    float*       Ob = O + (size_t)b * S_LEN * D_MODEL + h * D_K;

    // load Q tile transposed: QsT[d][q]
#pragma unroll
    for (int t = 0; t < 4; t++) {
        int idx = tid + t * 256;                // 0..1023
        int r = idx >> 4;                       // query 0..63
        int c4 = idx & 15;                      // d group
        float4 v = *(const float4*)(Qb + (size_t)(q0 + r) * D_MODEL + c4 * 4);
        QsT[(c4 * 4 + 0) * ATT_PAD + r] = v.x;
        QsT[(c4 * 4 + 1) * ATT_PAD + r] = v.y;
        QsT[(c4 * 4 + 2) * ATT_PAD + r] = v.z;
        QsT[(c4 * 4 + 3) * ATT_PAD + r] = v.w;
    }
    if (tid < 64) { m_s[tid] = -INFINITY; l_s[tid] = 0.f; }

    const int tr = tid >> 4;    // 0..15 -> queries 4*tr..+3
    const int tc = tid & 15;    // 0..15 -> keys/dims 4*tc..+3
    float o[4][4];
#pragma unroll
    for (int i = 0; i < 4; i++)
#pragma unroll
        for (int j = 0; j < 4; j++) o[i][j] = 0.f;

    for (int kb = 0; kb <= qtile; kb++) {
        __syncthreads();   // protects Q/m/l init (1st iter) and WAR on tiles/Ss
        // load K transposed, V straight
#pragma unroll
        for (int t = 0; t < 4; t++) {
            int idx = tid + t * 256;
            int r = idx >> 4;
            int c4 = idx & 15;
            float4 kv = *(const float4*)(Kb + (size_t)(kb * 64 + r) * D_MODEL + c4 * 4);
            KsT[(c4 * 4 + 0) * ATT_PAD + r] = kv.x;
            KsT[(c4 * 4 + 1) * ATT_PAD + r] = kv.y;
            KsT[(c4 * 4 + 2) * ATT_PAD + r] = kv.z;
            KsT[(c4 * 4 + 3) * ATT_PAD + r] = kv.w;
            float4 vv = *(const float4*)(Vb + (size_t)(kb * 64 + r) * D_MODEL + c4 * 4);
            *(float4*)(&Vs[r * ATT_PAD + c4 * 4]) = vv;
        }
        __syncthreads();

        // Phase A: S = Q * K^T  (4x4 microtile per thread)
        float s[4][4];
#pragma unroll
        for (int i = 0; i < 4; i++)
#pragma unroll
            for (int j = 0; j < 4; j++) s[i][j] = 0.f;
#pragma unroll 8
        for (int d = 0; d < 64; d++) {
            float4 a4 = *(const float4*)(&QsT[d * ATT_PAD + 4 * tr]);
            float4 b4 = *(const float4*)(&KsT[d * ATT_PAD + 4 * tc]);
            float a[4] = {a4.x, a4.y, a4.z, a4.w};
            float bb[4] = {b4.x, b4.y, b4.z, b4.w};
#pragma unroll
            for (int i = 0; i < 4; i++)
#pragma unroll
                for (int j = 0; j < 4; j++)
                    s[i][j] = fmaf(a[i], bb[j], s[i][j]);
        }
        // scale + causal mask (only diagonal block needs masking)
#pragma unroll
        for (int i = 0; i < 4; i++) {
#pragma unroll
            for (int j = 0; j < 4; j++) {
                float val = s[i][j] * 0.125f;
                if (kb == qtile && (4 * tc + j) >= (4 * tr + i)) val = -1e30f;
                Ss[(4 * tr + i) * ATT_PAD + (4 * tc + j)] = val;
            }
        }
        __syncthreads();

        // Online softmax: row r handled by 4 threads (tid/4 == r)
        {
            int r = tid >> 2;
            int qd = tid & 3;
            float loc[16];
            *(float4*)(loc)      = *(const float4*)(&Ss[r * ATT_PAD + qd * 16]);
            *(float4*)(loc + 4)  = *(const float4*)(&Ss[r * ATT_PAD + qd * 16 + 4]);
            *(float4*)(loc + 8)  = *(const float4*)(&Ss[r * ATT_PAD + qd * 16 + 8]);
            *(float4*)(loc + 12) = *(const float4*)(&Ss[r * ATT_PAD + qd * 16 + 12]);
            float mx = loc[0];
#pragma unroll
            for (int u = 1; u < 16; u++) mx = fmaxf(mx, loc[u]);
            mx = fmaxf(mx, __shfl_xor_sync(0xffffffffu, mx, 1));
            mx = fmaxf(mx, __shfl_xor_sync(0xffffffffu, mx, 2));
            float m_old = m_s[r];
            float m_new = fmaxf(m_old, mx);
            float sum = 0.f;
#pragma unroll
            for (int u = 0; u < 16; u++) {
                loc[u] = __expf(loc[u] - m_new);
                sum += loc[u];
            }
            sum += __shfl_xor_sync(0xffffffffu, sum, 1);
            sum += __shfl_xor_sync(0xffffffffu, sum, 2);
            *(float4*)(&Ss[r * ATT_PAD + qd * 16])      = *(float4*)(loc);
            *(float4*)(&Ss[r * ATT_PAD + qd * 16 + 4])  = *(float4*)(loc + 4);
            *(float4*)(&Ss[r * ATT_PAD + qd * 16 + 8])  = *(float4*)(loc + 8);
            *(float4*)(&Ss[r * ATT_PAD + qd * 16 + 12]) = *(float4*)(loc + 12);
            if (qd == 0) {
                float c = __expf(m_old - m_new);   // exp(-inf)=0 on first block
                corr_s[r] = c;
                l_s[r] = l_s[r] * c + sum;
                m_s[r] = m_new;
            }
        }
        __syncthreads();

        // Phase B: O = O*corr + P @ V
#pragma unroll
        for (int i = 0; i < 4; i++) {
            float c = corr_s[4 * tr + i];
#pragma unroll
            for (int j = 0; j < 4; j++) o[i][j] *= c;
        }
#pragma unroll 8
        for (int jj = 0; jj < 64; jj++) {
            float p[4];
#pragma unroll
            for (int i = 0; i < 4; i++) p[i] = Ss[(4 * tr + i) * ATT_PAD + jj];
            float4 vv = *(const float4*)(&Vs[jj * ATT_PAD + 4 * tc]);
#pragma unroll
            for (int i = 0; i < 4; i++) {
                o[i][0] = fmaf(p[i], vv.x, o[i][0]);
                o[i][1] = fmaf(p[i], vv.y, o[i][1]);
                o[i][2] = fmaf(p[i], vv.z, o[i][2]);
                o[i][3] = fmaf(p[i], vv.w, o[i][3]);
            }
        }
    }
    __syncthreads();

    // finalize: divide by l, zero global row 0 (reference zero_pad), store
#pragma unroll
    for (int i = 0; i < 4; i++) {
        int q = 4 * tr + i;
        int gi = q0 + q;
        float inv = 1.f / l_s[q];
        float4 out;
        out.x = o[i][0] * inv; out.y = o[i][1] * inv;
        out.z = o[i][2] * inv; out.w = o[i][3] * inv;
        if (gi == 0) { out.x = 0.f; out.y = 0.f; out.z = 0.f; out.w = 0.f; }
        *(float4*)(Ob + (size_t)gi * D_MODEL + 4 * tc) = out;
    }
}

// ---------------------------------------------------------------------------
// Fused residual add + LayerNorm over last dim (1024). One CTA per row.
// ---------------------------------------------------------------------------
__global__ __launch_bounds__(256)
void add_ln_kernel(const float* __restrict__ A, const float* __restrict__ Bm,
                   const float* __restrict__ g, const float* __restrict__ beta,
                   float* __restrict__ out)
{
    __shared__ float red_s[8];
    __shared__ float red_q[8];
    __shared__ float stats[2];

    const int row = blockIdx.x;
    const int c = threadIdx.x * 4;
    const float* a = A + (size_t)row * D_MODEL;
    const float* bm = Bm + (size_t)row * D_MODEL;

    float4 av = *(const float4*)(a + c);
    float4 bv = *(const float4*)(bm + c);
    float v0 = av.x + bv.x, v1 = av.y + bv.y, v2 = av.z + bv.z, v3 = av.w + bv.w;

    float s = v0 + v1 + v2 + v3;
    float q = v0 * v0 + v1 * v1 + v2 * v2 + v3 * v3;
#pragma unroll
    for (int off = 16; off > 0; off >>= 1) {
        s += __shfl_xor_sync(0xffffffffu, s, off);
        q += __shfl_xor_sync(0xffffffffu, q, off);
    }
    if ((threadIdx.x & 31) == 0) {
        red_s[threadIdx.x >> 5] = s;
        red_q[threadIdx.x >> 5] = q;
    }
    __syncthreads();
    if (threadIdx.x < 32) {
        float ts = (threadIdx.x < 8) ? red_s[threadIdx.x] : 0.f;
        float tq = (threadIdx.x < 8) ? red_q[threadIdx.x] : 0.f;
#pragma unroll
        for (int off = 4; off > 0; off >>= 1) {
            ts += __shfl_xor_sync(0xffffffffu, ts, off);
            tq += __shfl_xor_sync(0xffffffffu, tq, off);
        }
        if (threadIdx.x == 0) {
            float mu = ts * (1.f / D_MODEL);
            float var = tq * (1.f / D_MODEL) - mu * mu;
            var = fmaxf(var, 0.f);
            stats[0] = mu;
            stats[1] = rsqrtf(var + 1e-5f);
        }
    }
    __syncthreads();
    const float mu = stats[0];
    const float rstd = stats[1];

    float4 gv = *(const float4*)(g + c);
    float4 bev = *(const float4*)(beta + c);
    float4 ov;
    ov.x = (v0 - mu) * rstd * gv.x + bev.x;
    ov.y = (v1 - mu) * rstd * gv.y + bev.y;
    ov.z = (v2 - mu) * rstd * gv.z + bev.z;
    ov.w = (v3 - mu) * rstd * gv.w + bev.w;
    *(float4*)(out + (size_t)row * D_MODEL + c) = ov;
}

// ---------------------------------------------------------------------------
// Launch
// ---------------------------------------------------------------------------
extern "C" void kernel_launch(void* const* d_in, const int* in_sizes, int n_in,
                              void* d_out, int out_size)
{
    const float* x   = (const float*)d_in[0];
    const float* Wq  = (const float*)d_in[1];
    const float* bq  = (const float*)d_in[2];
    const float* Wk  = (const float*)d_in[3];
    const float* bk  = (const float*)d_in[4];
    const float* Wv  = (const float*)d_in[5];
    const float* bv  = (const float*)d_in[6];
    const float* Wo  = (const float*)d_in[7];
    const float* bo  = (const float*)d_in[8];
    const float* W1  = (const float*)d_in[9];
    const float* b1  = (const float*)d_in[10];
    const float* W2  = (const float*)d_in[11];
    const float* b2  = (const float*)d_in[12];
    const float* g1  = (const float*)d_in[13];
    const float* be1 = (const float*)d_in[14];
    const float* g3  = (const float*)d_in[15];
    const float* be3 = (const float*)d_in[16];
    float* out = (float*)d_out;

    void *pq, *pk, *pv, *pctx, *pmid;
    cudaGetSymbolAddress(&pq, g_q);
    cudaGetSymbolAddress(&pk, g_k);
    cudaGetSymbolAddress(&pv, g_v);
    cudaGetSymbolAddress(&pctx, g_ctx);
    cudaGetSymbolAddress(&pmid, g_mid);
    float* q   = (float*)pq;
    float* k   = (float*)pk;
    float* v   = (float*)pv;
    float* ctx = (float*)pctx;
    float* mid = (float*)pmid;

    const int att_smem = (4 * 64 * ATT_PAD + 3 * 64) * (int)sizeof(float);
    cudaFuncSetAttribute(attention_kernel,
                         cudaFuncAttributeMaxDynamicSharedMemorySize, att_smem);

    dim3 gProj(D_MODEL / BN, M_ROWS / BM);     // (8, 64)
    dim3 gFF1(D_FF / BN, M_ROWS / BM);         // (32, 64)

    // QKV projections
    gemm_bias<false><<<gProj, 256>>>(x, Wq, bq, q, M_ROWS, D_MODEL, D_MODEL);
    gemm_bias<false><<<gProj, 256>>>(x, Wk, bk, k, M_ROWS, D_MODEL, D_MODEL);
    gemm_bias<false><<<gProj, 256>>>(x, Wv, bv, v, M_ROWS, D_MODEL, D_MODEL);

    // causal attention -> ctx ([b,s,h,d] == concat layout)
    attention_kernel<<<dim3(S_LEN / 64, B_SZ * N_HEADS), 256, att_smem>>>(q, k, v, ctx);

    // output projection (reuse q as attn_out)
    gemm_bias<false><<<gProj, 256>>>(ctx, Wo, bo, q, M_ROWS, D_MODEL, D_MODEL);

    // h1 = LN(x + attn_out)  (reuse k as h1)
    add_ln_kernel<<<M_ROWS, 256>>>(x, q, g1, be1, k);

    // FFN
    gemm_bias<true><<<gFF1, 256>>>(k, W1, b1, mid, M_ROWS, D_FF, D_MODEL);
    gemm_bias<false><<<gProj, 256>>>(mid, W2, b2, v, M_ROWS, D_MODEL, D_FF);

    // out = LN(h1 + ffn)
    add_ln_kernel<<<M_ROWS, 256>>>(k, v, g3, be3, out);
}

// round 9
// speedup vs baseline: 1.8281x; 1.8281x over previous
#include <cuda_runtime.h>
#include <cuda_bf16.h>
#include <math.h>
#include <stdint.h>

// ---------------------------------------------------------------------------
// Problem constants
// ---------------------------------------------------------------------------
#define B_SZ 8
#define S_LEN 1024
#define D_MODEL 1024
#define N_HEADS 16
#define D_K 64
#define D_FF 4096
#define M_ROWS (B_SZ * S_LEN)   // 8192

// single dynamic-smem symbol shared by all kernels (typed locally)
extern __shared__ char dyn_smem[];

// ---------------------------------------------------------------------------
// Scratch (device globals — allocation-free rule)
// ---------------------------------------------------------------------------
__device__ float g_q[(size_t)M_ROWS * D_MODEL];
__device__ float g_k[(size_t)M_ROWS * D_MODEL];
__device__ float g_v[(size_t)M_ROWS * D_MODEL];
__device__ float g_ctx[(size_t)M_ROWS * D_MODEL];
__device__ float g_h1[(size_t)M_ROWS * D_MODEL];
__device__ float g_mid[(size_t)M_ROWS * D_FF];

// activation bf16 splits (sized for the largest: mid = 8192x4096)
__device__ __nv_bfloat16 g_ah[(size_t)M_ROWS * D_FF];
__device__ __nv_bfloat16 g_al[(size_t)M_ROWS * D_FF];

// transposed+split weights [N,K] bf16
__device__ __nv_bfloat16 g_wq_h[(size_t)D_MODEL * D_MODEL];
__device__ __nv_bfloat16 g_wq_l[(size_t)D_MODEL * D_MODEL];
__device__ __nv_bfloat16 g_wk_h[(size_t)D_MODEL * D_MODEL];
__device__ __nv_bfloat16 g_wk_l[(size_t)D_MODEL * D_MODEL];
__device__ __nv_bfloat16 g_wv_h[(size_t)D_MODEL * D_MODEL];
__device__ __nv_bfloat16 g_wv_l[(size_t)D_MODEL * D_MODEL];
__device__ __nv_bfloat16 g_wo_h[(size_t)D_MODEL * D_MODEL];
__device__ __nv_bfloat16 g_wo_l[(size_t)D_MODEL * D_MODEL];
__device__ __nv_bfloat16 g_w1_h[(size_t)D_FF * D_MODEL];
__device__ __nv_bfloat16 g_w1_l[(size_t)D_FF * D_MODEL];
__device__ __nv_bfloat16 g_w2_h[(size_t)D_MODEL * D_FF];
__device__ __nv_bfloat16 g_w2_l[(size_t)D_MODEL * D_FF];

// ---------------------------------------------------------------------------
// PTX helpers (portable: mma.sync + cp.async, no sm_103a-only instructions)
// ---------------------------------------------------------------------------
static __device__ __forceinline__ uint32_t smem_u32(const void* p) {
    uint32_t a;
    asm("{ .reg .u64 t; cvta.to.shared.u64 t, %1; cvt.u32.u64 %0, t; }"
        : "=r"(a) : "l"(p));
    return a;
}

#define CP_ASYNC16(dst, src) \
    asm volatile("cp.async.cg.shared.global [%0], [%1], 16;" \
                 :: "r"((uint32_t)(dst)), "l"(src))
#define CP_COMMIT() asm volatile("cp.async.commit_group;" ::: "memory")

// D += A * B  (m16n8k16, bf16 in, fp32 accum)
static __device__ __forceinline__ void mma16816(
    float* d, const uint32_t* a, uint32_t b0, uint32_t b1)
{
    asm volatile(
        "mma.sync.aligned.m16n8k16.row.col.f32.bf16.bf16.f32 "
        "{%0,%1,%2,%3}, {%4,%5,%6,%7}, {%8,%9}, {%0,%1,%2,%3};"
        : "+f"(d[0]), "+f"(d[1]), "+f"(d[2]), "+f"(d[3])
        : "r"(a[0]), "r"(a[1]), "r"(a[2]), "r"(a[3]), "r"(b0), "r"(b1));
}

// ---------------------------------------------------------------------------
// mma.sync GEMM:  C[M,N] = (Ah+Al)[M,K] @ (Bh+Bl)^T  (B stored [N,K]) + bias
// CTA tile 128x128, BK=32, 256 threads (8 warps, 2m x 4n grid, warp tile 64x32)
// 3-term bf16 split: AhBh + AhBl + AlBh, fp32 accum.
// 3-buffer cp.async pipeline (2-chunk lookahead).
// smem tile layout: 128 rows x 32 bf16, row stride 80 bytes (64 data + 16 pad)
// buffer = Ah(10240) Al(10240) Bh(10240) Bl(10240) = 40960 B; 3 bufs = 122880 B
// ---------------------------------------------------------------------------
#define GM_BUFSZ 40960
#define GM_SMEM  (3 * GM_BUFSZ)

static __device__ __forceinline__ void load_chunk(
    uint32_t sdst, const __nv_bfloat16* aH, const __nv_bfloat16* aL,
    const __nv_bfloat16* bH, const __nv_bfloat16* bL,
    int kb, int K, int tid)
{
#pragma unroll
    for (int j = 0; j < 2; j++) {
        int idx = tid + j * 256;          // 0..511
        int r = idx >> 2;                 // row 0..127
        int s = idx & 3;                  // 16B segment 0..3
        uint32_t doff = (uint32_t)(r * 80 + s * 16);
        size_t goff = (size_t)r * K + kb; // elements
        CP_ASYNC16(sdst + doff,         (const char*)(aH + goff) + s * 16);
        CP_ASYNC16(sdst + 10240 + doff, (const char*)(aL + goff) + s * 16);
        CP_ASYNC16(sdst + 20480 + doff, (const char*)(bH + goff) + s * 16);
        CP_ASYNC16(sdst + 30720 + doff, (const char*)(bL + goff) + s * 16);
    }
}

template <bool RELU>
__global__ __launch_bounds__(256, 1)
void gemm_mma(const __nv_bfloat16* __restrict__ Ah, const __nv_bfloat16* __restrict__ Al,
              const __nv_bfloat16* __restrict__ Bh, const __nv_bfloat16* __restrict__ Bl,
              const float* __restrict__ bias, float* __restrict__ C,
              int M, int N, int K)
{
    const uint32_t sbase = smem_u32(dyn_smem);
    const char* sm = dyn_smem;
    const int tid = threadIdx.x;
    const int wid = tid >> 5;
    const int lane = tid & 31;
    const int gid = lane >> 2;        // group id 0..7
    const int tig = lane & 3;         // thread in group 0..3
    const int n0 = blockIdx.x * 128;
    const int m0 = blockIdx.y * 128;
    const int wm = (wid >> 2) * 64;   // warp m offset in CTA tile
    const int wn = (wid & 3) * 32;    // warp n offset
    const int nch = K >> 5;

    const __nv_bfloat16* aH = Ah + (size_t)m0 * K;
    const __nv_bfloat16* aL = Al + (size_t)m0 * K;
    const __nv_bfloat16* bH = Bh + (size_t)n0 * K;
    const __nv_bfloat16* bL = Bl + (size_t)n0 * K;

    float acc[4][4][4];
#pragma unroll
    for (int mt = 0; mt < 4; mt++)
#pragma unroll
        for (int nt = 0; nt < 4; nt++)
#pragma unroll
            for (int u = 0; u < 4; u++) acc[mt][nt][u] = 0.f;

    // prologue: chunks 0, 1
    load_chunk(sbase,            aH, aL, bH, bL, 0,  K, tid);
    CP_COMMIT();
    load_chunk(sbase + GM_BUFSZ, aH, aL, bH, bL, 32, K, tid);
    CP_COMMIT();

    for (int ch = 0; ch < nch; ch++) {
        if (ch == nch - 1) asm volatile("cp.async.wait_group 0;" ::: "memory");
        else               asm volatile("cp.async.wait_group 1;" ::: "memory");
        __syncthreads();

        // prefetch chunk ch+2 into buffer (ch+2)%3 (freed by compute of ch-1)
        if (ch + 2 < nch) {
            load_chunk(sbase + ((ch + 2) % 3) * GM_BUFSZ,
                       aH, aL, bH, bL, (ch + 2) * 32, K, tid);
            CP_COMMIT();
        }

        const char* buf = sm + (ch % 3) * GM_BUFSZ;
        const char* pAh = buf;
        const char* pAl = buf + 10240;
        const char* pBh = buf + 20480;
        const char* pBl = buf + 30720;

#pragma unroll
        for (int kk = 0; kk < 2; kk++) {      // two k16 steps per BK=32 chunk
            uint32_t ahf[4][4], alf[4][4];
#pragma unroll
            for (int mt = 0; mt < 4; mt++) {
                int base = (wm + mt * 16 + gid) * 80 + kk * 32 + tig * 4;
                ahf[mt][0] = *(const uint32_t*)(pAh + base);
                ahf[mt][1] = *(const uint32_t*)(pAh + base + 640);
                ahf[mt][2] = *(const uint32_t*)(pAh + base + 16);
                ahf[mt][3] = *(const uint32_t*)(pAh + base + 656);
                alf[mt][0] = *(const uint32_t*)(pAl + base);
                alf[mt][1] = *(const uint32_t*)(pAl + base + 640);
                alf[mt][2] = *(const uint32_t*)(pAl + base + 16);
                alf[mt][3] = *(const uint32_t*)(pAl + base + 656);
            }
#pragma unroll
            for (int nt = 0; nt < 4; nt++) {
                int bbase = (wn + nt * 8 + gid) * 80 + kk * 32 + tig * 4;
                uint32_t bh0 = *(const uint32_t*)(pBh + bbase);
                uint32_t bh1 = *(const uint32_t*)(pBh + bbase + 16);
                uint32_t bl0 = *(const uint32_t*)(pBl + bbase);
                uint32_t bl1 = *(const uint32_t*)(pBl + bbase + 16);
#pragma unroll
                for (int mt = 0; mt < 4; mt++) {
                    mma16816(acc[mt][nt], ahf[mt], bh0, bh1);  // hi*hi
                    mma16816(acc[mt][nt], ahf[mt], bl0, bl1);  // hi*lo
                    mma16816(acc[mt][nt], alf[mt], bh0, bh1);  // lo*hi
                }
            }
        }
    }

    // epilogue: + bias (, ReLU), store
#pragma unroll
    for (int mt = 0; mt < 4; mt++) {
        int r0 = m0 + wm + mt * 16 + gid;
#pragma unroll
        for (int nt = 0; nt < 4; nt++) {
            int c0 = n0 + wn + nt * 8 + tig * 2;
            float bb0 = bias[c0], bb1 = bias[c0 + 1];
            float v0 = acc[mt][nt][0] + bb0;
            float v1 = acc[mt][nt][1] + bb1;
            float v2 = acc[mt][nt][2] + bb0;
            float v3 = acc[mt][nt][3] + bb1;
            if (RELU) {
                v0 = fmaxf(v0, 0.f); v1 = fmaxf(v1, 0.f);
                v2 = fmaxf(v2, 0.f); v3 = fmaxf(v3, 0.f);
            }
            float2 lo = make_float2(v0, v1);
            float2 hi = make_float2(v2, v3);
            *(float2*)(C + (size_t)r0 * N + c0)       = lo;
            *(float2*)(C + (size_t)(r0 + 8) * N + c0) = hi;
        }
    }
}

// ---------------------------------------------------------------------------
// fp32 -> bf16 hi/lo split (elementwise)
// ---------------------------------------------------------------------------
__global__ __launch_bounds__(256)
void split_bf16(const float4* __restrict__ in,
                __nv_bfloat162* __restrict__ h2, __nv_bfloat162* __restrict__ l2,
                int n4)
{
    int i = blockIdx.x * 256 + threadIdx.x;
    if (i >= n4) return;
    float4 v = in[i];
    __nv_bfloat16 h0 = __float2bfloat16(v.x);
    __nv_bfloat16 h1 = __float2bfloat16(v.y);
    __nv_bfloat16 h2v = __float2bfloat16(v.z);
    __nv_bfloat16 h3 = __float2bfloat16(v.w);
    __nv_bfloat16 l0 = __float2bfloat16(v.x - __bfloat162float(h0));
    __nv_bfloat16 l1 = __float2bfloat16(v.y - __bfloat162float(h1));
    __nv_bfloat16 l2v = __float2bfloat16(v.z - __bfloat162float(h2v));
    __nv_bfloat16 l3 = __float2bfloat16(v.w - __bfloat162float(h3));
    h2[2 * i]     = __nv_bfloat162(h0, h1);
    h2[2 * i + 1] = __nv_bfloat162(h2v, h3);
    l2[2 * i]     = __nv_bfloat162(l0, l1);
    l2[2 * i + 1] = __nv_bfloat162(l2v, l3);
}

// ---------------------------------------------------------------------------
// W[K,N] fp32 -> transposed hi/lo bf16 [N,K]
// ---------------------------------------------------------------------------
__global__ __launch_bounds__(256)
void transpose_split(const float* __restrict__ W,
                     __nv_bfloat16* __restrict__ Th, __nv_bfloat16* __restrict__ Tl,
                     int K, int N)
{
    __shared__ float tile[32][33];
    const int tx = threadIdx.x & 31;
    const int ty = threadIdx.x >> 5;   // 0..7
    const int n0 = blockIdx.x * 32;
    const int k0 = blockIdx.y * 32;
#pragma unroll
    for (int j = 0; j < 4; j++)
        tile[ty + 8 * j][tx] = W[(size_t)(k0 + ty + 8 * j) * N + n0 + tx];
    __syncthreads();
#pragma unroll
    for (int j = 0; j < 4; j++) {
        float v = tile[tx][ty + 8 * j];
        __nv_bfloat16 h = __float2bfloat16(v);
        __nv_bfloat16 l = __float2bfloat16(v - __bfloat162float(h));
        size_t o = (size_t)(n0 + ty + 8 * j) * K + k0 + tx;
        Th[o] = h;
        Tl[o] = l;
    }
}

// ---------------------------------------------------------------------------
// Flash-style causal attention (unchanged from passing R6 kernel)
// ---------------------------------------------------------------------------
#define ATT_PAD 68

__global__ __launch_bounds__(256)
void attention_kernel(const float* __restrict__ Q, const float* __restrict__ K,
                      const float* __restrict__ V, float* __restrict__ O)
{
    float* smem = (float*)dyn_smem;
    float* QsT = smem;
    float* KsT = QsT + 64 * ATT_PAD;
    float* Vs  = KsT + 64 * ATT_PAD;
    float* Ss  = Vs  + 64 * ATT_PAD;
    float* m_s = Ss + 64 * ATT_PAD;
    float* l_s = m_s + 64;
    float* corr_s = l_s + 64;

    const int tid = threadIdx.x;
    const int qtile = blockIdx.x;
    const int bh = blockIdx.y;
    const int b = bh >> 4;
    const int h = bh & 15;
    const int q0 = qtile * 64;

    const float* Qb = Q + (size_t)b * S_LEN * D_MODEL + h * D_K;
    const float* Kb = K + (size_t)b * S_LEN * D_MODEL + h * D_K;
    const float* Vb = V + (size_t)b * S_LEN * D_MODEL + h * D_K;
    float*       Ob = O + (size_t)b * S_LEN * D_MODEL + h * D_K;

#pragma unroll
    for (int t = 0; t < 4; t++) {
        int idx = tid + t * 256;
        int r = idx >> 4;
        int c4 = idx & 15;
        float4 v = *(const float4*)(Qb + (size_t)(q0 + r) * D_MODEL + c4 * 4);
        QsT[(c4 * 4 + 0) * ATT_PAD + r] = v.x;
        QsT[(c4 * 4 + 1) * ATT_PAD + r] = v.y;
        QsT[(c4 * 4 + 2) * ATT_PAD + r] = v.z;
        QsT[(c4 * 4 + 3) * ATT_PAD + r] = v.w;
    }
    if (tid < 64) { m_s[tid] = -INFINITY; l_s[tid] = 0.f; }

    const int tr = tid >> 4;
    const int tc = tid & 15;
    float o[4][4];
#pragma unroll
    for (int i = 0; i < 4; i++)
#pragma unroll
        for (int j = 0; j < 4; j++) o[i][j] = 0.f;

    for (int kb = 0; kb <= qtile; kb++) {
        __syncthreads();
#pragma unroll
        for (int t = 0; t < 4; t++) {
            int idx = tid + t * 256;
            int r = idx >> 4;
            int c4 = idx & 15;
            float4 kv = *(const float4*)(Kb + (size_t)(kb * 64 + r) * D_MODEL + c4 * 4);
            KsT[(c4 * 4 + 0) * ATT_PAD + r] = kv.x;
            KsT[(c4 * 4 + 1) * ATT_PAD + r] = kv.y;
            KsT[(c4 * 4 + 2) * ATT_PAD + r] = kv.z;
            KsT[(c4 * 4 + 3) * ATT_PAD + r] = kv.w;
            float4 vv = *(const float4*)(Vb + (size_t)(kb * 64 + r) * D_MODEL + c4 * 4);
            *(float4*)(&Vs[r * ATT_PAD + c4 * 4]) = vv;
        }
        __syncthreads();

        float s[4][4];
#pragma unroll
        for (int i = 0; i < 4; i++)
#pragma unroll
            for (int j = 0; j < 4; j++) s[i][j] = 0.f;
#pragma unroll 8
        for (int d = 0; d < 64; d++) {
            float4 a4 = *(const float4*)(&QsT[d * ATT_PAD + 4 * tr]);
            float4 b4 = *(const float4*)(&KsT[d * ATT_PAD + 4 * tc]);
            float a[4] = {a4.x, a4.y, a4.z, a4.w};
            float bb[4] = {b4.x, b4.y, b4.z, b4.w};
#pragma unroll
            for (int i = 0; i < 4; i++)
#pragma unroll
                for (int j = 0; j < 4; j++)
                    s[i][j] = fmaf(a[i], bb[j], s[i][j]);
        }
#pragma unroll
        for (int i = 0; i < 4; i++) {
#pragma unroll
            for (int j = 0; j < 4; j++) {
                float val = s[i][j] * 0.125f;
                if (kb == qtile && (4 * tc + j) >= (4 * tr + i)) val = -1e30f;
                Ss[(4 * tr + i) * ATT_PAD + (4 * tc + j)] = val;
            }
        }
        __syncthreads();

        {
            int r = tid >> 2;
            int qd = tid & 3;
            float loc[16];
            *(float4*)(loc)      = *(const float4*)(&Ss[r * ATT_PAD + qd * 16]);
            *(float4*)(loc + 4)  = *(const float4*)(&Ss[r * ATT_PAD + qd * 16 + 4]);
            *(float4*)(loc + 8)  = *(const float4*)(&Ss[r * ATT_PAD + qd * 16 + 8]);
            *(float4*)(loc + 12) = *(const float4*)(&Ss[r * ATT_PAD + qd * 16 + 12]);
            float mx = loc[0];
#pragma unroll
            for (int u = 1; u < 16; u++) mx = fmaxf(mx, loc[u]);
            mx = fmaxf(mx, __shfl_xor_sync(0xffffffffu, mx, 1));
            mx = fmaxf(mx, __shfl_xor_sync(0xffffffffu, mx, 2));
            float m_old = m_s[r];
            float m_new = fmaxf(m_old, mx);
            float sum = 0.f;
#pragma unroll
            for (int u = 0; u < 16; u++) {
                loc[u] = __expf(loc[u] - m_new);
                sum += loc[u];
            }
            sum += __shfl_xor_sync(0xffffffffu, sum, 1);
            sum += __shfl_xor_sync(0xffffffffu, sum, 2);
            *(float4*)(&Ss[r * ATT_PAD + qd * 16])      = *(float4*)(loc);
            *(float4*)(&Ss[r * ATT_PAD + qd * 16 + 4])  = *(float4*)(loc + 4);
            *(float4*)(&Ss[r * ATT_PAD + qd * 16 + 8])  = *(float4*)(loc + 8);
            *(float4*)(&Ss[r * ATT_PAD + qd * 16 + 12]) = *(float4*)(loc + 12);
            if (qd == 0) {
                float c = __expf(m_old - m_new);
                corr_s[r] = c;
                l_s[r] = l_s[r] * c + sum;
                m_s[r] = m_new;
            }
        }
        __syncthreads();

#pragma unroll
        for (int i = 0; i < 4; i++) {
            float c = corr_s[4 * tr + i];
#pragma unroll
            for (int j = 0; j < 4; j++) o[i][j] *= c;
        }
#pragma unroll 8
        for (int jj = 0; jj < 64; jj++) {
            float p[4];
#pragma unroll
            for (int i = 0; i < 4; i++) p[i] = Ss[(4 * tr + i) * ATT_PAD + jj];
            float4 vv = *(const float4*)(&Vs[jj * ATT_PAD + 4 * tc]);
#pragma unroll
            for (int i = 0; i < 4; i++) {
                o[i][0] = fmaf(p[i], vv.x, o[i][0]);
                o[i][1] = fmaf(p[i], vv.y, o[i][1]);
                o[i][2] = fmaf(p[i], vv.z, o[i][2]);
                o[i][3] = fmaf(p[i], vv.w, o[i][3]);
            }
        }
    }
    __syncthreads();

#pragma unroll
    for (int i = 0; i < 4; i++) {
        int q = 4 * tr + i;
        int gi = q0 + q;
        float inv = 1.f / l_s[q];
        float4 out;
        out.x = o[i][0] * inv; out.y = o[i][1] * inv;
        out.z = o[i][2] * inv; out.w = o[i][3] * inv;
        if (gi == 0) { out.x = 0.f; out.y = 0.f; out.z = 0.f; out.w = 0.f; }
        *(float4*)(Ob + (size_t)gi * D_MODEL + 4 * tc) = out;
    }
}

// ---------------------------------------------------------------------------
// Fused residual add + LayerNorm
// ---------------------------------------------------------------------------
__global__ __launch_bounds__(256)
void add_ln_kernel(const float* __restrict__ A, const float* __restrict__ Bm,
                   const float* __restrict__ g, const float* __restrict__ beta,
                   float* __restrict__ out)
{
    __shared__ float red_s[8];
    __shared__ float red_q[8];
    __shared__ float stats[2];

    const int row = blockIdx.x;
    const int c = threadIdx.x * 4;
    const float* a = A + (size_t)row * D_MODEL;
    const float* bm = Bm + (size_t)row * D_MODEL;

    float4 av = *(const float4*)(a + c);
    float4 bv = *(const float4*)(bm + c);
    float v0 = av.x + bv.x, v1 = av.y + bv.y, v2 = av.z + bv.z, v3 = av.w + bv.w;

    float s = v0 + v1 + v2 + v3;
    float q = v0 * v0 + v1 * v1 + v2 * v2 + v3 * v3;
#pragma unroll
    for (int off = 16; off > 0; off >>= 1) {
        s += __shfl_xor_sync(0xffffffffu, s, off);
        q += __shfl_xor_sync(0xffffffffu, q, off);
    }
    if ((threadIdx.x & 31) == 0) {
        red_s[threadIdx.x >> 5] = s;
        red_q[threadIdx.x >> 5] = q;
    }
    __syncthreads();
    if (threadIdx.x < 32) {
        float ts = (threadIdx.x < 8) ? red_s[threadIdx.x] : 0.f;
        float tq = (threadIdx.x < 8) ? red_q[threadIdx.x] : 0.f;
#pragma unroll
        for (int off = 4; off > 0; off >>= 1) {
            ts += __shfl_xor_sync(0xffffffffu, ts, off);
            tq += __shfl_xor_sync(0xffffffffu, tq, off);
        }
        if (threadIdx.x == 0) {
            float mu = ts * (1.f / D_MODEL);
            float var = tq * (1.f / D_MODEL) - mu * mu;
            var = fmaxf(var, 0.f);
            stats[0] = mu;
            stats[1] = rsqrtf(var + 1e-5f);
        }
    }
    __syncthreads();
    const float mu = stats[0];
    const float rstd = stats[1];

    float4 gv = *(const float4*)(g + c);
    float4 bev = *(const float4*)(beta + c);
    float4 ov;
    ov.x = (v0 - mu) * rstd * gv.x + bev.x;
    ov.y = (v1 - mu) * rstd * gv.y + bev.y;
    ov.z = (v2 - mu) * rstd * gv.z + bev.z;
    ov.w = (v3 - mu) * rstd * gv.w + bev.w;
    *(float4*)(out + (size_t)row * D_MODEL + c) = ov;
}

// ---------------------------------------------------------------------------
// Launch
// ---------------------------------------------------------------------------
static inline float* sym(const void* s) {
    void* p = nullptr;
    cudaGetSymbolAddress(&p, s);
    return (float*)p;
}

extern "C" void kernel_launch(void* const* d_in, const int* in_sizes, int n_in,
                              void* d_out, int out_size)
{
    const float* x   = (const float*)d_in[0];
    const float* Wq  = (const float*)d_in[1];
    const float* bq  = (const float*)d_in[2];
    const float* Wk  = (const float*)d_in[3];
    const float* bk  = (const float*)d_in[4];
    const float* Wv  = (const float*)d_in[5];
    const float* bv  = (const float*)d_in[6];
    const float* Wo  = (const float*)d_in[7];
    const float* bo  = (const float*)d_in[8];
    const float* W1  = (const float*)d_in[9];
    const float* b1  = (const float*)d_in[10];
    const float* W2  = (const float*)d_in[11];
    const float* b2  = (const float*)d_in[12];
    const float* g1  = (const float*)d_in[13];
    const float* be1 = (const float*)d_in[14];
    const float* g3  = (const float*)d_in[15];
    const float* be3 = (const float*)d_in[16];
    float* out = (float*)d_out;

    float* q   = sym(g_q);
    float* k   = sym(g_k);
    float* v   = sym(g_v);
    float* ctx = sym(g_ctx);
    float* h1  = sym(g_h1);
    float* mid = sym(g_mid);
    __nv_bfloat16* ah = (__nv_bfloat16*)sym(g_ah);
    __nv_bfloat16* al = (__nv_bfloat16*)sym(g_al);
    __nv_bfloat16* wqh = (__nv_bfloat16*)sym(g_wq_h);
    __nv_bfloat16* wql = (__nv_bfloat16*)sym(g_wq_l);
    __nv_bfloat16* wkh = (__nv_bfloat16*)sym(g_wk_h);
    __nv_bfloat16* wkl = (__nv_bfloat16*)sym(g_wk_l);
    __nv_bfloat16* wvh = (__nv_bfloat16*)sym(g_wv_h);
    __nv_bfloat16* wvl = (__nv_bfloat16*)sym(g_wv_l);
    __nv_bfloat16* woh = (__nv_bfloat16*)sym(g_wo_h);
    __nv_bfloat16* wol = (__nv_bfloat16*)sym(g_wo_l);
    __nv_bfloat16* w1h = (__nv_bfloat16*)sym(g_w1_h);
    __nv_bfloat16* w1l = (__nv_bfloat16*)sym(g_w1_l);
    __nv_bfloat16* w2h = (__nv_bfloat16*)sym(g_w2_h);
    __nv_bfloat16* w2l = (__nv_bfloat16*)sym(g_w2_l);

    const int att_smem = (4 * 64 * ATT_PAD + 3 * 64) * (int)sizeof(float);
    cudaFuncSetAttribute(attention_kernel,
                         cudaFuncAttributeMaxDynamicSharedMemorySize, att_smem);
    cudaFuncSetAttribute(gemm_mma<false>,
                         cudaFuncAttributeMaxDynamicSharedMemorySize, GM_SMEM);
    cudaFuncSetAttribute(gemm_mma<true>,
                         cudaFuncAttributeMaxDynamicSharedMemorySize, GM_SMEM);

    dim3 tb(256);

    // weight transposes + splits  (W[K,N] -> [N,K] hi/lo)
    transpose_split<<<dim3(D_MODEL / 32, D_MODEL / 32), tb>>>(Wq, wqh, wql, D_MODEL, D_MODEL);
    transpose_split<<<dim3(D_MODEL / 32, D_MODEL / 32), tb>>>(Wk, wkh, wkl, D_MODEL, D_MODEL);
    transpose_split<<<dim3(D_MODEL / 32, D_MODEL / 32), tb>>>(Wv, wvh, wvl, D_MODEL, D_MODEL);
    transpose_split<<<dim3(D_MODEL / 32, D_MODEL / 32), tb>>>(Wo, woh, wol, D_MODEL, D_MODEL);
    transpose_split<<<dim3(D_FF / 32, D_MODEL / 32), tb>>>(W1, w1h, w1l, D_MODEL, D_FF);
    transpose_split<<<dim3(D_MODEL / 32, D_FF / 32), tb>>>(W2, w2h, w2l, D_FF, D_MODEL);

    const int n4_x = (M_ROWS * D_MODEL) / 4;
    const int n4_mid = (M_ROWS * D_FF) / 4;
    dim3 gProj(D_MODEL / 128, M_ROWS / 128);   // (8, 64)
    dim3 gFF1(D_FF / 128, M_ROWS / 128);       // (32, 64)

    // QKV projections
    split_bf16<<<n4_x / 256, tb>>>((const float4*)x, (__nv_bfloat162*)ah, (__nv_bfloat162*)al, n4_x);
    gemm_mma<false><<<gProj, tb, GM_SMEM>>>(ah, al, wqh, wql, bq, q, M_ROWS, D_MODEL, D_MODEL);
    gemm_mma<false><<<gProj, tb, GM_SMEM>>>(ah, al, wkh, wkl, bk, k, M_ROWS, D_MODEL, D_MODEL);
    gemm_mma<false><<<gProj, tb, GM_SMEM>>>(ah, al, wvh, wvl, bv, v, M_ROWS, D_MODEL, D_MODEL);

    // causal attention -> ctx
    attention_kernel<<<dim3(S_LEN / 64, B_SZ * N_HEADS), tb, att_smem>>>(q, k, v, ctx);

    // output projection (attn_out -> q)
    split_bf16<<<n4_x / 256, tb>>>((const float4*)ctx, (__nv_bfloat162*)ah, (__nv_bfloat162*)al, n4_x);
    gemm_mma<false><<<gProj, tb, GM_SMEM>>>(ah, al, woh, wol, bo, q, M_ROWS, D_MODEL, D_MODEL);

    // h1 = LN(x + attn_out)
    add_ln_kernel<<<M_ROWS, tb>>>(x, q, g1, be1, h1);

    // FFN
    split_bf16<<<n4_x / 256, tb>>>((const float4*)h1, (__nv_bfloat162*)ah, (__nv_bfloat162*)al, n4_x);
    gemm_mma<true><<<gFF1, tb, GM_SMEM>>>(ah, al, w1h, w1l, b1, mid, M_ROWS, D_FF, D_MODEL);
    split_bf16<<<n4_mid / 256, tb>>>((const float4*)mid, (__nv_bfloat162*)ah, (__nv_bfloat162*)al, n4_mid);
    gemm_mma<false><<<gProj, tb, GM_SMEM>>>(ah, al, w2h, w2l, b2, v, M_ROWS, D_MODEL, D_FF);

    // out = LN(h1 + ffn)
    add_ln_kernel<<<M_ROWS, tb>>>(h1, v, g3, be3, out);
}

// round 10
// speedup vs baseline: 1.8990x; 1.0388x over previous
#include <cuda_runtime.h>
#include <cuda_bf16.h>
#include <math.h>
#include <stdint.h>

// ---------------------------------------------------------------------------
// Problem constants
// ---------------------------------------------------------------------------
#define B_SZ 8
#define S_LEN 1024
#define D_MODEL 1024
#define N_HEADS 16
#define D_K 64
#define D_FF 4096
#define M_ROWS (B_SZ * S_LEN)   // 8192

// single dynamic-smem symbol shared by all kernels (typed locally)
extern __shared__ char dyn_smem[];

// ---------------------------------------------------------------------------
// Scratch (device globals — allocation-free rule)
// ---------------------------------------------------------------------------
__device__ float g_q[(size_t)M_ROWS * D_MODEL];
__device__ float g_k[(size_t)M_ROWS * D_MODEL];
__device__ float g_v[(size_t)M_ROWS * D_MODEL];
__device__ float g_h1[(size_t)M_ROWS * D_MODEL];

// bf16 hi/lo activation buffers
// sA: holds split of x, later split of h1      [M_ROWS, D_MODEL]
// sB: holds split of ctx, later split of mid   [M_ROWS, D_FF]
__device__ __nv_bfloat16 g_sa_h[(size_t)M_ROWS * D_MODEL];
__device__ __nv_bfloat16 g_sa_l[(size_t)M_ROWS * D_MODEL];
__device__ __nv_bfloat16 g_sb_h[(size_t)M_ROWS * D_FF];
__device__ __nv_bfloat16 g_sb_l[(size_t)M_ROWS * D_FF];

// transposed+split weights [N,K] bf16
__device__ __nv_bfloat16 g_wq_h[(size_t)D_MODEL * D_MODEL];
__device__ __nv_bfloat16 g_wq_l[(size_t)D_MODEL * D_MODEL];
__device__ __nv_bfloat16 g_wk_h[(size_t)D_MODEL * D_MODEL];
__device__ __nv_bfloat16 g_wk_l[(size_t)D_MODEL * D_MODEL];
__device__ __nv_bfloat16 g_wv_h[(size_t)D_MODEL * D_MODEL];
__device__ __nv_bfloat16 g_wv_l[(size_t)D_MODEL * D_MODEL];
__device__ __nv_bfloat16 g_wo_h[(size_t)D_MODEL * D_MODEL];
__device__ __nv_bfloat16 g_wo_l[(size_t)D_MODEL * D_MODEL];
__device__ __nv_bfloat16 g_w1_h[(size_t)D_FF * D_MODEL];
__device__ __nv_bfloat16 g_w1_l[(size_t)D_FF * D_MODEL];
__device__ __nv_bfloat16 g_w2_h[(size_t)D_MODEL * D_FF];
__device__ __nv_bfloat16 g_w2_l[(size_t)D_MODEL * D_FF];

// ---------------------------------------------------------------------------
// PTX helpers (portable: mma.sync + ldmatrix + cp.async)
// ---------------------------------------------------------------------------
static __device__ __forceinline__ uint32_t smem_u32(const void* p) {
    uint32_t a;
    asm("{ .reg .u64 t; cvta.to.shared.u64 t, %1; cvt.u32.u64 %0, t; }"
        : "=r"(a) : "l"(p));
    return a;
}

#define CP_ASYNC16(dst, src) \
    asm volatile("cp.async.cg.shared.global [%0], [%1], 16;" \
                 :: "r"((uint32_t)(dst)), "l"(src))
#define CP_COMMIT() asm volatile("cp.async.commit_group;" ::: "memory")

#define LDSM_X4(R0, R1, R2, R3, ADDR) \
    asm volatile("ldmatrix.sync.aligned.m8n8.x4.shared.b16 {%0,%1,%2,%3}, [%4];" \
                 : "=r"(R0), "=r"(R1), "=r"(R2), "=r"(R3) : "r"(ADDR))

// D += A * B  (m16n8k16, bf16 in, fp32 accum)
static __device__ __forceinline__ void mma16816(
    float* d, const uint32_t* a, uint32_t b0, uint32_t b1)
{
    asm volatile(
        "mma.sync.aligned.m16n8k16.row.col.f32.bf16.bf16.f32 "
        "{%0,%1,%2,%3}, {%4,%5,%6,%7}, {%8,%9}, {%0,%1,%2,%3};"
        : "+f"(d[0]), "+f"(d[1]), "+f"(d[2]), "+f"(d[3])
        : "r"(a[0]), "r"(a[1]), "r"(a[2]), "r"(a[3]), "r"(b0), "r"(b1));
}

static __device__ __forceinline__ __nv_bfloat162 split_hi2(float a, float b,
                                                           __nv_bfloat162& lo)
{
    __nv_bfloat16 h0 = __float2bfloat16(a);
    __nv_bfloat16 h1 = __float2bfloat16(b);
    lo = __nv_bfloat162(__float2bfloat16(a - __bfloat162float(h0)),
                        __float2bfloat16(b - __bfloat162float(h1)));
    return __nv_bfloat162(h0, h1);
}

// ---------------------------------------------------------------------------
// mma.sync GEMM:  C[M,N] = (Ah+Al)[M,K] @ (Bh+Bl)^T  (B stored [N,K]) + bias
// CTA tile 128x128, BK=32, 256 threads (8 warps, 2m x 4n, warp tile 64x32)
// 3-term bf16 split: AhBh + AhBl + AlBh, fp32 accum. ldmatrix fragment loads.
// 3-buffer cp.async pipeline. smem rows: 32 bf16 + 16B pad = 80 B stride.
// ---------------------------------------------------------------------------
#define GM_BUFSZ 40960
#define GM_SMEM  (3 * GM_BUFSZ)

static __device__ __forceinline__ void load_chunk(
    uint32_t sdst, const __nv_bfloat16* aH, const __nv_bfloat16* aL,
    const __nv_bfloat16* bH, const __nv_bfloat16* bL,
    int kb, int K, int tid)
{
#pragma unroll
    for (int j = 0; j < 2; j++) {
        int idx = tid + j * 256;          // 0..511
        int r = idx >> 2;                 // row 0..127
        int s = idx & 3;                  // 16B segment 0..3
        uint32_t doff = (uint32_t)(r * 80 + s * 16);
        size_t goff = (size_t)r * K + kb;
        CP_ASYNC16(sdst + doff,         (const char*)(aH + goff) + s * 16);
        CP_ASYNC16(sdst + 10240 + doff, (const char*)(aL + goff) + s * 16);
        CP_ASYNC16(sdst + 20480 + doff, (const char*)(bH + goff) + s * 16);
        CP_ASYNC16(sdst + 30720 + doff, (const char*)(bL + goff) + s * 16);
    }
}

template <bool RELU, bool SPLIT_OUT>
__global__ __launch_bounds__(256, 1)
void gemm_mma(const __nv_bfloat16* __restrict__ Ah, const __nv_bfloat16* __restrict__ Al,
              const __nv_bfloat16* __restrict__ Bh, const __nv_bfloat16* __restrict__ Bl,
              const float* __restrict__ bias, float* __restrict__ C,
              __nv_bfloat16* __restrict__ Ch, __nv_bfloat16* __restrict__ Cl,
              int M, int N, int K)
{
    const uint32_t sbase = smem_u32(dyn_smem);
    const int tid = threadIdx.x;
    const int wid = tid >> 5;
    const int lane = tid & 31;
    const int gid = lane >> 2;
    const int tig = lane & 3;
    const int n0 = blockIdx.x * 128;
    const int m0 = blockIdx.y * 128;
    const int wm = (wid >> 2) * 64;   // warp m offset
    const int wn = (wid & 3) * 32;    // warp n offset
    const int nch = K >> 5;

    const __nv_bfloat16* aH = Ah + (size_t)m0 * K;
    const __nv_bfloat16* aL = Al + (size_t)m0 * K;
    const __nv_bfloat16* bH = Bh + (size_t)n0 * K;
    const __nv_bfloat16* bL = Bl + (size_t)n0 * K;

    // ldmatrix per-thread address offsets (relative to tile base)
    // A (16x16 per mt): lanes 0-7 rows0-7/k0, 8-15 rows8-15/k0, 16-23 rows0-7/k1, 24-31 rows8-15/k1
    const uint32_t offA = (uint32_t)((wm + ((lane >> 3) & 1) * 8 + (lane & 7)) * 80 +
                                     (lane >> 4) * 16);
    // B (8x16 x2 per nt2): lanes 0-7 n0-7/k0, 8-15 n0-7/k1, 16-23 n8-15/k0, 24-31 n8-15/k1
    const uint32_t offB = (uint32_t)((wn + (lane >> 4) * 8 + (lane & 7)) * 80 +
                                     ((lane >> 3) & 1) * 16);

    float acc[4][4][4];
#pragma unroll
    for (int mt = 0; mt < 4; mt++)
#pragma unroll
        for (int nt = 0; nt < 4; nt++)
#pragma unroll
            for (int u = 0; u < 4; u++) acc[mt][nt][u] = 0.f;

    load_chunk(sbase,            aH, aL, bH, bL, 0,  K, tid);
    CP_COMMIT();
    load_chunk(sbase + GM_BUFSZ, aH, aL, bH, bL, 32, K, tid);
    CP_COMMIT();

    for (int ch = 0; ch < nch; ch++) {
        if (ch == nch - 1) asm volatile("cp.async.wait_group 0;" ::: "memory");
        else               asm volatile("cp.async.wait_group 1;" ::: "memory");
        __syncthreads();

        if (ch + 2 < nch) {
            load_chunk(sbase + ((ch + 2) % 3) * GM_BUFSZ,
                       aH, aL, bH, bL, (ch + 2) * 32, K, tid);
            CP_COMMIT();
        }

        const uint32_t buf = sbase + (ch % 3) * GM_BUFSZ;
        const uint32_t pAh = buf + offA;
        const uint32_t pAl = buf + 10240 + offA;
        const uint32_t pBh = buf + 20480 + offB;
        const uint32_t pBl = buf + 30720 + offB;

#pragma unroll
        for (int kk = 0; kk < 2; kk++) {      // two k16 steps per BK=32
            uint32_t ahf[4][4], alf[4][4], bhf[4][2], blf[4][2];
#pragma unroll
            for (int mt = 0; mt < 4; mt++) {
                LDSM_X4(ahf[mt][0], ahf[mt][1], ahf[mt][2], ahf[mt][3],
                        pAh + mt * 1280 + kk * 32);
                LDSM_X4(alf[mt][0], alf[mt][1], alf[mt][2], alf[mt][3],
                        pAl + mt * 1280 + kk * 32);
            }
#pragma unroll
            for (int nt2 = 0; nt2 < 2; nt2++) {
                LDSM_X4(bhf[nt2 * 2][0], bhf[nt2 * 2][1],
                        bhf[nt2 * 2 + 1][0], bhf[nt2 * 2 + 1][1],
                        pBh + nt2 * 1280 + kk * 32);
                LDSM_X4(blf[nt2 * 2][0], blf[nt2 * 2][1],
                        blf[nt2 * 2 + 1][0], blf[nt2 * 2 + 1][1],
                        pBl + nt2 * 1280 + kk * 32);
            }
#pragma unroll
            for (int nt = 0; nt < 4; nt++) {
#pragma unroll
                for (int mt = 0; mt < 4; mt++) {
                    mma16816(acc[mt][nt], ahf[mt], bhf[nt][0], bhf[nt][1]); // hi*hi
                    mma16816(acc[mt][nt], ahf[mt], blf[nt][0], blf[nt][1]); // hi*lo
                    mma16816(acc[mt][nt], alf[mt], bhf[nt][0], bhf[nt][1]); // lo*hi
                }
            }
        }
    }

    // epilogue
#pragma unroll
    for (int mt = 0; mt < 4; mt++) {
        int r0 = m0 + wm + mt * 16 + gid;
#pragma unroll
        for (int nt = 0; nt < 4; nt++) {
            int c0 = n0 + wn + nt * 8 + tig * 2;
            float bb0 = bias[c0], bb1 = bias[c0 + 1];
            float v0 = acc[mt][nt][0] + bb0;
            float v1 = acc[mt][nt][1] + bb1;
            float v2 = acc[mt][nt][2] + bb0;
            float v3 = acc[mt][nt][3] + bb1;
            if (RELU) {
                v0 = fmaxf(v0, 0.f); v1 = fmaxf(v1, 0.f);
                v2 = fmaxf(v2, 0.f); v3 = fmaxf(v3, 0.f);
            }
            if (SPLIT_OUT) {
                __nv_bfloat162 lo0, lo1;
                __nv_bfloat162 hi0 = split_hi2(v0, v1, lo0);
                __nv_bfloat162 hi1 = split_hi2(v2, v3, lo1);
                *(__nv_bfloat162*)(Ch + (size_t)r0 * N + c0)       = hi0;
                *(__nv_bfloat162*)(Cl + (size_t)r0 * N + c0)       = lo0;
                *(__nv_bfloat162*)(Ch + (size_t)(r0 + 8) * N + c0) = hi1;
                *(__nv_bfloat162*)(Cl + (size_t)(r0 + 8) * N + c0) = lo1;
            } else {
                *(float2*)(C + (size_t)r0 * N + c0)       = make_float2(v0, v1);
                *(float2*)(C + (size_t)(r0 + 8) * N + c0) = make_float2(v2, v3);
            }
        }
    }
}

// ---------------------------------------------------------------------------
// fp32 -> bf16 hi/lo split (elementwise) — only used once, for x
// ---------------------------------------------------------------------------
__global__ __launch_bounds__(256)
void split_bf16(const float4* __restrict__ in,
                __nv_bfloat162* __restrict__ h2, __nv_bfloat162* __restrict__ l2,
                int n4)
{
    int i = blockIdx.x * 256 + threadIdx.x;
    if (i >= n4) return;
    float4 v = in[i];
    __nv_bfloat162 lo0, lo1;
    __nv_bfloat162 hi0 = split_hi2(v.x, v.y, lo0);
    __nv_bfloat162 hi1 = split_hi2(v.z, v.w, lo1);
    h2[2 * i] = hi0; h2[2 * i + 1] = hi1;
    l2[2 * i] = lo0; l2[2 * i + 1] = lo1;
}

// ---------------------------------------------------------------------------
// W[K,N] fp32 -> transposed hi/lo bf16 [N,K]
// ---------------------------------------------------------------------------
__global__ __launch_bounds__(256)
void transpose_split(const float* __restrict__ W,
                     __nv_bfloat16* __restrict__ Th, __nv_bfloat16* __restrict__ Tl,
                     int K, int N)
{
    __shared__ float tile[32][33];
    const int tx = threadIdx.x & 31;
    const int ty = threadIdx.x >> 5;
    const int n0 = blockIdx.x * 32;
    const int k0 = blockIdx.y * 32;
#pragma unroll
    for (int j = 0; j < 4; j++)
        tile[ty + 8 * j][tx] = W[(size_t)(k0 + ty + 8 * j) * N + n0 + tx];
    __syncthreads();
#pragma unroll
    for (int j = 0; j < 4; j++) {
        float v = tile[tx][ty + 8 * j];
        __nv_bfloat16 h = __float2bfloat16(v);
        __nv_bfloat16 l = __float2bfloat16(v - __bfloat162float(h));
        size_t o = (size_t)(n0 + ty + 8 * j) * K + k0 + tx;
        Th[o] = h;
        Tl[o] = l;
    }
}

// ---------------------------------------------------------------------------
// Flash-style causal attention; output written directly as bf16 hi/lo split
// ---------------------------------------------------------------------------
#define ATT_PAD 68

__global__ __launch_bounds__(256)
void attention_kernel(const float* __restrict__ Q, const float* __restrict__ K,
                      const float* __restrict__ V,
                      __nv_bfloat16* __restrict__ Oh, __nv_bfloat16* __restrict__ Ol)
{
    float* smem = (float*)dyn_smem;
    float* QsT = smem;
    float* KsT = QsT + 64 * ATT_PAD;
    float* Vs  = KsT + 64 * ATT_PAD;
    float* Ss  = Vs  + 64 * ATT_PAD;
    float* m_s = Ss + 64 * ATT_PAD;
    float* l_s = m_s + 64;
    float* corr_s = l_s + 64;

    const int tid = threadIdx.x;
    const int qtile = blockIdx.x;
    const int bh = blockIdx.y;
    const int b = bh >> 4;
    const int h = bh & 15;
    const int q0 = qtile * 64;

    const float* Qb = Q + (size_t)b * S_LEN * D_MODEL + h * D_K;
    const float* Kb = K + (size_t)b * S_LEN * D_MODEL + h * D_K;
    const float* Vb = V + (size_t)b * S_LEN * D_MODEL + h * D_K;
    __nv_bfloat16* Obh = Oh + (size_t)b * S_LEN * D_MODEL + h * D_K;
    __nv_bfloat16* Obl = Ol + (size_t)b * S_LEN * D_MODEL + h * D_K;

#pragma unroll
    for (int t = 0; t < 4; t++) {
        int idx = tid + t * 256;
        int r = idx >> 4;
        int c4 = idx & 15;
        float4 v = *(const float4*)(Qb + (size_t)(q0 + r) * D_MODEL + c4 * 4);
        QsT[(c4 * 4 + 0) * ATT_PAD + r] = v.x;
        QsT[(c4 * 4 + 1) * ATT_PAD + r] = v.y;
        QsT[(c4 * 4 + 2) * ATT_PAD + r] = v.z;
        QsT[(c4 * 4 + 3) * ATT_PAD + r] = v.w;
    }
    if (tid < 64) { m_s[tid] = -INFINITY; l_s[tid] = 0.f; }

    const int tr = tid >> 4;
    const int tc = tid & 15;
    float o[4][4];
#pragma unroll
    for (int i = 0; i < 4; i++)
#pragma unroll
        for (int j = 0; j < 4; j++) o[i][j] = 0.f;

    for (int kb = 0; kb <= qtile; kb++) {
        __syncthreads();
#pragma unroll
        for (int t = 0; t < 4; t++) {
            int idx = tid + t * 256;
            int r = idx >> 4;
            int c4 = idx & 15;
            float4 kv = *(const float4*)(Kb + (size_t)(kb * 64 + r) * D_MODEL + c4 * 4);
            KsT[(c4 * 4 + 0) * ATT_PAD + r] = kv.x;
            KsT[(c4 * 4 + 1) * ATT_PAD + r] = kv.y;
            KsT[(c4 * 4 + 2) * ATT_PAD + r] = kv.z;
            KsT[(c4 * 4 + 3) * ATT_PAD + r] = kv.w;
            float4 vv = *(const float4*)(Vb + (size_t)(kb * 64 + r) * D_MODEL + c4 * 4);
            *(float4*)(&Vs[r * ATT_PAD + c4 * 4]) = vv;
        }
        __syncthreads();

        float s[4][4];
#pragma unroll
        for (int i = 0; i < 4; i++)
#pragma unroll
            for (int j = 0; j < 4; j++) s[i][j] = 0.f;
#pragma unroll 8
        for (int d = 0; d < 64; d++) {
            float4 a4 = *(const float4*)(&QsT[d * ATT_PAD + 4 * tr]);
            float4 b4 = *(const float4*)(&KsT[d * ATT_PAD + 4 * tc]);
            float a[4] = {a4.x, a4.y, a4.z, a4.w};
            float bb[4] = {b4.x, b4.y, b4.z, b4.w};
#pragma unroll
            for (int i = 0; i < 4; i++)
#pragma unroll
                for (int j = 0; j < 4; j++)
                    s[i][j] = fmaf(a[i], bb[j], s[i][j]);
        }
#pragma unroll
        for (int i = 0; i < 4; i++) {
#pragma unroll
            for (int j = 0; j < 4; j++) {
                float val = s[i][j] * 0.125f;
                if (kb == qtile && (4 * tc + j) >= (4 * tr + i)) val = -1e30f;
                Ss[(4 * tr + i) * ATT_PAD + (4 * tc + j)] = val;
            }
        }
        __syncthreads();

        {
            int r = tid >> 2;
            int qd = tid & 3;
            float loc[16];
            *(float4*)(loc)      = *(const float4*)(&Ss[r * ATT_PAD + qd * 16]);
            *(float4*)(loc + 4)  = *(const float4*)(&Ss[r * ATT_PAD + qd * 16 + 4]);
            *(float4*)(loc + 8)  = *(const float4*)(&Ss[r * ATT_PAD + qd * 16 + 8]);
            *(float4*)(loc + 12) = *(const float4*)(&Ss[r * ATT_PAD + qd * 16 + 12]);
            float mx = loc[0];
#pragma unroll
            for (int u = 1; u < 16; u++) mx = fmaxf(mx, loc[u]);
            mx = fmaxf(mx, __shfl_xor_sync(0xffffffffu, mx, 1));
            mx = fmaxf(mx, __shfl_xor_sync(0xffffffffu, mx, 2));
            float m_old = m_s[r];
            float m_new = fmaxf(m_old, mx);
            float sum = 0.f;
#pragma unroll
            for (int u = 0; u < 16; u++) {
                loc[u] = __expf(loc[u] - m_new);
                sum += loc[u];
            }
            sum += __shfl_xor_sync(0xffffffffu, sum, 1);
            sum += __shfl_xor_sync(0xffffffffu, sum, 2);
            *(float4*)(&Ss[r * ATT_PAD + qd * 16])      = *(float4*)(loc);
            *(float4*)(&Ss[r * ATT_PAD + qd * 16 + 4])  = *(float4*)(loc + 4);
            *(float4*)(&Ss[r * ATT_PAD + qd * 16 + 8])  = *(float4*)(loc + 8);
            *(float4*)(&Ss[r * ATT_PAD + qd * 16 + 12]) = *(float4*)(loc + 12);
            if (qd == 0) {
                float c = __expf(m_old - m_new);
                corr_s[r] = c;
                l_s[r] = l_s[r] * c + sum;
                m_s[r] = m_new;
            }
        }
        __syncthreads();

#pragma unroll
        for (int i = 0; i < 4; i++) {
            float c = corr_s[4 * tr + i];
#pragma unroll
            for (int j = 0; j < 4; j++) o[i][j] *= c;
        }
#pragma unroll 8
        for (int jj = 0; jj < 64; jj++) {
            float p[4];
#pragma unroll
            for (int i = 0; i < 4; i++) p[i] = Ss[(4 * tr + i) * ATT_PAD + jj];
            float4 vv = *(const float4*)(&Vs[jj * ATT_PAD + 4 * tc]);
#pragma unroll
            for (int i = 0; i < 4; i++) {
                o[i][0] = fmaf(p[i], vv.x, o[i][0]);
                o[i][1] = fmaf(p[i], vv.y, o[i][1]);
                o[i][2] = fmaf(p[i], vv.z, o[i][2]);
                o[i][3] = fmaf(p[i], vv.w, o[i][3]);
            }
        }
    }
    __syncthreads();

    // finalize: /l, zero first global row, write bf16 hi/lo split directly
#pragma unroll
    for (int i = 0; i < 4; i++) {
        int q = 4 * tr + i;
        int gi = q0 + q;
        float inv = 1.f / l_s[q];
        float v0 = o[i][0] * inv, v1 = o[i][1] * inv;
        float v2 = o[i][2] * inv, v3 = o[i][3] * inv;
        if (gi == 0) { v0 = 0.f; v1 = 0.f; v2 = 0.f; v3 = 0.f; }
        __nv_bfloat162 lo0, lo1;
        __nv_bfloat162 hi0 = split_hi2(v0, v1, lo0);
        __nv_bfloat162 hi1 = split_hi2(v2, v3, lo1);
        size_t off = (size_t)gi * D_MODEL + 4 * tc;
        *(__nv_bfloat162*)(Obh + off)     = hi0;
        *(__nv_bfloat162*)(Obh + off + 2) = hi1;
        *(__nv_bfloat162*)(Obl + off)     = lo0;
        *(__nv_bfloat162*)(Obl + off + 2) = lo1;
    }
}

// ---------------------------------------------------------------------------
// Fused residual add + LayerNorm (+ optional bf16 hi/lo split output)
// ---------------------------------------------------------------------------
template <bool SPLIT>
__global__ __launch_bounds__(256)
void add_ln_kernel(const float* __restrict__ A, const float* __restrict__ Bm,
                   const float* __restrict__ g, const float* __restrict__ beta,
                   float* __restrict__ out,
                   __nv_bfloat16* __restrict__ oh, __nv_bfloat16* __restrict__ ol)
{
    __shared__ float red_s[8];
    __shared__ float red_q[8];
    __shared__ float stats[2];

    const int row = blockIdx.x;
    const int c = threadIdx.x * 4;
    const float* a = A + (size_t)row * D_MODEL;
    const float* bm = Bm + (size_t)row * D_MODEL;

    float4 av = *(const float4*)(a + c);
    float4 bv = *(const float4*)(bm + c);
    float v0 = av.x + bv.x, v1 = av.y + bv.y, v2 = av.z + bv.z, v3 = av.w + bv.w;

    float s = v0 + v1 + v2 + v3;
    float q = v0 * v0 + v1 * v1 + v2 * v2 + v3 * v3;
#pragma unroll
    for (int off = 16; off > 0; off >>= 1) {
        s += __shfl_xor_sync(0xffffffffu, s, off);
        q += __shfl_xor_sync(0xffffffffu, q, off);
    }
    if ((threadIdx.x & 31) == 0) {
        red_s[threadIdx.x >> 5] = s;
        red_q[threadIdx.x >> 5] = q;
    }
    __syncthreads();
    if (threadIdx.x < 32) {
        float ts = (threadIdx.x < 8) ? red_s[threadIdx.x] : 0.f;
        float tq = (threadIdx.x < 8) ? red_q[threadIdx.x] : 0.f;
#pragma unroll
        for (int off = 4; off > 0; off >>= 1) {
            ts += __shfl_xor_sync(0xffffffffu, ts, off);
            tq += __shfl_xor_sync(0xffffffffu, tq, off);
        }
        if (threadIdx.x == 0) {
            float mu = ts * (1.f / D_MODEL);
            float var = tq * (1.f / D_MODEL) - mu * mu;
            var = fmaxf(var, 0.f);
            stats[0] = mu;
            stats[1] = rsqrtf(var + 1e-5f);
        }
    }
    __syncthreads();
    const float mu = stats[0];
    const float rstd = stats[1];

    float4 gv = *(const float4*)(g + c);
    float4 bev = *(const float4*)(beta + c);
    float4 ov;
    ov.x = (v0 - mu) * rstd * gv.x + bev.x;
    ov.y = (v1 - mu) * rstd * gv.y + bev.y;
    ov.z = (v2 - mu) * rstd * gv.z + bev.z;
    ov.w = (v3 - mu) * rstd * gv.w + bev.w;
    *(float4*)(out + (size_t)row * D_MODEL + c) = ov;
    if (SPLIT) {
        __nv_bfloat162 lo0, lo1;
        __nv_bfloat162 hi0 = split_hi2(ov.x, ov.y, lo0);
        __nv_bfloat162 hi1 = split_hi2(ov.z, ov.w, lo1);
        size_t off = (size_t)row * D_MODEL + c;
        *(__nv_bfloat162*)(oh + off)     = hi0;
        *(__nv_bfloat162*)(oh + off + 2) = hi1;
        *(__nv_bfloat162*)(ol + off)     = lo0;
        *(__nv_bfloat162*)(ol + off + 2) = lo1;
    }
}

// ---------------------------------------------------------------------------
// Launch
// ---------------------------------------------------------------------------
static inline float* sym(const void* s) {
    void* p = nullptr;
    cudaGetSymbolAddress(&p, s);
    return (float*)p;
}

extern "C" void kernel_launch(void* const* d_in, const int* in_sizes, int n_in,
                              void* d_out, int out_size)
{
    const float* x   = (const float*)d_in[0];
    const float* Wq  = (const float*)d_in[1];
    const float* bq  = (const float*)d_in[2];
    const float* Wk  = (const float*)d_in[3];
    const float* bk  = (const float*)d_in[4];
    const float* Wv  = (const float*)d_in[5];
    const float* bv  = (const float*)d_in[6];
    const float* Wo  = (const float*)d_in[7];
    const float* bo  = (const float*)d_in[8];
    const float* W1  = (const float*)d_in[9];
    const float* b1  = (const float*)d_in[10];
    const float* W2  = (const float*)d_in[11];
    const float* b2  = (const float*)d_in[12];
    const float* g1  = (const float*)d_in[13];
    const float* be1 = (const float*)d_in[14];
    const float* g3  = (const float*)d_in[15];
    const float* be3 = (const float*)d_in[16];
    float* out = (float*)d_out;

    float* q   = sym(g_q);
    float* k   = sym(g_k);
    float* v   = sym(g_v);
    float* h1  = sym(g_h1);
    __nv_bfloat16* sah = (__nv_bfloat16*)sym(g_sa_h);
    __nv_bfloat16* sal = (__nv_bfloat16*)sym(g_sa_l);
    __nv_bfloat16* sbh = (__nv_bfloat16*)sym(g_sb_h);
    __nv_bfloat16* sbl = (__nv_bfloat16*)sym(g_sb_l);
    __nv_bfloat16* wqh = (__nv_bfloat16*)sym(g_wq_h);
    __nv_bfloat16* wql = (__nv_bfloat16*)sym(g_wq_l);
    __nv_bfloat16* wkh = (__nv_bfloat16*)sym(g_wk_h);
    __nv_bfloat16* wkl = (__nv_bfloat16*)sym(g_wk_l);
    __nv_bfloat16* wvh = (__nv_bfloat16*)sym(g_wv_h);
    __nv_bfloat16* wvl = (__nv_bfloat16*)sym(g_wv_l);
    __nv_bfloat16* woh = (__nv_bfloat16*)sym(g_wo_h);
    __nv_bfloat16* wol = (__nv_bfloat16*)sym(g_wo_l);
    __nv_bfloat16* w1h = (__nv_bfloat16*)sym(g_w1_h);
    __nv_bfloat16* w1l = (__nv_bfloat16*)sym(g_w1_l);
    __nv_bfloat16* w2h = (__nv_bfloat16*)sym(g_w2_h);
    __nv_bfloat16* w2l = (__nv_bfloat16*)sym(g_w2_l);

    const int att_smem = (4 * 64 * ATT_PAD + 3 * 64) * (int)sizeof(float);
    cudaFuncSetAttribute(attention_kernel,
                         cudaFuncAttributeMaxDynamicSharedMemorySize, att_smem);
    cudaFuncSetAttribute(gemm_mma<false, false>,
                         cudaFuncAttributeMaxDynamicSharedMemorySize, GM_SMEM);
    cudaFuncSetAttribute(gemm_mma<true, true>,
                         cudaFuncAttributeMaxDynamicSharedMemorySize, GM_SMEM);

    dim3 tb(256);

    // weight transposes + splits  (W[K,N] -> [N,K] hi/lo)
    transpose_split<<<dim3(D_MODEL / 32, D_MODEL / 32), tb>>>(Wq, wqh, wql, D_MODEL, D_MODEL);
    transpose_split<<<dim3(D_MODEL / 32, D_MODEL / 32), tb>>>(Wk, wkh, wkl, D_MODEL, D_MODEL);
    transpose_split<<<dim3(D_MODEL / 32, D_MODEL / 32), tb>>>(Wv, wvh, wvl, D_MODEL, D_MODEL);
    transpose_split<<<dim3(D_MODEL / 32, D_MODEL / 32), tb>>>(Wo, woh, wol, D_MODEL, D_MODEL);
    transpose_split<<<dim3(D_FF / 32, D_MODEL / 32), tb>>>(W1, w1h, w1l, D_MODEL, D_FF);
    transpose_split<<<dim3(D_MODEL / 32, D_FF / 32), tb>>>(W2, w2h, w2l, D_FF, D_MODEL);

    const int n4_x = (M_ROWS * D_MODEL) / 4;
    dim3 gProj(D_MODEL / 128, M_ROWS / 128);   // (8, 64)
    dim3 gFF1(D_FF / 128, M_ROWS / 128);       // (32, 64)

    // x split (the only standalone split)
    split_bf16<<<n4_x / 256, tb>>>((const float4*)x,
                                   (__nv_bfloat162*)sah, (__nv_bfloat162*)sal, n4_x);

    // QKV projections (fp32 out)
    gemm_mma<false, false><<<gProj, tb, GM_SMEM>>>(sah, sal, wqh, wql, bq, q, nullptr, nullptr, M_ROWS, D_MODEL, D_MODEL);
    gemm_mma<false, false><<<gProj, tb, GM_SMEM>>>(sah, sal, wkh, wkl, bk, k, nullptr, nullptr, M_ROWS, D_MODEL, D_MODEL);
    gemm_mma<false, false><<<gProj, tb, GM_SMEM>>>(sah, sal, wvh, wvl, bv, v, nullptr, nullptr, M_ROWS, D_MODEL, D_MODEL);

    // causal attention -> ctx split (sB)
    attention_kernel<<<dim3(S_LEN / 64, B_SZ * N_HEADS), tb, att_smem>>>(q, k, v, sbh, sbl);

    // output projection: attn_out fp32 (reuse q)
    gemm_mma<false, false><<<gProj, tb, GM_SMEM>>>(sbh, sbl, woh, wol, bo, q, nullptr, nullptr, M_ROWS, D_MODEL, D_MODEL);

    // h1 = LN(x + attn_out), also emit h1 split into sA
    add_ln_kernel<true><<<M_ROWS, tb>>>(x, q, g1, be1, h1, sah, sal);

    // FFN1: ReLU(h1 @ W1 + b1) -> split directly into sB [M, D_FF]
    gemm_mma<true, true><<<gFF1, tb, GM_SMEM>>>(sah, sal, w1h, w1l, b1, nullptr, sbh, sbl, M_ROWS, D_FF, D_MODEL);

    // FFN2: fp32 out (reuse v)
    gemm_mma<false, false><<<gProj, tb, GM_SMEM>>>(sbh, sbl, w2h, w2l, b2, v, nullptr, nullptr, M_ROWS, D_MODEL, D_FF);

    // out = LN(h1 + ffn)
    add_ln_kernel<false><<<M_ROWS, tb>>>(h1, v, g3, be3, out, nullptr, nullptr);
}

// round 11
// speedup vs baseline: 1.9245x; 1.0134x over previous
#include <cuda_runtime.h>
#include <cuda_bf16.h>
#include <math.h>
#include <stdint.h>

// ---------------------------------------------------------------------------
// Problem constants
// ---------------------------------------------------------------------------
#define B_SZ 8
#define S_LEN 1024
#define D_MODEL 1024
#define N_HEADS 16
#define D_K 64
#define D_FF 4096
#define M_ROWS (B_SZ * S_LEN)   // 8192

// single dynamic-smem symbol shared by all kernels (typed locally)
extern __shared__ char dyn_smem[];

// ---------------------------------------------------------------------------
// Scratch (device globals — allocation-free rule)
// ---------------------------------------------------------------------------
__device__ float g_q[(size_t)M_ROWS * D_MODEL];
__device__ float g_k[(size_t)M_ROWS * D_MODEL];
__device__ float g_v[(size_t)M_ROWS * D_MODEL];
__device__ float g_h1[(size_t)M_ROWS * D_MODEL];

// bf16 hi/lo activation buffers
// sA: holds split of x, later split of h1      [M_ROWS, D_MODEL]
// sB: holds split of ctx, later split of mid   [M_ROWS, D_FF]
__device__ __nv_bfloat16 g_sa_h[(size_t)M_ROWS * D_MODEL];
__device__ __nv_bfloat16 g_sa_l[(size_t)M_ROWS * D_MODEL];
__device__ __nv_bfloat16 g_sb_h[(size_t)M_ROWS * D_FF];
__device__ __nv_bfloat16 g_sb_l[(size_t)M_ROWS * D_FF];

// transposed+split weights [N,K] bf16
__device__ __nv_bfloat16 g_wq_h[(size_t)D_MODEL * D_MODEL];
__device__ __nv_bfloat16 g_wq_l[(size_t)D_MODEL * D_MODEL];
__device__ __nv_bfloat16 g_wk_h[(size_t)D_MODEL * D_MODEL];
__device__ __nv_bfloat16 g_wk_l[(size_t)D_MODEL * D_MODEL];
__device__ __nv_bfloat16 g_wv_h[(size_t)D_MODEL * D_MODEL];
__device__ __nv_bfloat16 g_wv_l[(size_t)D_MODEL * D_MODEL];
__device__ __nv_bfloat16 g_wo_h[(size_t)D_MODEL * D_MODEL];
__device__ __nv_bfloat16 g_wo_l[(size_t)D_MODEL * D_MODEL];
__device__ __nv_bfloat16 g_w1_h[(size_t)D_FF * D_MODEL];
__device__ __nv_bfloat16 g_w1_l[(size_t)D_FF * D_MODEL];
__device__ __nv_bfloat16 g_w2_h[(size_t)D_MODEL * D_FF];
__device__ __nv_bfloat16 g_w2_l[(size_t)D_MODEL * D_FF];

// ---------------------------------------------------------------------------
// PTX helpers (portable: mma.sync + ldmatrix + cp.async)
// ---------------------------------------------------------------------------
static __device__ __forceinline__ uint32_t smem_u32(const void* p) {
    uint32_t a;
    asm("{ .reg .u64 t; cvta.to.shared.u64 t, %1; cvt.u32.u64 %0, t; }"
        : "=r"(a) : "l"(p));
    return a;
}

#define CP_ASYNC16(dst, src) \
    asm volatile("cp.async.cg.shared.global [%0], [%1], 16;" \
                 :: "r"((uint32_t)(dst)), "l"(src))
#define CP_COMMIT() asm volatile("cp.async.commit_group;" ::: "memory")

#define LDSM_X4(R0, R1, R2, R3, ADDR) \
    asm volatile("ldmatrix.sync.aligned.m8n8.x4.shared.b16 {%0,%1,%2,%3}, [%4];" \
                 : "=r"(R0), "=r"(R1), "=r"(R2), "=r"(R3) : "r"(ADDR))

// D += A * B  (m16n8k16, bf16 in, fp32 accum)
static __device__ __forceinline__ void mma16816(
    float* d, const uint32_t* a, uint32_t b0, uint32_t b1)
{
    asm volatile(
        "mma.sync.aligned.m16n8k16.row.col.f32.bf16.bf16.f32 "
        "{%0,%1,%2,%3}, {%4,%5,%6,%7}, {%8,%9}, {%0,%1,%2,%3};"
        : "+f"(d[0]), "+f"(d[1]), "+f"(d[2]), "+f"(d[3])
        : "r"(a[0]), "r"(a[1]), "r"(a[2]), "r"(a[3]), "r"(b0), "r"(b1));
}

static __device__ __forceinline__ __nv_bfloat162 split_hi2(float a, float b,
                                                           __nv_bfloat162& lo)
{
    __nv_bfloat16 h0 = __float2bfloat16(a);
    __nv_bfloat16 h1 = __float2bfloat16(b);
    lo = __nv_bfloat162(__float2bfloat16(a - __bfloat162float(h0)),
                        __float2bfloat16(b - __bfloat162float(h1)));
    return __nv_bfloat162(h0, h1);
}

// ---------------------------------------------------------------------------
// mma.sync GEMM:  C[M,N] = (Ah+Al)[M,K] @ (Bh+Bl)^T  (B stored [N,K]) + bias
// CTA tile 128x128, BK=32, 256 threads (8 warps, 2m x 4n, warp tile 64x32)
// 3-term bf16 split: AhBh + AhBl + AlBh, fp32 accum. ldmatrix fragment loads.
// 3-buffer cp.async pipeline. smem rows: 32 bf16 + 16B pad = 80 B stride.
// ---------------------------------------------------------------------------
#define GM_BUFSZ 40960
#define GM_SMEM  (3 * GM_BUFSZ)

static __device__ __forceinline__ void load_chunk(
    uint32_t sdst, const __nv_bfloat16* aH, const __nv_bfloat16* aL,
    const __nv_bfloat16* bH, const __nv_bfloat16* bL,
    int kb, int K, int tid)
{
#pragma unroll
    for (int j = 0; j < 2; j++) {
        int idx = tid + j * 256;          // 0..511
        int r = idx >> 2;                 // row 0..127
        int s = idx & 3;                  // 16B segment 0..3
        uint32_t doff = (uint32_t)(r * 80 + s * 16);
        size_t goff = (size_t)r * K + kb;
        CP_ASYNC16(sdst + doff,         (const char*)(aH + goff) + s * 16);
        CP_ASYNC16(sdst + 10240 + doff, (const char*)(aL + goff) + s * 16);
        CP_ASYNC16(sdst + 20480 + doff, (const char*)(bH + goff) + s * 16);
        CP_ASYNC16(sdst + 30720 + doff, (const char*)(bL + goff) + s * 16);
    }
}

template <bool RELU, bool SPLIT_OUT>
__global__ __launch_bounds__(256, 1)
void gemm_mma(const __nv_bfloat16* __restrict__ Ah, const __nv_bfloat16* __restrict__ Al,
              const __nv_bfloat16* __restrict__ Bh, const __nv_bfloat16* __restrict__ Bl,
              const float* __restrict__ bias, float* __restrict__ C,
              __nv_bfloat16* __restrict__ Ch, __nv_bfloat16* __restrict__ Cl,
              int M, int N, int K)
{
    const uint32_t sbase = smem_u32(dyn_smem);
    const int tid = threadIdx.x;
    const int wid = tid >> 5;
    const int lane = tid & 31;
    const int gid = lane >> 2;
    const int tig = lane & 3;
    const int n0 = blockIdx.x * 128;
    const int m0 = blockIdx.y * 128;
    const int wm = (wid >> 2) * 64;   // warp m offset
    const int wn = (wid & 3) * 32;    // warp n offset
    const int nch = K >> 5;

    const __nv_bfloat16* aH = Ah + (size_t)m0 * K;
    const __nv_bfloat16* aL = Al + (size_t)m0 * K;
    const __nv_bfloat16* bH = Bh + (size_t)n0 * K;
    const __nv_bfloat16* bL = Bl + (size_t)n0 * K;

    // ldmatrix per-thread address offsets (relative to tile base)
    // A (16x16 per mt): lanes 0-7 rows0-7/k0, 8-15 rows8-15/k0, 16-23 rows0-7/k1, 24-31 rows8-15/k1
    const uint32_t offA = (uint32_t)((wm + ((lane >> 3) & 1) * 8 + (lane & 7)) * 80 +
                                     (lane >> 4) * 16);
    // B (8x16 x2 per nt2): lanes 0-7 n0-7/k0, 8-15 n0-7/k1, 16-23 n8-15/k0, 24-31 n8-15/k1
    const uint32_t offB = (uint32_t)((wn + (lane >> 4) * 8 + (lane & 7)) * 80 +
                                     ((lane >> 3) & 1) * 16);

    float acc[4][4][4];
#pragma unroll
    for (int mt = 0; mt < 4; mt++)
#pragma unroll
        for (int nt = 0; nt < 4; nt++)
#pragma unroll
            for (int u = 0; u < 4; u++) acc[mt][nt][u] = 0.f;

    load_chunk(sbase,            aH, aL, bH, bL, 0,  K, tid);
    CP_COMMIT();
    load_chunk(sbase + GM_BUFSZ, aH, aL, bH, bL, 32, K, tid);
    CP_COMMIT();

    for (int ch = 0; ch < nch; ch++) {
        if (ch == nch - 1) asm volatile("cp.async.wait_group 0;" ::: "memory");
        else               asm volatile("cp.async.wait_group 1;" ::: "memory");
        __syncthreads();

        if (ch + 2 < nch) {
            load_chunk(sbase + ((ch + 2) % 3) * GM_BUFSZ,
                       aH, aL, bH, bL, (ch + 2) * 32, K, tid);
            CP_COMMIT();
        }

        const uint32_t buf = sbase + (ch % 3) * GM_BUFSZ;
        const uint32_t pAh = buf + offA;
        const uint32_t pAl = buf + 10240 + offA;
        const uint32_t pBh = buf + 20480 + offB;
        const uint32_t pBl = buf + 30720 + offB;

#pragma unroll
        for (int kk = 0; kk < 2; kk++) {      // two k16 steps per BK=32
            uint32_t ahf[4][4], alf[4][4], bhf[4][2], blf[4][2];
#pragma unroll
            for (int mt = 0; mt < 4; mt++) {
                LDSM_X4(ahf[mt][0], ahf[mt][1], ahf[mt][2], ahf[mt][3],
                        pAh + mt * 1280 + kk * 32);
                LDSM_X4(alf[mt][0], alf[mt][1], alf[mt][2], alf[mt][3],
                        pAl + mt * 1280 + kk * 32);
            }
#pragma unroll
            for (int nt2 = 0; nt2 < 2; nt2++) {
                LDSM_X4(bhf[nt2 * 2][0], bhf[nt2 * 2][1],
                        bhf[nt2 * 2 + 1][0], bhf[nt2 * 2 + 1][1],
                        pBh + nt2 * 1280 + kk * 32);
                LDSM_X4(blf[nt2 * 2][0], blf[nt2 * 2][1],
                        blf[nt2 * 2 + 1][0], blf[nt2 * 2 + 1][1],
                        pBl + nt2 * 1280 + kk * 32);
            }
#pragma unroll
            for (int nt = 0; nt < 4; nt++) {
#pragma unroll
                for (int mt = 0; mt < 4; mt++) {
                    mma16816(acc[mt][nt], ahf[mt], bhf[nt][0], bhf[nt][1]); // hi*hi
                    mma16816(acc[mt][nt], ahf[mt], blf[nt][0], blf[nt][1]); // hi*lo
                    mma16816(acc[mt][nt], alf[mt], bhf[nt][0], bhf[nt][1]); // lo*hi
                }
            }
        }
    }

    // epilogue
#pragma unroll
    for (int mt = 0; mt < 4; mt++) {
        int r0 = m0 + wm + mt * 16 + gid;
#pragma unroll
        for (int nt = 0; nt < 4; nt++) {
            int c0 = n0 + wn + nt * 8 + tig * 2;
            float bb0 = bias[c0], bb1 = bias[c0 + 1];
            float v0 = acc[mt][nt][0] + bb0;
            float v1 = acc[mt][nt][1] + bb1;
            float v2 = acc[mt][nt][2] + bb0;
            float v3 = acc[mt][nt][3] + bb1;
            if (RELU) {
                v0 = fmaxf(v0, 0.f); v1 = fmaxf(v1, 0.f);
                v2 = fmaxf(v2, 0.f); v3 = fmaxf(v3, 0.f);
            }
            if (SPLIT_OUT) {
                __nv_bfloat162 lo0, lo1;
                __nv_bfloat162 hi0 = split_hi2(v0, v1, lo0);
                __nv_bfloat162 hi1 = split_hi2(v2, v3, lo1);
                *(__nv_bfloat162*)(Ch + (size_t)r0 * N + c0)       = hi0;
                *(__nv_bfloat162*)(Cl + (size_t)r0 * N + c0)       = lo0;
                *(__nv_bfloat162*)(Ch + (size_t)(r0 + 8) * N + c0) = hi1;
                *(__nv_bfloat162*)(Cl + (size_t)(r0 + 8) * N + c0) = lo1;
            } else {
                *(float2*)(C + (size_t)r0 * N + c0)       = make_float2(v0, v1);
                *(float2*)(C + (size_t)(r0 + 8) * N + c0) = make_float2(v2, v3);
            }
        }
    }
}

// ---------------------------------------------------------------------------
// fp32 -> bf16 hi/lo split (elementwise) — only used once, for x
// ---------------------------------------------------------------------------
__global__ __launch_bounds__(256)
void split_bf16(const float4* __restrict__ in,
                __nv_bfloat162* __restrict__ h2, __nv_bfloat162* __restrict__ l2,
                int n4)
{
    int i = blockIdx.x * 256 + threadIdx.x;
    if (i >= n4) return;
    float4 v = in[i];
    __nv_bfloat162 lo0, lo1;
    __nv_bfloat162 hi0 = split_hi2(v.x, v.y, lo0);
    __nv_bfloat162 hi1 = split_hi2(v.z, v.w, lo1);
    h2[2 * i] = hi0; h2[2 * i + 1] = hi1;
    l2[2 * i] = lo0; l2[2 * i + 1] = lo1;
}

// ---------------------------------------------------------------------------
// W[K,N] fp32 -> transposed hi/lo bf16 [N,K]
// ---------------------------------------------------------------------------
__global__ __launch_bounds__(256)
void transpose_split(const float* __restrict__ W,
                     __nv_bfloat16* __restrict__ Th, __nv_bfloat16* __restrict__ Tl,
                     int K, int N)
{
    __shared__ float tile[32][33];
    const int tx = threadIdx.x & 31;
    const int ty = threadIdx.x >> 5;
    const int n0 = blockIdx.x * 32;
    const int k0 = blockIdx.y * 32;
#pragma unroll
    for (int j = 0; j < 4; j++)
        tile[ty + 8 * j][tx] = W[(size_t)(k0 + ty + 8 * j) * N + n0 + tx];
    __syncthreads();
#pragma unroll
    for (int j = 0; j < 4; j++) {
        float v = tile[tx][ty + 8 * j];
        __nv_bfloat16 h = __float2bfloat16(v);
        __nv_bfloat16 l = __float2bfloat16(v - __bfloat162float(h));
        size_t o = (size_t)(n0 + ty + 8 * j) * K + k0 + tx;
        Th[o] = h;
        Tl[o] = l;
    }
}

// ---------------------------------------------------------------------------
// Flash-style causal attention; output written directly as bf16 hi/lo split
// ---------------------------------------------------------------------------
#define ATT_PAD 68

__global__ __launch_bounds__(256)
void attention_kernel(const float* __restrict__ Q, const float* __restrict__ K,
                      const float* __restrict__ V,
                      __nv_bfloat16* __restrict__ Oh, __nv_bfloat16* __restrict__ Ol)
{
    float* smem = (float*)dyn_smem;
    float* QsT = smem;
    float* KsT = QsT + 64 * ATT_PAD;
    float* Vs  = KsT + 64 * ATT_PAD;
    float* Ss  = Vs  + 64 * ATT_PAD;
    float* m_s = Ss + 64 * ATT_PAD;
    float* l_s = m_s + 64;
    float* corr_s = l_s + 64;

    const int tid = threadIdx.x;
    const int qtile = blockIdx.x;
    const int bh = blockIdx.y;
    const int b = bh >> 4;
    const int h = bh & 15;
    const int q0 = qtile * 64;

    const float* Qb = Q + (size_t)b * S_LEN * D_MODEL + h * D_K;
    const float* Kb = K + (size_t)b * S_LEN * D_MODEL + h * D_K;
    const float* Vb = V + (size_t)b * S_LEN * D_MODEL + h * D_K;
    __nv_bfloat16* Obh = Oh + (size_t)b * S_LEN * D_MODEL + h * D_K;
    __nv_bfloat16* Obl = Ol + (size_t)b * S_LEN * D_MODEL + h * D_K;

#pragma unroll
    for (int t = 0; t < 4; t++) {
        int idx = tid + t * 256;
        int r = idx >> 4;
        int c4 = idx & 15;
        float4 v = *(const float4*)(Qb + (size_t)(q0 + r) * D_MODEL + c4 * 4);
        QsT[(c4 * 4 + 0) * ATT_PAD + r] = v.x;
        QsT[(c4 * 4 + 1) * ATT_PAD + r] = v.y;
        QsT[(c4 * 4 + 2) * ATT_PAD + r] = v.z;
        QsT[(c4 * 4 + 3) * ATT_PAD + r] = v.w;
    }
    if (tid < 64) { m_s[tid] = -INFINITY; l_s[tid] = 0.f; }

    const int tr = tid >> 4;
    const int tc = tid & 15;
    float o[4][4];
#pragma unroll
    for (int i = 0; i < 4; i++)
#pragma unroll
        for (int j = 0; j < 4; j++) o[i][j] = 0.f;

    for (int kb = 0; kb <= qtile; kb++) {
        __syncthreads();
#pragma unroll
        for (int t = 0; t < 4; t++) {
            int idx = tid + t * 256;
            int r = idx >> 4;
            int c4 = idx & 15;
            float4 kv = *(const float4*)(Kb + (size_t)(kb * 64 + r) * D_MODEL + c4 * 4);
            KsT[(c4 * 4 + 0) * ATT_PAD + r] = kv.x;
            KsT[(c4 * 4 + 1) * ATT_PAD + r] = kv.y;
            KsT[(c4 * 4 + 2) * ATT_PAD + r] = kv.z;
            KsT[(c4 * 4 + 3) * ATT_PAD + r] = kv.w;
            float4 vv = *(const float4*)(Vb + (size_t)(kb * 64 + r) * D_MODEL + c4 * 4);
            *(float4*)(&Vs[r * ATT_PAD + c4 * 4]) = vv;
        }
        __syncthreads();

        float s[4][4];
#pragma unroll
        for (int i = 0; i < 4; i++)
#pragma unroll
            for (int j = 0; j < 4; j++) s[i][j] = 0.f;
#pragma unroll 8
        for (int d = 0; d < 64; d++) {
            float4 a4 = *(const float4*)(&QsT[d * ATT_PAD + 4 * tr]);
            float4 b4 = *(const float4*)(&KsT[d * ATT_PAD + 4 * tc]);
            float a[4] = {a4.x, a4.y, a4.z, a4.w};
            float bb[4] = {b4.x, b4.y, b4.z, b4.w};
#pragma unroll
            for (int i = 0; i < 4; i++)
#pragma unroll
                for (int j = 0; j < 4; j++)
                    s[i][j] = fmaf(a[i], bb[j], s[i][j]);
        }
#pragma unroll
        for (int i = 0; i < 4; i++) {
#pragma unroll
            for (int j = 0; j < 4; j++) {
                float val = s[i][j] * 0.125f;
                if (kb == qtile && (4 * tc + j) >= (4 * tr + i)) val = -1e30f;
                Ss[(4 * tr + i) * ATT_PAD + (4 * tc + j)] = val;
            }
        }
        __syncthreads();

        {
            int r = tid >> 2;
            int qd = tid & 3;
            float loc[16];
            *(float4*)(loc)      = *(const float4*)(&Ss[r * ATT_PAD + qd * 16]);
            *(float4*)(loc + 4)  = *(const float4*)(&Ss[r * ATT_PAD + qd * 16 + 4]);
            *(float4*)(loc + 8)  = *(const float4*)(&Ss[r * ATT_PAD + qd * 16 + 8]);
            *(float4*)(loc + 12) = *(const float4*)(&Ss[r * ATT_PAD + qd * 16 + 12]);
            float mx = loc[0];
#pragma unroll
            for (int u = 1; u < 16; u++) mx = fmaxf(mx, loc[u]);
            mx = fmaxf(mx, __shfl_xor_sync(0xffffffffu, mx, 1));
            mx = fmaxf(mx, __shfl_xor_sync(0xffffffffu, mx, 2));
            float m_old = m_s[r];
            float m_new = fmaxf(m_old, mx);
            float sum = 0.f;
#pragma unroll
            for (int u = 0; u < 16; u++) {
                loc[u] = __expf(loc[u] - m_new);
                sum += loc[u];
            }
            sum += __shfl_xor_sync(0xffffffffu, sum, 1);
            sum += __shfl_xor_sync(0xffffffffu, sum, 2);
            *(float4*)(&Ss[r * ATT_PAD + qd * 16])      = *(float4*)(loc);
            *(float4*)(&Ss[r * ATT_PAD + qd * 16 + 4])  = *(float4*)(loc + 4);
            *(float4*)(&Ss[r * ATT_PAD + qd * 16 + 8])  = *(float4*)(loc + 8);
            *(float4*)(&Ss[r * ATT_PAD + qd * 16 + 12]) = *(float4*)(loc + 12);
            if (qd == 0) {
                float c = __expf(m_old - m_new);
                corr_s[r] = c;
                l_s[r] = l_s[r] * c + sum;
                m_s[r] = m_new;
            }
        }
        __syncthreads();

#pragma unroll
        for (int i = 0; i < 4; i++) {
            float c = corr_s[4 * tr + i];
#pragma unroll
            for (int j = 0; j < 4; j++) o[i][j] *= c;
        }
#pragma unroll 8
        for (int jj = 0; jj < 64; jj++) {
            float p[4];
#pragma unroll
            for (int i = 0; i < 4; i++) p[i] = Ss[(4 * tr + i) * ATT_PAD + jj];
            float4 vv = *(const float4*)(&Vs[jj * ATT_PAD + 4 * tc]);
#pragma unroll
            for (int i = 0; i < 4; i++) {
                o[i][0] = fmaf(p[i], vv.x, o[i][0]);
                o[i][1] = fmaf(p[i], vv.y, o[i][1]);
                o[i][2] = fmaf(p[i], vv.z, o[i][2]);
                o[i][3] = fmaf(p[i], vv.w, o[i][3]);
            }
        }
    }
    __syncthreads();

    // finalize: /l, zero first global row, write bf16 hi/lo split directly
#pragma unroll
    for (int i = 0; i < 4; i++) {
        int q = 4 * tr + i;
        int gi = q0 + q;
        float inv = 1.f / l_s[q];
        float v0 = o[i][0] * inv, v1 = o[i][1] * inv;
        float v2 = o[i][2] * inv, v3 = o[i][3] * inv;
        if (gi == 0) { v0 = 0.f; v1 = 0.f; v2 = 0.f; v3 = 0.f; }
        __nv_bfloat162 lo0, lo1;
        __nv_bfloat162 hi0 = split_hi2(v0, v1, lo0);
        __nv_bfloat162 hi1 = split_hi2(v2, v3, lo1);
        size_t off = (size_t)gi * D_MODEL + 4 * tc;
        *(__nv_bfloat162*)(Obh + off)     = hi0;
        *(__nv_bfloat162*)(Obh + off + 2) = hi1;
        *(__nv_bfloat162*)(Obl + off)     = lo0;
        *(__nv_bfloat162*)(Obl + off + 2) = lo1;
    }
}

// ---------------------------------------------------------------------------
// Fused residual add + LayerNorm (+ optional bf16 hi/lo split output)
// ---------------------------------------------------------------------------
template <bool SPLIT>
__global__ __launch_bounds__(256)
void add_ln_kernel(const float* __restrict__ A, const float* __restrict__ Bm,
                   const float* __restrict__ g, const float* __restrict__ beta,
                   float* __restrict__ out,
                   __nv_bfloat16* __restrict__ oh, __nv_bfloat16* __restrict__ ol)
{
    __shared__ float red_s[8];
    __shared__ float red_q[8];
    __shared__ float stats[2];

    const int row = blockIdx.x;
    const int c = threadIdx.x * 4;
    const float* a = A + (size_t)row * D_MODEL;
    const float* bm = Bm + (size_t)row * D_MODEL;

    float4 av = *(const float4*)(a + c);
    float4 bv = *(const float4*)(bm + c);
    float v0 = av.x + bv.x, v1 = av.y + bv.y, v2 = av.z + bv.z, v3 = av.w + bv.w;

    float s = v0 + v1 + v2 + v3;
    float q = v0 * v0 + v1 * v1 + v2 * v2 + v3 * v3;
#pragma unroll
    for (int off = 16; off > 0; off >>= 1) {
        s += __shfl_xor_sync(0xffffffffu, s, off);
        q += __shfl_xor_sync(0xffffffffu, q, off);
    }
    if ((threadIdx.x & 31) == 0) {
        red_s[threadIdx.x >> 5] = s;
        red_q[threadIdx.x >> 5] = q;
    }
    __syncthreads();
    if (threadIdx.x < 32) {
        float ts = (threadIdx.x < 8) ? red_s[threadIdx.x] : 0.f;
        float tq = (threadIdx.x < 8) ? red_q[threadIdx.x] : 0.f;
#pragma unroll
        for (int off = 4; off > 0; off >>= 1) {
            ts += __shfl_xor_sync(0xffffffffu, ts, off);
            tq += __shfl_xor_sync(0xffffffffu, tq, off);
        }
        if (threadIdx.x == 0) {
            float mu = ts * (1.f / D_MODEL);
            float var = tq * (1.f / D_MODEL) - mu * mu;
            var = fmaxf(var, 0.f);
            stats[0] = mu;
            stats[1] = rsqrtf(var + 1e-5f);
        }
    }
    __syncthreads();
    const float mu = stats[0];
    const float rstd = stats[1];

    float4 gv = *(const float4*)(g + c);
    float4 bev = *(const float4*)(beta + c);
    float4 ov;
    ov.x = (v0 - mu) * rstd * gv.x + bev.x;
    ov.y = (v1 - mu) * rstd * gv.y + bev.y;
    ov.z = (v2 - mu) * rstd * gv.z + bev.z;
    ov.w = (v3 - mu) * rstd * gv.w + bev.w;
    *(float4*)(out + (size_t)row * D_MODEL + c) = ov;
    if (SPLIT) {
        __nv_bfloat162 lo0, lo1;
        __nv_bfloat162 hi0 = split_hi2(ov.x, ov.y, lo0);
        __nv_bfloat162 hi1 = split_hi2(ov.z, ov.w, lo1);
        size_t off = (size_t)row * D_MODEL + c;
        *(__nv_bfloat162*)(oh + off)     = hi0;
        *(__nv_bfloat162*)(oh + off + 2) = hi1;
        *(__nv_bfloat162*)(ol + off)     = lo0;
        *(__nv_bfloat162*)(ol + off + 2) = lo1;
    }
}

// ---------------------------------------------------------------------------
// Launch
// ---------------------------------------------------------------------------
static inline float* sym(const void* s) {
    void* p = nullptr;
    cudaGetSymbolAddress(&p, s);
    return (float*)p;
}

extern "C" void kernel_launch(void* const* d_in, const int* in_sizes, int n_in,
                              void* d_out, int out_size)
{
    const float* x   = (const float*)d_in[0];
    const float* Wq  = (const float*)d_in[1];
    const float* bq  = (const float*)d_in[2];
    const float* Wk  = (const float*)d_in[3];
    const float* bk  = (const float*)d_in[4];
    const float* Wv  = (const float*)d_in[5];
    const float* bv  = (const float*)d_in[6];
    const float* Wo  = (const float*)d_in[7];
    const float* bo  = (const float*)d_in[8];
    const float* W1  = (const float*)d_in[9];
    const float* b1  = (const float*)d_in[10];
    const float* W2  = (const float*)d_in[11];
    const float* b2  = (const float*)d_in[12];
    const float* g1  = (const float*)d_in[13];
    const float* be1 = (const float*)d_in[14];
    const float* g3  = (const float*)d_in[15];
    const float* be3 = (const float*)d_in[16];
    float* out = (float*)d_out;

    float* q   = sym(g_q);
    float* k   = sym(g_k);
    float* v   = sym(g_v);
    float* h1  = sym(g_h1);
    __nv_bfloat16* sah = (__nv_bfloat16*)sym(g_sa_h);
    __nv_bfloat16* sal = (__nv_bfloat16*)sym(g_sa_l);
    __nv_bfloat16* sbh = (__nv_bfloat16*)sym(g_sb_h);
    __nv_bfloat16* sbl = (__nv_bfloat16*)sym(g_sb_l);
    __nv_bfloat16* wqh = (__nv_bfloat16*)sym(g_wq_h);
    __nv_bfloat16* wql = (__nv_bfloat16*)sym(g_wq_l);
    __nv_bfloat16* wkh = (__nv_bfloat16*)sym(g_wk_h);
    __nv_bfloat16* wkl = (__nv_bfloat16*)sym(g_wk_l);
    __nv_bfloat16* wvh = (__nv_bfloat16*)sym(g_wv_h);
    __nv_bfloat16* wvl = (__nv_bfloat16*)sym(g_wv_l);
    __nv_bfloat16* woh = (__nv_bfloat16*)sym(g_wo_h);
    __nv_bfloat16* wol = (__nv_bfloat16*)sym(g_wo_l);
    __nv_bfloat16* w1h = (__nv_bfloat16*)sym(g_w1_h);
    __nv_bfloat16* w1l = (__nv_bfloat16*)sym(g_w1_l);
    __nv_bfloat16* w2h = (__nv_bfloat16*)sym(g_w2_h);
    __nv_bfloat16* w2l = (__nv_bfloat16*)sym(g_w2_l);

    const int att_smem = (4 * 64 * ATT_PAD + 3 * 64) * (int)sizeof(float);
    cudaFuncSetAttribute(attention_kernel,
                         cudaFuncAttributeMaxDynamicSharedMemorySize, att_smem);
    cudaFuncSetAttribute(gemm_mma<false, false>,
                         cudaFuncAttributeMaxDynamicSharedMemorySize, GM_SMEM);
    cudaFuncSetAttribute(gemm_mma<true, true>,
                         cudaFuncAttributeMaxDynamicSharedMemorySize, GM_SMEM);

    dim3 tb(256);

    // weight transposes + splits  (W[K,N] -> [N,K] hi/lo)
    transpose_split<<<dim3(D_MODEL / 32, D_MODEL / 32), tb>>>(Wq, wqh, wql, D_MODEL, D_MODEL);
    transpose_split<<<dim3(D_MODEL / 32, D_MODEL / 32), tb>>>(Wk, wkh, wkl, D_MODEL, D_MODEL);
    transpose_split<<<dim3(D_MODEL / 32, D_MODEL / 32), tb>>>(Wv, wvh, wvl, D_MODEL, D_MODEL);
    transpose_split<<<dim3(D_MODEL / 32, D_MODEL / 32), tb>>>(Wo, woh, wol, D_MODEL, D_MODEL);
    transpose_split<<<dim3(D_FF / 32, D_MODEL / 32), tb>>>(W1, w1h, w1l, D_MODEL, D_FF);
    transpose_split<<<dim3(D_MODEL / 32, D_FF / 32), tb>>>(W2, w2h, w2l, D_FF, D_MODEL);

    const int n4_x = (M_ROWS * D_MODEL) / 4;
    dim3 gProj(D_MODEL / 128, M_ROWS / 128);   // (8, 64)
    dim3 gFF1(D_FF / 128, M_ROWS / 128);       // (32, 64)

    // x split (the only standalone split)
    split_bf16<<<n4_x / 256, tb>>>((const float4*)x,
                                   (__nv_bfloat162*)sah, (__nv_bfloat162*)sal, n4_x);

    // QKV projections (fp32 out)
    gemm_mma<false, false><<<gProj, tb, GM_SMEM>>>(sah, sal, wqh, wql, bq, q, nullptr, nullptr, M_ROWS, D_MODEL, D_MODEL);
    gemm_mma<false, false><<<gProj, tb, GM_SMEM>>>(sah, sal, wkh, wkl, bk, k, nullptr, nullptr, M_ROWS, D_MODEL, D_MODEL);
    gemm_mma<false, false><<<gProj, tb, GM_SMEM>>>(sah, sal, wvh, wvl, bv, v, nullptr, nullptr, M_ROWS, D_MODEL, D_MODEL);

    // causal attention -> ctx split (sB)
    attention_kernel<<<dim3(S_LEN / 64, B_SZ * N_HEADS), tb, att_smem>>>(q, k, v, sbh, sbl);

    // output projection: attn_out fp32 (reuse q)
    gemm_mma<false, false><<<gProj, tb, GM_SMEM>>>(sbh, sbl, woh, wol, bo, q, nullptr, nullptr, M_ROWS, D_MODEL, D_MODEL);

    // h1 = LN(x + attn_out), also emit h1 split into sA
    add_ln_kernel<true><<<M_ROWS, tb>>>(x, q, g1, be1, h1, sah, sal);

    // FFN1: ReLU(h1 @ W1 + b1) -> split directly into sB [M, D_FF]
    gemm_mma<true, true><<<gFF1, tb, GM_SMEM>>>(sah, sal, w1h, w1l, b1, nullptr, sbh, sbl, M_ROWS, D_FF, D_MODEL);

    // FFN2: fp32 out (reuse v)
    gemm_mma<false, false><<<gProj, tb, GM_SMEM>>>(sbh, sbl, w2h, w2l, b2, v, nullptr, nullptr, M_ROWS, D_MODEL, D_FF);

    // out = LN(h1 + ffn)
    add_ln_kernel<false><<<M_ROWS, tb>>>(h1, v, g3, be3, out, nullptr, nullptr);
}

// round 12
// speedup vs baseline: 2.2661x; 1.1775x over previous
#include <cuda_runtime.h>
#include <cuda_bf16.h>
#include <math.h>
#include <stdint.h>

#define B_SZ 8
#define S_LEN 1024
#define D_MODEL 1024
#define N_HEADS 16
#define D_K 64
#define D_FF 4096
#define M_ROWS (B_SZ * S_LEN)

extern __shared__ char dyn_smem[];

// ---- scratch globals ----
__device__ float g_attn[(size_t)M_ROWS * D_MODEL];
__device__ float g_ffn[(size_t)M_ROWS * D_MODEL];
__device__ float g_h1[(size_t)M_ROWS * D_MODEL];
__device__ __nv_bfloat16 g_sa_h[(size_t)M_ROWS * D_MODEL];
__device__ __nv_bfloat16 g_sa_l[(size_t)M_ROWS * D_MODEL];
__device__ __nv_bfloat16 g_sb_h[(size_t)M_ROWS * D_FF];
__device__ __nv_bfloat16 g_sb_l[(size_t)M_ROWS * D_FF];
__device__ __nv_bfloat16 g_qh[(size_t)M_ROWS * D_MODEL];
__device__ __nv_bfloat16 g_ql[(size_t)M_ROWS * D_MODEL];
__device__ __nv_bfloat16 g_kh[(size_t)M_ROWS * D_MODEL];
__device__ __nv_bfloat16 g_kl[(size_t)M_ROWS * D_MODEL];
__device__ __nv_bfloat16 g_vh[(size_t)M_ROWS * D_MODEL];
__device__ __nv_bfloat16 g_vl[(size_t)M_ROWS * D_MODEL];
__device__ __nv_bfloat16 g_wq_h[(size_t)D_MODEL * D_MODEL];
__device__ __nv_bfloat16 g_wq_l[(size_t)D_MODEL * D_MODEL];
__device__ __nv_bfloat16 g_wk_h[(size_t)D_MODEL * D_MODEL];
__device__ __nv_bfloat16 g_wk_l[(size_t)D_MODEL * D_MODEL];
__device__ __nv_bfloat16 g_wv_h[(size_t)D_MODEL * D_MODEL];
__device__ __nv_bfloat16 g_wv_l[(size_t)D_MODEL * D_MODEL];
__device__ __nv_bfloat16 g_wo_h[(size_t)D_MODEL * D_MODEL];
__device__ __nv_bfloat16 g_wo_l[(size_t)D_MODEL * D_MODEL];
__device__ __nv_bfloat16 g_w1_h[(size_t)D_FF * D_MODEL];
__device__ __nv_bfloat16 g_w1_l[(size_t)D_FF * D_MODEL];
__device__ __nv_bfloat16 g_w2_h[(size_t)D_MODEL * D_FF];
__device__ __nv_bfloat16 g_w2_l[(size_t)D_MODEL * D_FF];

// ---- PTX helpers ----
static __device__ __forceinline__ uint32_t smem_u32(const void* p) {
    uint32_t a;
    asm("{ .reg .u64 t; cvta.to.shared.u64 t, %1; cvt.u32.u64 %0, t; }" : "=r"(a) : "l"(p));
    return a;
}
#define CP_ASYNC16(dst, src) \
    asm volatile("cp.async.cg.shared.global [%0], [%1], 16;" :: "r"((uint32_t)(dst)), "l"(src))
#define CP_COMMIT() asm volatile("cp.async.commit_group;" ::: "memory")
#define LDSM_X4(R0, R1, R2, R3, ADDR) \
    asm volatile("ldmatrix.sync.aligned.m8n8.x4.shared.b16 {%0,%1,%2,%3}, [%4];" \
                 : "=r"(R0), "=r"(R1), "=r"(R2), "=r"(R3) : "r"(ADDR))
#define LDSM_X4_T(R0, R1, R2, R3, ADDR) \
    asm volatile("ldmatrix.sync.aligned.m8n8.x4.trans.shared.b16 {%0,%1,%2,%3}, [%4];" \
                 : "=r"(R0), "=r"(R1), "=r"(R2), "=r"(R3) : "r"(ADDR))

static __device__ __forceinline__ void mma16816(float* d, const uint32_t* a, uint32_t b0, uint32_t b1)
{
    asm volatile(
        "mma.sync.aligned.m16n8k16.row.col.f32.bf16.bf16.f32 "
        "{%0,%1,%2,%3}, {%4,%5,%6,%7}, {%8,%9}, {%0,%1,%2,%3};"
        : "+f"(d[0]), "+f"(d[1]), "+f"(d[2]), "+f"(d[3])
        : "r"(a[0]), "r"(a[1]), "r"(a[2]), "r"(a[3]), "r"(b0), "r"(b1));
}

static __device__ __forceinline__ __nv_bfloat162 split_hi2(float a, float b, __nv_bfloat162& lo)
{
    __nv_bfloat16 h0 = __float2bfloat16(a);
    __nv_bfloat16 h1 = __float2bfloat16(b);
    lo = __nv_bfloat162(__float2bfloat16(a - __bfloat162float(h0)),
                        __float2bfloat16(b - __bfloat162float(h1)));
    return __nv_bfloat162(h0, h1);
}
static __device__ __forceinline__ uint32_t pack_split(float a, float b, uint32_t& lo_u)
{
    __nv_bfloat162 lo;
    __nv_bfloat162 hi = split_hi2(a, b, lo);
    lo_u = *reinterpret_cast<uint32_t*>(&lo);
    return *reinterpret_cast<uint32_t*>(&hi);
}

// ---------------------------------------------------------------------------
// GEMM (unchanged from R10, proven): CTA 128x128, BK=32, 3-term split
// ---------------------------------------------------------------------------
#define GM_BUFSZ 40960
#define GM_SMEM  (3 * GM_BUFSZ)

static __device__ __forceinline__ void load_chunk(
    uint32_t sdst, const __nv_bfloat16* aH, const __nv_bfloat16* aL,
    const __nv_bfloat16* bH, const __nv_bfloat16* bL, int kb, int K, int tid)
{
#pragma unroll
    for (int j = 0; j < 2; j++) {
        int idx = tid + j * 256;
        int r = idx >> 2;
        int s = idx & 3;
        uint32_t doff = (uint32_t)(r * 80 + s * 16);
        size_t goff = (size_t)r * K + kb;
        CP_ASYNC16(sdst + doff,         (const char*)(aH + goff) + s * 16);
        CP_ASYNC16(sdst + 10240 + doff, (const char*)(aL + goff) + s * 16);
        CP_ASYNC16(sdst + 20480 + doff, (const char*)(bH + goff) + s * 16);
        CP_ASYNC16(sdst + 30720 + doff, (const char*)(bL + goff) + s * 16);
    }
}

template <bool RELU, bool SPLIT_OUT>
__global__ __launch_bounds__(256, 1)
void gemm_mma(const __nv_bfloat16* __restrict__ Ah, const __nv_bfloat16* __restrict__ Al,
              const __nv_bfloat16* __restrict__ Bh, const __nv_bfloat16* __restrict__ Bl,
              const float* __restrict__ bias, float* __restrict__ C,
              __nv_bfloat16* __restrict__ Ch, __nv_bfloat16* __restrict__ Cl,
              int M, int N, int K)
{
    const uint32_t sbase = smem_u32(dyn_smem);
    const int tid = threadIdx.x;
    const int wid = tid >> 5;
    const int lane = tid & 31;
    const int gid = lane >> 2;
    const int tig = lane & 3;
    const int n0 = blockIdx.x * 128;
    const int m0 = blockIdx.y * 128;
    const int wm = (wid >> 2) * 64;
    const int wn = (wid & 3) * 32;
    const int nch = K >> 5;

    const __nv_bfloat16* aH = Ah + (size_t)m0 * K;
    const __nv_bfloat16* aL = Al + (size_t)m0 * K;
    const __nv_bfloat16* bH = Bh + (size_t)n0 * K;
    const __nv_bfloat16* bL = Bl + (size_t)n0 * K;

    const uint32_t offA = (uint32_t)((wm + ((lane >> 3) & 1) * 8 + (lane & 7)) * 80 + (lane >> 4) * 16);
    const uint32_t offB = (uint32_t)((wn + (lane >> 4) * 8 + (lane & 7)) * 80 + ((lane >> 3) & 1) * 16);

    float acc[4][4][4];
#pragma unroll
    for (int mt = 0; mt < 4; mt++)
#pragma unroll
        for (int nt = 0; nt < 4; nt++)
#pragma unroll
            for (int u = 0; u < 4; u++) acc[mt][nt][u] = 0.f;

    load_chunk(sbase,            aH, aL, bH, bL, 0,  K, tid);
    CP_COMMIT();
    load_chunk(sbase + GM_BUFSZ, aH, aL, bH, bL, 32, K, tid);
    CP_COMMIT();

    for (int ch = 0; ch < nch; ch++) {
        if (ch == nch - 1) asm volatile("cp.async.wait_group 0;" ::: "memory");
        else               asm volatile("cp.async.wait_group 1;" ::: "memory");
        __syncthreads();

        if (ch + 2 < nch) {
            load_chunk(sbase + ((ch + 2) % 3) * GM_BUFSZ, aH, aL, bH, bL, (ch + 2) * 32, K, tid);
            CP_COMMIT();
        }

        const uint32_t buf = sbase + (ch % 3) * GM_BUFSZ;
        const uint32_t pAh = buf + offA;
        const uint32_t pAl = buf + 10240 + offA;
        const uint32_t pBh = buf + 20480 + offB;
        const uint32_t pBl = buf + 30720 + offB;

#pragma unroll
        for (int kk = 0; kk < 2; kk++) {
            uint32_t ahf[4][4], alf[4][4], bhf[4][2], blf[4][2];
#pragma unroll
            for (int mt = 0; mt < 4; mt++) {
                LDSM_X4(ahf[mt][0], ahf[mt][1], ahf[mt][2], ahf[mt][3], pAh + mt * 1280 + kk * 32);
                LDSM_X4(alf[mt][0], alf[mt][1], alf[mt][2], alf[mt][3], pAl + mt * 1280 + kk * 32);
            }
#pragma unroll
            for (int nt2 = 0; nt2 < 2; nt2++) {
                LDSM_X4(bhf[nt2 * 2][0], bhf[nt2 * 2][1], bhf[nt2 * 2 + 1][0], bhf[nt2 * 2 + 1][1],
                        pBh + nt2 * 1280 + kk * 32);
                LDSM_X4(blf[nt2 * 2][0], blf[nt2 * 2][1], blf[nt2 * 2 + 1][0], blf[nt2 * 2 + 1][1],
                        pBl + nt2 * 1280 + kk * 32);
            }
#pragma unroll
            for (int nt = 0; nt < 4; nt++) {
#pragma unroll
                for (int mt = 0; mt < 4; mt++) {
                    mma16816(acc[mt][nt], ahf[mt], bhf[nt][0], bhf[nt][1]);
                    mma16816(acc[mt][nt], ahf[mt], blf[nt][0], blf[nt][1]);
                    mma16816(acc[mt][nt], alf[mt], bhf[nt][0], bhf[nt][1]);
                }
            }
        }
    }

#pragma unroll
    for (int mt = 0; mt < 4; mt++) {
        int r0 = m0 + wm + mt * 16 + gid;
#pragma unroll
        for (int nt = 0; nt < 4; nt++) {
            int c0 = n0 + wn + nt * 8 + tig * 2;
            float bb0 = bias[c0], bb1 = bias[c0 + 1];
            float v0 = acc[mt][nt][0] + bb0;
            float v1 = acc[mt][nt][1] + bb1;
            float v2 = acc[mt][nt][2] + bb0;
            float v3 = acc[mt][nt][3] + bb1;
            if (RELU) {
                v0 = fmaxf(v0, 0.f); v1 = fmaxf(v1, 0.f);
                v2 = fmaxf(v2, 0.f); v3 = fmaxf(v3, 0.f);
            }
            if (SPLIT_OUT) {
                __nv_bfloat162 lo0, lo1;
                __nv_bfloat162 hi0 = split_hi2(v0, v1, lo0);
                __nv_bfloat162 hi1 = split_hi2(v2, v3, lo1);
                *(__nv_bfloat162*)(Ch + (size_t)r0 * N + c0)       = hi0;
                *(__nv_bfloat162*)(Cl + (size_t)r0 * N + c0)       = lo0;
                *(__nv_bfloat162*)(Ch + (size_t)(r0 + 8) * N + c0) = hi1;
                *(__nv_bfloat162*)(Cl + (size_t)(r0 + 8) * N + c0) = lo1;
            } else {
                *(float2*)(C + (size_t)r0 * N + c0)       = make_float2(v0, v1);
                *(float2*)(C + (size_t)(r0 + 8) * N + c0) = make_float2(v2, v3);
            }
        }
    }
}

// ---------------------------------------------------------------------------
// split / transpose prep
// ---------------------------------------------------------------------------
__global__ __launch_bounds__(256)
void split_bf16(const float4* __restrict__ in,
                __nv_bfloat162* __restrict__ h2, __nv_bfloat162* __restrict__ l2, int n4)
{
    int i = blockIdx.x * 256 + threadIdx.x;
    if (i >= n4) return;
    float4 v = in[i];
    __nv_bfloat162 lo0, lo1;
    __nv_bfloat162 hi0 = split_hi2(v.x, v.y, lo0);
    __nv_bfloat162 hi1 = split_hi2(v.z, v.w, lo1);
    h2[2 * i] = hi0; h2[2 * i + 1] = hi1;
    l2[2 * i] = lo0; l2[2 * i + 1] = lo1;
}

__global__ __launch_bounds__(256)
void transpose_split(const float* __restrict__ W,
                     __nv_bfloat16* __restrict__ Th, __nv_bfloat16* __restrict__ Tl,
                     int K, int N)
{
    __shared__ float tile[32][33];
    const int tx = threadIdx.x & 31;
    const int ty = threadIdx.x >> 5;
    const int n0 = blockIdx.x * 32;
    const int k0 = blockIdx.y * 32;
#pragma unroll
    for (int j = 0; j < 4; j++)
        tile[ty + 8 * j][tx] = W[(size_t)(k0 + ty + 8 * j) * N + n0 + tx];
    __syncthreads();
#pragma unroll
    for (int j = 0; j < 4; j++) {
        float v = tile[tx][ty + 8 * j];
        __nv_bfloat16 h = __float2bfloat16(v);
        __nv_bfloat16 l = __float2bfloat16(v - __bfloat162float(h));
        size_t o = (size_t)(n0 + ty + 8 * j) * K + k0 + tx;
        Th[o] = h;
        Tl[o] = l;
    }
}

// ---------------------------------------------------------------------------
// Tensor-core causal attention (bf16x3). CTA = 128 queries x one (b,h).
// 8 warps x 16 query rows. smem: Q hi/lo (2x18432) + 3 KV bufs (4x9216 each).
// ---------------------------------------------------------------------------
#define AT_STR  144
#define AT_QSZ  36864
#define AT_BUF  36864
#define AT_SMEM (AT_QSZ + 3 * AT_BUF)

static __device__ __forceinline__ void load_kv(
    uint32_t dst, const __nv_bfloat16* Kh, const __nv_bfloat16* Kl,
    const __nv_bfloat16* Vh, const __nv_bfloat16* Vl, size_t rowbase, int kb, int tid)
{
#pragma unroll
    for (int j = 0; j < 2; j++) {
        int idx = tid + j * 256;
        int r = idx >> 3;
        int s = idx & 7;
        uint32_t doff = (uint32_t)(r * AT_STR + s * 16);
        size_t g = rowbase + (size_t)(kb * 64 + r) * D_MODEL + s * 8;
        CP_ASYNC16(dst + doff,         Kh + g);
        CP_ASYNC16(dst + 9216 + doff,  Kl + g);
        CP_ASYNC16(dst + 18432 + doff, Vh + g);
        CP_ASYNC16(dst + 27648 + doff, Vl + g);
    }
}

__global__ __launch_bounds__(256, 1)
void attention_mma(const __nv_bfloat16* __restrict__ Qh, const __nv_bfloat16* __restrict__ Ql,
                   const __nv_bfloat16* __restrict__ Kh, const __nv_bfloat16* __restrict__ Kl,
                   const __nv_bfloat16* __restrict__ Vh, const __nv_bfloat16* __restrict__ Vl,
                   __nv_bfloat16* __restrict__ Oh, __nv_bfloat16* __restrict__ Ol)
{
    const uint32_t sb = smem_u32(dyn_smem);
    const int tid = threadIdx.x;
    const int wid = tid >> 5;
    const int lane = tid & 31;
    const int gid = lane >> 2;
    const int tig = lane & 3;
    const int qblk = blockIdx.x;
    const int bh = blockIdx.y;
    const int b = bh >> 4;
    const int h = bh & 15;
    const int q0 = qblk * 128;
    const size_t rowbase = (size_t)b * S_LEN * D_MODEL + h * D_K;
    const int nkb = 2 * qblk + 2;

    // stage Q (hi @0, lo @18432)
#pragma unroll
    for (int j = 0; j < 4; j++) {
        int idx = tid + j * 256;
        int r = idx >> 3;
        int s = idx & 7;
        size_t g = rowbase + (size_t)(q0 + r) * D_MODEL + s * 8;
        uint32_t doff = (uint32_t)(r * AT_STR + s * 16);
        CP_ASYNC16(sb + doff,         Qh + g);
        CP_ASYNC16(sb + 18432 + doff, Ql + g);
    }
    CP_COMMIT();
    load_kv(sb + AT_QSZ,          Kh, Kl, Vh, Vl, rowbase, 0, tid); CP_COMMIT();
    load_kv(sb + AT_QSZ + AT_BUF, Kh, Kl, Vh, Vl, rowbase, 1, tid); CP_COMMIT();

    uint32_t qhf[4][4], qlf[4][4];
    float m0 = -INFINITY, m1 = -INFINITY, l0 = 0.f, l1 = 0.f;
    float o[8][4];
#pragma unroll
    for (int t = 0; t < 8; t++)
#pragma unroll
        for (int u = 0; u < 4; u++) o[t][u] = 0.f;

    const uint32_t offQ = sb + (uint32_t)((wid * 16 + ((lane >> 3) & 1) * 8 + (lane & 7)) * AT_STR +
                                          (lane >> 4) * 16);
    const uint32_t offBK = (uint32_t)(((lane >> 4) * 8 + (lane & 7)) * AT_STR + ((lane >> 3) & 1) * 16);
    const uint32_t offBV = (uint32_t)((lane & 15) * AT_STR + (lane >> 4) * 16);

    for (int kb = 0; kb < nkb; kb++) {
        if (kb + 1 < nkb) asm volatile("cp.async.wait_group 1;" ::: "memory");
        else              asm volatile("cp.async.wait_group 0;" ::: "memory");
        __syncthreads();

        if (kb == 0) {
#pragma unroll
            for (int kk = 0; kk < 4; kk++) {
                LDSM_X4(qhf[kk][0], qhf[kk][1], qhf[kk][2], qhf[kk][3], offQ + kk * 32);
                LDSM_X4(qlf[kk][0], qlf[kk][1], qlf[kk][2], qlf[kk][3], offQ + 18432 + kk * 32);
            }
        }
        if (kb + 2 < nkb) {
            load_kv(sb + AT_QSZ + ((kb + 2) % 3) * AT_BUF, Kh, Kl, Vh, Vl, rowbase, kb + 2, tid);
            CP_COMMIT();
        }

        const uint32_t kbuf = sb + AT_QSZ + (kb % 3) * AT_BUF;

        // S = Q @ K^T (3-term)
        float sc[8][4];
#pragma unroll
        for (int t = 0; t < 8; t++)
#pragma unroll
            for (int u = 0; u < 4; u++) sc[t][u] = 0.f;
#pragma unroll
        for (int kk = 0; kk < 4; kk++) {
#pragma unroll
            for (int p = 0; p < 4; p++) {
                uint32_t a = kbuf + p * (16 * AT_STR) + offBK + kk * 32;
                uint32_t h0, h1, h2, h3, e0, e1, e2, e3;
                LDSM_X4(h0, h1, h2, h3, a);
                LDSM_X4(e0, e1, e2, e3, a + 9216);
                mma16816(sc[2 * p],     qhf[kk], h0, h1);
                mma16816(sc[2 * p],     qhf[kk], e0, e1);
                mma16816(sc[2 * p],     qlf[kk], h0, h1);
                mma16816(sc[2 * p + 1], qhf[kk], h2, h3);
                mma16816(sc[2 * p + 1], qhf[kk], e2, e3);
                mma16816(sc[2 * p + 1], qlf[kk], h2, h3);
            }
        }
#pragma unroll
        for (int t = 0; t < 8; t++)
#pragma unroll
            for (int u = 0; u < 4; u++) sc[t][u] *= 0.125f;
        if (kb >= 2 * qblk) {   // only diagonal-adjacent blocks need masking
            int r0 = q0 + wid * 16 + gid;
            int cb = kb * 64 + tig * 2;
#pragma unroll
            for (int t = 0; t < 8; t++) {
                int col = cb + t * 8;
                if (col     >= r0)     sc[t][0] = -1e30f;
                if (col + 1 >= r0)     sc[t][1] = -1e30f;
                if (col     >= r0 + 8) sc[t][2] = -1e30f;
                if (col + 1 >= r0 + 8) sc[t][3] = -1e30f;
            }
        }

        // online softmax (register-resident; reduce over tig bits)
        float mx0 = -INFINITY, mx1 = -INFINITY;
#pragma unroll
        for (int t = 0; t < 8; t++) {
            mx0 = fmaxf(mx0, fmaxf(sc[t][0], sc[t][1]));
            mx1 = fmaxf(mx1, fmaxf(sc[t][2], sc[t][3]));
        }
        mx0 = fmaxf(mx0, __shfl_xor_sync(0xffffffffu, mx0, 1));
        mx0 = fmaxf(mx0, __shfl_xor_sync(0xffffffffu, mx0, 2));
        mx1 = fmaxf(mx1, __shfl_xor_sync(0xffffffffu, mx1, 1));
        mx1 = fmaxf(mx1, __shfl_xor_sync(0xffffffffu, mx1, 2));
        float mn0 = fmaxf(m0, mx0);
        float mn1 = fmaxf(m1, mx1);
        float cr0 = __expf(m0 - mn0);
        float cr1 = __expf(m1 - mn1);
        float sum0 = 0.f, sum1 = 0.f;
#pragma unroll
        for (int t = 0; t < 8; t++) {
            sc[t][0] = __expf(sc[t][0] - mn0); sum0 += sc[t][0];
            sc[t][1] = __expf(sc[t][1] - mn0); sum0 += sc[t][1];
            sc[t][2] = __expf(sc[t][2] - mn1); sum1 += sc[t][2];
            sc[t][3] = __expf(sc[t][3] - mn1); sum1 += sc[t][3];
        }
        sum0 += __shfl_xor_sync(0xffffffffu, sum0, 1);
        sum0 += __shfl_xor_sync(0xffffffffu, sum0, 2);
        sum1 += __shfl_xor_sync(0xffffffffu, sum1, 1);
        sum1 += __shfl_xor_sync(0xffffffffu, sum1, 2);
        l0 = l0 * cr0 + sum0;
        l1 = l1 * cr1 + sum1;
        m0 = mn0; m1 = mn1;
#pragma unroll
        for (int t = 0; t < 8; t++) {
            o[t][0] *= cr0; o[t][1] *= cr0;
            o[t][2] *= cr1; o[t][3] *= cr1;
        }

        // O += P @ V (3-term; P repacked C->A in registers; V via ldmatrix.trans)
        const uint32_t vbuf = kbuf + 18432;
#pragma unroll
        for (int kk = 0; kk < 4; kk++) {
            uint32_t ph[4], pl[4];
            ph[0] = pack_split(sc[2 * kk][0],     sc[2 * kk][1],     pl[0]);
            ph[1] = pack_split(sc[2 * kk][2],     sc[2 * kk][3],     pl[1]);
            ph[2] = pack_split(sc[2 * kk + 1][0], sc[2 * kk + 1][1], pl[2]);
            ph[3] = pack_split(sc[2 * kk + 1][2], sc[2 * kk + 1][3], pl[3]);
#pragma unroll
            for (int dp = 0; dp < 4; dp++) {
                uint32_t a = vbuf + kk * (16 * AT_STR) + dp * 32 + offBV;
                uint32_t vh0, vh1, vh2, vh3, w0, w1, w2, w3;
                LDSM_X4_T(vh0, vh1, vh2, vh3, a);
                LDSM_X4_T(w0, w1, w2, w3, a + 9216);
                mma16816(o[2 * dp],     ph, vh0, vh1);
                mma16816(o[2 * dp],     pl, vh0, vh1);
                mma16816(o[2 * dp],     ph, w0, w1);
                mma16816(o[2 * dp + 1], ph, vh2, vh3);
                mma16816(o[2 * dp + 1], pl, vh2, vh3);
                mma16816(o[2 * dp + 1], ph, w2, w3);
            }
        }
    }

    // finalize: /l, zero global first query row (zero_pad), write hi/lo split
    const int srow0 = q0 + wid * 16 + gid;
    const int srow1 = srow0 + 8;
    const float inv0 = (srow0 == 0) ? 0.f : 1.f / l0;
    const float inv1 = 1.f / l1;
#pragma unroll
    for (int t = 0; t < 8; t++) {
        int d = t * 8 + tig * 2;
        float v0 = o[t][0] * inv0, v1 = o[t][1] * inv0;
        float v2 = o[t][2] * inv1, v3 = o[t][3] * inv1;
        __nv_bfloat162 lo0, lo1;
        __nv_bfloat162 hi0 = split_hi2(v0, v1, lo0);
        __nv_bfloat162 hi1 = split_hi2(v2, v3, lo1);
        size_t off0 = rowbase + (size_t)srow0 * D_MODEL + d;
        size_t off1 = rowbase + (size_t)srow1 * D_MODEL + d;
        *(__nv_bfloat162*)(Oh + off0) = hi0;
        *(__nv_bfloat162*)(Ol + off0) = lo0;
        *(__nv_bfloat162*)(Oh + off1) = hi1;
        *(__nv_bfloat162*)(Ol + off1) = lo1;
    }
}

// ---------------------------------------------------------------------------
// Fused residual add + LayerNorm (+ optional split output)
// ---------------------------------------------------------------------------
template <bool SPLIT>
__global__ __launch_bounds__(256)
void add_ln_kernel(const float* __restrict__ A, const float* __restrict__ Bm,
                   const float* __restrict__ g, const float* __restrict__ beta,
                   float* __restrict__ out,
                   __nv_bfloat16* __restrict__ oh, __nv_bfloat16* __restrict__ ol)
{
    __shared__ float red_s[8];
    __shared__ float red_q[8];
    __shared__ float stats[2];

    const int row = blockIdx.x;
    const int c = threadIdx.x * 4;
    float4 av = *(const float4*)(A + (size_t)row * D_MODEL + c);
    float4 bv = *(const float4*)(Bm + (size_t)row * D_MODEL + c);
    float v0 = av.x + bv.x, v1 = av.y + bv.y, v2 = av.z + bv.z, v3 = av.w + bv.w;

    float s = v0 + v1 + v2 + v3;
    float q = v0 * v0 + v1 * v1 + v2 * v2 + v3 * v3;
#pragma unroll
    for (int off = 16; off > 0; off >>= 1) {
        s += __shfl_xor_sync(0xffffffffu, s, off);
        q += __shfl_xor_sync(0xffffffffu, q, off);
    }
    if ((threadIdx.x & 31) == 0) {
        red_s[threadIdx.x >> 5] = s;
        red_q[threadIdx.x >> 5] = q;
    }
    __syncthreads();
    if (threadIdx.x < 32) {
        float ts = (threadIdx.x < 8) ? red_s[threadIdx.x] : 0.f;
        float tq = (threadIdx.x < 8) ? red_q[threadIdx.x] : 0.f;
#pragma unroll
        for (int off = 4; off > 0; off >>= 1) {
            ts += __shfl_xor_sync(0xffffffffu, ts, off);
            tq += __shfl_xor_sync(0xffffffffu, tq, off);
        }
        if (threadIdx.x == 0) {
            float mu = ts * (1.f / D_MODEL);
            float var = tq * (1.f / D_MODEL) - mu * mu;
            stats[0] = mu;
            stats[1] = rsqrtf(fmaxf(var, 0.f) + 1e-5f);
        }
    }
    __syncthreads();
    const float mu = stats[0];
    const float rstd = stats[1];

    float4 gv = *(const float4*)(g + c);
    float4 bev = *(const float4*)(beta + c);
    float4 ov;
    ov.x = (v0 - mu) * rstd * gv.x + bev.x;
    ov.y = (v1 - mu) * rstd * gv.y + bev.y;
    ov.z = (v2 - mu) * rstd * gv.z + bev.z;
    ov.w = (v3 - mu) * rstd * gv.w + bev.w;
    *(float4*)(out + (size_t)row * D_MODEL + c) = ov;
    if (SPLIT) {
        __nv_bfloat162 lo0, lo1;
        __nv_bfloat162 hi0 = split_hi2(ov.x, ov.y, lo0);
        __nv_bfloat162 hi1 = split_hi2(ov.z, ov.w, lo1);
        size_t off = (size_t)row * D_MODEL + c;
        *(__nv_bfloat162*)(oh + off)     = hi0;
        *(__nv_bfloat162*)(oh + off + 2) = hi1;
        *(__nv_bfloat162*)(ol + off)     = lo0;
        *(__nv_bfloat162*)(ol + off + 2) = lo1;
    }
}

// ---------------------------------------------------------------------------
static inline float* sym(const void* s) {
    void* p = nullptr;
    cudaGetSymbolAddress(&p, s);
    return (float*)p;
}

extern "C" void kernel_launch(void* const* d_in, const int* in_sizes, int n_in,
                              void* d_out, int out_size)
{
    const float* x   = (const float*)d_in[0];
    const float* Wq  = (const float*)d_in[1];
    const float* bq  = (const float*)d_in[2];
    const float* Wk  = (const float*)d_in[3];
    const float* bk  = (const float*)d_in[4];
    const float* Wv  = (const float*)d_in[5];
    const float* bv  = (const float*)d_in[6];
    const float* Wo  = (const float*)d_in[7];
    const float* bo  = (const float*)d_in[8];
    const float* W1  = (const float*)d_in[9];
    const float* b1  = (const float*)d_in[10];
    const float* W2  = (const float*)d_in[11];
    const float* b2  = (const float*)d_in[12];
    const float* g1  = (const float*)d_in[13];
    const float* be1 = (const float*)d_in[14];
    const float* g3  = (const float*)d_in[15];
    const float* be3 = (const float*)d_in[16];
    float* out = (float*)d_out;

    float* attn = sym(g_attn);
    float* ffn  = sym(g_ffn);
    float* h1   = sym(g_h1);
    __nv_bfloat16* sah = (__nv_bfloat16*)sym(g_sa_h);
    __nv_bfloat16* sal = (__nv_bfloat16*)sym(g_sa_l);
    __nv_bfloat16* sbh = (__nv_bfloat16*)sym(g_sb_h);
    __nv_bfloat16* sbl = (__nv_bfloat16*)sym(g_sb_l);
    __nv_bfloat16* qh  = (__nv_bfloat16*)sym(g_qh);
    __nv_bfloat16* ql  = (__nv_bfloat16*)sym(g_ql);
    __nv_bfloat16* kh  = (__nv_bfloat16*)sym(g_kh);
    __nv_bfloat16* kl  = (__nv_bfloat16*)sym(g_kl);
    __nv_bfloat16* vh  = (__nv_bfloat16*)sym(g_vh);
    __nv_bfloat16* vl  = (__nv_bfloat16*)sym(g_vl);
    __nv_bfloat16* wqh = (__nv_bfloat16*)sym(g_wq_h);
    __nv_bfloat16* wql = (__nv_bfloat16*)sym(g_wq_l);
    __nv_bfloat16* wkh = (__nv_bfloat16*)sym(g_wk_h);
    __nv_bfloat16* wkl = (__nv_bfloat16*)sym(g_wk_l);
    __nv_bfloat16* wvh = (__nv_bfloat16*)sym(g_wv_h);
    __nv_bfloat16* wvl = (__nv_bfloat16*)sym(g_wv_l);
    __nv_bfloat16* woh = (__nv_bfloat16*)sym(g_wo_h);
    __nv_bfloat16* wol = (__nv_bfloat16*)sym(g_wo_l);
    __nv_bfloat16* w1h = (__nv_bfloat16*)sym(g_w1_h);
    __nv_bfloat16* w1l = (__nv_bfloat16*)sym(g_w1_l);
    __nv_bfloat16* w2h = (__nv_bfloat16*)sym(g_w2_h);
    __nv_bfloat16* w2l = (__nv_bfloat16*)sym(g_w2_l);

    cudaFuncSetAttribute(attention_mma, cudaFuncAttributeMaxDynamicSharedMemorySize, AT_SMEM);
    cudaFuncSetAttribute(gemm_mma<false, false>, cudaFuncAttributeMaxDynamicSharedMemorySize, GM_SMEM);
    cudaFuncSetAttribute(gemm_mma<false, true>,  cudaFuncAttributeMaxDynamicSharedMemorySize, GM_SMEM);
    cudaFuncSetAttribute(gemm_mma<true, true>,   cudaFuncAttributeMaxDynamicSharedMemorySize, GM_SMEM);

    dim3 tb(256);
    const int n4_x = (M_ROWS * D_MODEL) / 4;
    dim3 gProj(D_MODEL / 128, M_ROWS / 128);
    dim3 gFF1(D_FF / 128, M_ROWS / 128);
    dim3 gT(D_MODEL / 32, D_MODEL / 32);

    // launch 5 is a gemm -> ncu (-s 5 -c 1) profiles it
    transpose_split<<<gT, tb>>>(Wq, wqh, wql, D_MODEL, D_MODEL);                 // 0
    transpose_split<<<gT, tb>>>(Wk, wkh, wkl, D_MODEL, D_MODEL);                 // 1
    transpose_split<<<gT, tb>>>(Wv, wvh, wvl, D_MODEL, D_MODEL);                 // 2
    transpose_split<<<gT, tb>>>(Wo, woh, wol, D_MODEL, D_MODEL);                 // 3
    split_bf16<<<n4_x / 256, tb>>>((const float4*)x,
                                   (__nv_bfloat162*)sah, (__nv_bfloat162*)sal, n4_x); // 4
    gemm_mma<false, true><<<gProj, tb, GM_SMEM>>>(sah, sal, wqh, wql, bq,
                                                  nullptr, qh, ql, M_ROWS, D_MODEL, D_MODEL); // 5
    gemm_mma<false, true><<<gProj, tb, GM_SMEM>>>(sah, sal, wkh, wkl, bk,
                                                  nullptr, kh, kl, M_ROWS, D_MODEL, D_MODEL);
    gemm_mma<false, true><<<gProj, tb, GM_SMEM>>>(sah, sal, wvh, wvl, bv,
                                                  nullptr, vh, vl, M_ROWS, D_MODEL, D_MODEL);
    transpose_split<<<dim3(D_FF / 32, D_MODEL / 32), tb>>>(W1, w1h, w1l, D_MODEL, D_FF);
    transpose_split<<<dim3(D_MODEL / 32, D_FF / 32), tb>>>(W2, w2h, w2l, D_FF, D_MODEL);

    attention_mma<<<dim3(S_LEN / 128, B_SZ * N_HEADS), tb, AT_SMEM>>>(
        qh, ql, kh, kl, vh, vl, sbh, sbl);

    gemm_mma<false, false><<<gProj, tb, GM_SMEM>>>(sbh, sbl, woh, wol, bo,
                                                   attn, nullptr, nullptr, M_ROWS, D_MODEL, D_MODEL);
    add_ln_kernel<true><<<M_ROWS, tb>>>(x, attn, g1, be1, h1, sah, sal);
    gemm_mma<true, true><<<gFF1, tb, GM_SMEM>>>(sah, sal, w1h, w1l, b1,
                                                nullptr, sbh, sbl, M_ROWS, D_FF, D_MODEL);
    gemm_mma<false, false><<<gProj, tb, GM_SMEM>>>(sbh, sbl, w2h, w2l, b2,
                                                   ffn, nullptr, nullptr, M_ROWS, D_MODEL, D_FF);
    add_ln_kernel<false><<<M_ROWS, tb>>>(h1, ffn, g3, be3, out, nullptr, nullptr);
}

// round 13
// speedup vs baseline: 3.0584x; 1.3496x over previous
#include <cuda_runtime.h>
#include <cuda_fp16.h>
#include <math.h>
#include <stdint.h>

#define B_SZ 8
#define S_LEN 1024
#define D_MODEL 1024
#define N_HEADS 16
#define D_K 64
#define D_FF 4096
#define M_ROWS (B_SZ * S_LEN)

extern __shared__ char dyn_smem[];

// ---- scratch globals ----
__device__ float g_attn[(size_t)M_ROWS * D_MODEL];
__device__ float g_ffn[(size_t)M_ROWS * D_MODEL];
__device__ float g_h1[(size_t)M_ROWS * D_MODEL];
__device__ __half g_sa_h[(size_t)M_ROWS * D_MODEL];   // x / h1 split hi
__device__ __half g_sa_l[(size_t)M_ROWS * D_MODEL];
__device__ __half g_sb_h[(size_t)M_ROWS * D_FF];      // ctx / mid split hi
__device__ __half g_sb_l[(size_t)M_ROWS * D_FF];
__device__ __half g_qh[(size_t)M_ROWS * D_MODEL];
__device__ __half g_ql[(size_t)M_ROWS * D_MODEL];
__device__ __half g_kh[(size_t)M_ROWS * D_MODEL];     // K: hi only
__device__ __half g_vh[(size_t)M_ROWS * D_MODEL];     // V: hi only
__device__ __half g_wq[(size_t)D_MODEL * D_MODEL];    // weights: fp16 hi only, [N,K]
__device__ __half g_wk[(size_t)D_MODEL * D_MODEL];
__device__ __half g_wv[(size_t)D_MODEL * D_MODEL];
__device__ __half g_wo[(size_t)D_MODEL * D_MODEL];
__device__ __half g_w1[(size_t)D_FF * D_MODEL];
__device__ __half g_w2[(size_t)D_MODEL * D_FF];

// ---- PTX helpers ----
static __device__ __forceinline__ uint32_t smem_u32(const void* p) {
    uint32_t a;
    asm("{ .reg .u64 t; cvta.to.shared.u64 t, %1; cvt.u32.u64 %0, t; }" : "=r"(a) : "l"(p));
    return a;
}
#define CP_ASYNC16(dst, src) \
    asm volatile("cp.async.cg.shared.global [%0], [%1], 16;" :: "r"((uint32_t)(dst)), "l"(src))
#define CP_COMMIT() asm volatile("cp.async.commit_group;" ::: "memory")
#define LDSM_X4(R0, R1, R2, R3, ADDR) \
    asm volatile("ldmatrix.sync.aligned.m8n8.x4.shared.b16 {%0,%1,%2,%3}, [%4];" \
                 : "=r"(R0), "=r"(R1), "=r"(R2), "=r"(R3) : "r"(ADDR))
#define LDSM_X4_T(R0, R1, R2, R3, ADDR) \
    asm volatile("ldmatrix.sync.aligned.m8n8.x4.trans.shared.b16 {%0,%1,%2,%3}, [%4];" \
                 : "=r"(R0), "=r"(R1), "=r"(R2), "=r"(R3) : "r"(ADDR))

// D += A * B  (m16n8k16, fp16 in, fp32 accum)
static __device__ __forceinline__ void mma16816(float* d, const uint32_t* a, uint32_t b0, uint32_t b1)
{
    asm volatile(
        "mma.sync.aligned.m16n8k16.row.col.f32.f16.f16.f32 "
        "{%0,%1,%2,%3}, {%4,%5,%6,%7}, {%8,%9}, {%0,%1,%2,%3};"
        : "+f"(d[0]), "+f"(d[1]), "+f"(d[2]), "+f"(d[3])
        : "r"(a[0]), "r"(a[1]), "r"(a[2]), "r"(a[3]), "r"(b0), "r"(b1));
}

static __device__ __forceinline__ __half2 split_hi2(float a, float b, __half2& lo)
{
    __half h0 = __float2half_rn(a);
    __half h1 = __float2half_rn(b);
    lo = __half2(__float2half_rn(a - __half2float(h0)),
                 __float2half_rn(b - __half2float(h1)));
    return __half2(h0, h1);
}
static __device__ __forceinline__ uint32_t pack_split(float a, float b, uint32_t& lo_u)
{
    __half2 lo;
    __half2 hi = split_hi2(a, b, lo);
    lo_u = *reinterpret_cast<uint32_t*>(&lo);
    return *reinterpret_cast<uint32_t*>(&hi);
}

// ---------------------------------------------------------------------------
// GEMM: C[M,N] = (Ah+Al)[M,K] @ Bh^T + bias.  fp16 2-term.
// CTA 128x128, BK=32, 8 warps (2m x 4n, warp tile 64x32), 3-stage cp.async.
// smem rows: 32 fp16 = 64B + 16 pad = 80B stride; tiles Ah,Al,Bh = 3x10240.
// ---------------------------------------------------------------------------
#define GM_BUFSZ 30720
#define GM_SMEM  (3 * GM_BUFSZ)
// OUT modes
#define OUT_F32   0
#define OUT_SPLIT 1
#define OUT_HI    2

static __device__ __forceinline__ void load_chunk(
    uint32_t sdst, const __half* aH, const __half* aL, const __half* bH,
    int kb, int K, int tid)
{
#pragma unroll
    for (int j = 0; j < 2; j++) {
        int idx = tid + j * 256;
        int r = idx >> 2;
        int s = idx & 3;
        uint32_t doff = (uint32_t)(r * 80 + s * 16);
        size_t goff = (size_t)r * K + kb;
        CP_ASYNC16(sdst + doff,         (const char*)(aH + goff) + s * 16);
        CP_ASYNC16(sdst + 10240 + doff, (const char*)(aL + goff) + s * 16);
        CP_ASYNC16(sdst + 20480 + doff, (const char*)(bH + goff) + s * 16);
    }
}

template <bool RELU, int OUT>
__global__ __launch_bounds__(256, 1)
void gemm_mma(const __half* __restrict__ Ah, const __half* __restrict__ Al,
              const __half* __restrict__ Bh,
              const float* __restrict__ bias, float* __restrict__ C,
              __half* __restrict__ Ch, __half* __restrict__ Cl,
              int M, int N, int K)
{
    const uint32_t sbase = smem_u32(dyn_smem);
    const int tid = threadIdx.x;
    const int wid = tid >> 5;
    const int lane = tid & 31;
    const int gid = lane >> 2;
    const int tig = lane & 3;
    const int n0 = blockIdx.x * 128;
    const int m0 = blockIdx.y * 128;
    const int wm = (wid >> 2) * 64;
    const int wn = (wid & 3) * 32;
    const int nch = K >> 5;

    const __half* aH = Ah + (size_t)m0 * K;
    const __half* aL = Al + (size_t)m0 * K;
    const __half* bH = Bh + (size_t)n0 * K;

    const uint32_t offA = (uint32_t)((wm + ((lane >> 3) & 1) * 8 + (lane & 7)) * 80 + (lane >> 4) * 16);
    const uint32_t offB = (uint32_t)((wn + (lane >> 4) * 8 + (lane & 7)) * 80 + ((lane >> 3) & 1) * 16);

    float acc[4][4][4];
#pragma unroll
    for (int mt = 0; mt < 4; mt++)
#pragma unroll
        for (int nt = 0; nt < 4; nt++)
#pragma unroll
            for (int u = 0; u < 4; u++) acc[mt][nt][u] = 0.f;

    load_chunk(sbase,            aH, aL, bH, 0,  K, tid);
    CP_COMMIT();
    load_chunk(sbase + GM_BUFSZ, aH, aL, bH, 32, K, tid);
    CP_COMMIT();

    for (int ch = 0; ch < nch; ch++) {
        if (ch == nch - 1) asm volatile("cp.async.wait_group 0;" ::: "memory");
        else               asm volatile("cp.async.wait_group 1;" ::: "memory");
        __syncthreads();

        if (ch + 2 < nch) {
            load_chunk(sbase + ((ch + 2) % 3) * GM_BUFSZ, aH, aL, bH, (ch + 2) * 32, K, tid);
            CP_COMMIT();
        }

        const uint32_t buf = sbase + (ch % 3) * GM_BUFSZ;
        const uint32_t pAh = buf + offA;
        const uint32_t pAl = buf + 10240 + offA;
        const uint32_t pBh = buf + 20480 + offB;

#pragma unroll
        for (int kk = 0; kk < 2; kk++) {
            uint32_t ahf[4][4], alf[4][4], bhf[4][2];
#pragma unroll
            for (int mt = 0; mt < 4; mt++) {
                LDSM_X4(ahf[mt][0], ahf[mt][1], ahf[mt][2], ahf[mt][3], pAh + mt * 1280 + kk * 32);
                LDSM_X4(alf[mt][0], alf[mt][1], alf[mt][2], alf[mt][3], pAl + mt * 1280 + kk * 32);
            }
#pragma unroll
            for (int nt2 = 0; nt2 < 2; nt2++) {
                LDSM_X4(bhf[nt2 * 2][0], bhf[nt2 * 2][1], bhf[nt2 * 2 + 1][0], bhf[nt2 * 2 + 1][1],
                        pBh + nt2 * 1280 + kk * 32);
            }
#pragma unroll
            for (int nt = 0; nt < 4; nt++) {
#pragma unroll
                for (int mt = 0; mt < 4; mt++) {
                    mma16816(acc[mt][nt], ahf[mt], bhf[nt][0], bhf[nt][1]);
                    mma16816(acc[mt][nt], alf[mt], bhf[nt][0], bhf[nt][1]);
                }
            }
        }
    }

#pragma unroll
    for (int mt = 0; mt < 4; mt++) {
        int r0 = m0 + wm + mt * 16 + gid;
#pragma unroll
        for (int nt = 0; nt < 4; nt++) {
            int c0 = n0 + wn + nt * 8 + tig * 2;
            float bb0 = bias[c0], bb1 = bias[c0 + 1];
            float v0 = acc[mt][nt][0] + bb0;
            float v1 = acc[mt][nt][1] + bb1;
            float v2 = acc[mt][nt][2] + bb0;
            float v3 = acc[mt][nt][3] + bb1;
            if (RELU) {
                v0 = fmaxf(v0, 0.f); v1 = fmaxf(v1, 0.f);
                v2 = fmaxf(v2, 0.f); v3 = fmaxf(v3, 0.f);
            }
            if (OUT == OUT_SPLIT) {
                __half2 lo0, lo1;
                __half2 hi0 = split_hi2(v0, v1, lo0);
                __half2 hi1 = split_hi2(v2, v3, lo1);
                *(__half2*)(Ch + (size_t)r0 * N + c0)       = hi0;
                *(__half2*)(Cl + (size_t)r0 * N + c0)       = lo0;
                *(__half2*)(Ch + (size_t)(r0 + 8) * N + c0) = hi1;
                *(__half2*)(Cl + (size_t)(r0 + 8) * N + c0) = lo1;
            } else if (OUT == OUT_HI) {
                *(__half2*)(Ch + (size_t)r0 * N + c0) =
                    __half2(__float2half_rn(v0), __float2half_rn(v1));
                *(__half2*)(Ch + (size_t)(r0 + 8) * N + c0) =
                    __half2(__float2half_rn(v2), __float2half_rn(v3));
            } else {
                *(float2*)(C + (size_t)r0 * N + c0)       = make_float2(v0, v1);
                *(float2*)(C + (size_t)(r0 + 8) * N + c0) = make_float2(v2, v3);
            }
        }
    }
}

// ---------------------------------------------------------------------------
// prep kernels
// ---------------------------------------------------------------------------
__global__ __launch_bounds__(256)
void split_f16(const float4* __restrict__ in,
               __half2* __restrict__ h2, __half2* __restrict__ l2, int n4)
{
    int i = blockIdx.x * 256 + threadIdx.x;
    if (i >= n4) return;
    float4 v = in[i];
    __half2 lo0, lo1;
    __half2 hi0 = split_hi2(v.x, v.y, lo0);
    __half2 hi1 = split_hi2(v.z, v.w, lo1);
    h2[2 * i] = hi0; h2[2 * i + 1] = hi1;
    l2[2 * i] = lo0; l2[2 * i + 1] = lo1;
}

// W[K,N] fp32 -> transposed fp16 [N,K]
__global__ __launch_bounds__(256)
void transpose_f16(const float* __restrict__ W, __half* __restrict__ T, int K, int N)
{
    __shared__ float tile[32][33];
    const int tx = threadIdx.x & 31;
    const int ty = threadIdx.x >> 5;
    const int n0 = blockIdx.x * 32;
    const int k0 = blockIdx.y * 32;
#pragma unroll
    for (int j = 0; j < 4; j++)
        tile[ty + 8 * j][tx] = W[(size_t)(k0 + ty + 8 * j) * N + n0 + tx];
    __syncthreads();
#pragma unroll
    for (int j = 0; j < 4; j++)
        T[(size_t)(n0 + ty + 8 * j) * K + k0 + tx] = __float2half_rn(tile[tx][ty + 8 * j]);
}

// ---------------------------------------------------------------------------
// Tensor-core causal attention, fp16 2-term. CTA = 128 queries x one (b,h).
// Q split (hi/lo), K/V fp16 hi only. 8 warps x 16 query rows.
// smem: Q hi/lo (2x18432) + 3 KV bufs (Kh 9216 + Vh 9216 each).
// ---------------------------------------------------------------------------
#define AT_STR  144
#define AT_QSZ  36864
#define AT_BUF  18432
#define AT_SMEM (AT_QSZ + 3 * AT_BUF)

static __device__ __forceinline__ void load_kv(
    uint32_t dst, const __half* Kh, const __half* Vh, size_t rowbase, int kb, int tid)
{
#pragma unroll
    for (int j = 0; j < 2; j++) {
        int idx = tid + j * 256;
        int r = idx >> 3;
        int s = idx & 7;
        uint32_t doff = (uint32_t)(r * AT_STR + s * 16);
        size_t g = rowbase + (size_t)(kb * 64 + r) * D_MODEL + s * 8;
        CP_ASYNC16(dst + doff,        Kh + g);
        CP_ASYNC16(dst + 9216 + doff, Vh + g);
    }
}

__global__ __launch_bounds__(256, 1)
void attention_mma(const __half* __restrict__ Qh, const __half* __restrict__ Ql,
                   const __half* __restrict__ Kh, const __half* __restrict__ Vh,
                   __half* __restrict__ Oh, __half* __restrict__ Ol)
{
    const uint32_t sb = smem_u32(dyn_smem);
    const int tid = threadIdx.x;
    const int wid = tid >> 5;
    const int lane = tid & 31;
    const int gid = lane >> 2;
    const int tig = lane & 3;
    const int qblk = blockIdx.x;
    const int bh = blockIdx.y;
    const int b = bh >> 4;
    const int h = bh & 15;
    const int q0 = qblk * 128;
    const size_t rowbase = (size_t)b * S_LEN * D_MODEL + h * D_K;
    const int nkb = 2 * qblk + 2;

    // stage Q (hi @0, lo @18432)
#pragma unroll
    for (int j = 0; j < 4; j++) {
        int idx = tid + j * 256;
        int r = idx >> 3;
        int s = idx & 7;
        size_t g = rowbase + (size_t)(q0 + r) * D_MODEL + s * 8;
        uint32_t doff = (uint32_t)(r * AT_STR + s * 16);
        CP_ASYNC16(sb + doff,         Qh + g);
        CP_ASYNC16(sb + 18432 + doff, Ql + g);
    }
    CP_COMMIT();
    load_kv(sb + AT_QSZ,          Kh, Vh, rowbase, 0, tid); CP_COMMIT();
    load_kv(sb + AT_QSZ + AT_BUF, Kh, Vh, rowbase, 1, tid); CP_COMMIT();

    uint32_t qhf[4][4], qlf[4][4];
    float m0 = -INFINITY, m1 = -INFINITY, l0 = 0.f, l1 = 0.f;
    float o[8][4];
#pragma unroll
    for (int t = 0; t < 8; t++)
#pragma unroll
        for (int u = 0; u < 4; u++) o[t][u] = 0.f;

    const uint32_t offQ = sb + (uint32_t)((wid * 16 + ((lane >> 3) & 1) * 8 + (lane & 7)) * AT_STR +
                                          (lane >> 4) * 16);
    const uint32_t offBK = (uint32_t)(((lane >> 4) * 8 + (lane & 7)) * AT_STR + ((lane >> 3) & 1) * 16);
    const uint32_t offBV = (uint32_t)((lane & 15) * AT_STR + (lane >> 4) * 16);

    for (int kb = 0; kb < nkb; kb++) {
        if (kb + 1 < nkb) asm volatile("cp.async.wait_group 1;" ::: "memory");
        else              asm volatile("cp.async.wait_group 0;" ::: "memory");
        __syncthreads();

        if (kb == 0) {
#pragma unroll
            for (int kk = 0; kk < 4; kk++) {
                LDSM_X4(qhf[kk][0], qhf[kk][1], qhf[kk][2], qhf[kk][3], offQ + kk * 32);
                LDSM_X4(qlf[kk][0], qlf[kk][1], qlf[kk][2], qlf[kk][3], offQ + 18432 + kk * 32);
            }
        }
        if (kb + 2 < nkb) {
            load_kv(sb + AT_QSZ + ((kb + 2) % 3) * AT_BUF, Kh, Vh, rowbase, kb + 2, tid);
            CP_COMMIT();
        }

        const uint32_t kbuf = sb + AT_QSZ + (kb % 3) * AT_BUF;

        // S = (Qh+Ql) @ Kh^T
        float sc[8][4];
#pragma unroll
        for (int t = 0; t < 8; t++)
#pragma unroll
            for (int u = 0; u < 4; u++) sc[t][u] = 0.f;
#pragma unroll
        for (int kk = 0; kk < 4; kk++) {
#pragma unroll
            for (int p = 0; p < 4; p++) {
                uint32_t a = kbuf + p * (16 * AT_STR) + offBK + kk * 32;
                uint32_t h0, h1, h2, h3;
                LDSM_X4(h0, h1, h2, h3, a);
                mma16816(sc[2 * p],     qhf[kk], h0, h1);
                mma16816(sc[2 * p],     qlf[kk], h0, h1);
                mma16816(sc[2 * p + 1], qhf[kk], h2, h3);
                mma16816(sc[2 * p + 1], qlf[kk], h2, h3);
            }
        }
#pragma unroll
        for (int t = 0; t < 8; t++)
#pragma unroll
            for (int u = 0; u < 4; u++) sc[t][u] *= 0.125f;
        if (kb >= 2 * qblk) {
            int r0 = q0 + wid * 16 + gid;
            int cb = kb * 64 + tig * 2;
#pragma unroll
            for (int t = 0; t < 8; t++) {
                int col = cb + t * 8;
                if (col     >= r0)     sc[t][0] = -1e30f;
                if (col + 1 >= r0)     sc[t][1] = -1e30f;
                if (col     >= r0 + 8) sc[t][2] = -1e30f;
                if (col + 1 >= r0 + 8) sc[t][3] = -1e30f;
            }
        }

        // online softmax (register-resident)
        float mx0 = -INFINITY, mx1 = -INFINITY;
#pragma unroll
        for (int t = 0; t < 8; t++) {
            mx0 = fmaxf(mx0, fmaxf(sc[t][0], sc[t][1]));
            mx1 = fmaxf(mx1, fmaxf(sc[t][2], sc[t][3]));
        }
        mx0 = fmaxf(mx0, __shfl_xor_sync(0xffffffffu, mx0, 1));
        mx0 = fmaxf(mx0, __shfl_xor_sync(0xffffffffu, mx0, 2));
        mx1 = fmaxf(mx1, __shfl_xor_sync(0xffffffffu, mx1, 1));
        mx1 = fmaxf(mx1, __shfl_xor_sync(0xffffffffu, mx1, 2));
        float mn0 = fmaxf(m0, mx0);
        float mn1 = fmaxf(m1, mx1);
        float cr0 = __expf(m0 - mn0);
        float cr1 = __expf(m1 - mn1);
        float sum0 = 0.f, sum1 = 0.f;
#pragma unroll
        for (int t = 0; t < 8; t++) {
            sc[t][0] = __expf(sc[t][0] - mn0); sum0 += sc[t][0];
            sc[t][1] = __expf(sc[t][1] - mn0); sum0 += sc[t][1];
            sc[t][2] = __expf(sc[t][2] - mn1); sum1 += sc[t][2];
            sc[t][3] = __expf(sc[t][3] - mn1); sum1 += sc[t][3];
        }
        sum0 += __shfl_xor_sync(0xffffffffu, sum0, 1);
        sum0 += __shfl_xor_sync(0xffffffffu, sum0, 2);
        sum1 += __shfl_xor_sync(0xffffffffu, sum1, 1);
        sum1 += __shfl_xor_sync(0xffffffffu, sum1, 2);
        l0 = l0 * cr0 + sum0;
        l1 = l1 * cr1 + sum1;
        m0 = mn0; m1 = mn1;
#pragma unroll
        for (int t = 0; t < 8; t++) {
            o[t][0] *= cr0; o[t][1] *= cr0;
            o[t][2] *= cr1; o[t][3] *= cr1;
        }

        // O += (Ph+Pl) @ Vh
        const uint32_t vbuf = kbuf + 9216;
#pragma unroll
        for (int kk = 0; kk < 4; kk++) {
            uint32_t ph[4], pl[4];
            ph[0] = pack_split(sc[2 * kk][0],     sc[2 * kk][1],     pl[0]);
            ph[1] = pack_split(sc[2 * kk][2],     sc[2 * kk][3],     pl[1]);
            ph[2] = pack_split(sc[2 * kk + 1][0], sc[2 * kk + 1][1], pl[2]);
            ph[3] = pack_split(sc[2 * kk + 1][2], sc[2 * kk + 1][3], pl[3]);
#pragma unroll
            for (int dp = 0; dp < 4; dp++) {
                uint32_t a = vbuf + kk * (16 * AT_STR) + dp * 32 + offBV;
                uint32_t v0, v1, v2, v3;
                LDSM_X4_T(v0, v1, v2, v3, a);
                mma16816(o[2 * dp],     ph, v0, v1);
                mma16816(o[2 * dp],     pl, v0, v1);
                mma16816(o[2 * dp + 1], ph, v2, v3);
                mma16816(o[2 * dp + 1], pl, v2, v3);
            }
        }
    }

    // finalize: /l, zero global first query row (zero_pad), write hi/lo split
    const int srow0 = q0 + wid * 16 + gid;
    const int srow1 = srow0 + 8;
    const float inv0 = (srow0 == 0) ? 0.f : 1.f / l0;
    const float inv1 = 1.f / l1;
#pragma unroll
    for (int t = 0; t < 8; t++) {
        int d = t * 8 + tig * 2;
        float v0 = o[t][0] * inv0, v1 = o[t][1] * inv0;
        float v2 = o[t][2] * inv1, v3 = o[t][3] * inv1;
        __half2 lo0, lo1;
        __half2 hi0 = split_hi2(v0, v1, lo0);
        __half2 hi1 = split_hi2(v2, v3, lo1);
        size_t off0 = rowbase + (size_t)srow0 * D_MODEL + d;
        size_t off1 = rowbase + (size_t)srow1 * D_MODEL + d;
        *(__half2*)(Oh + off0) = hi0;
        *(__half2*)(Ol + off0) = lo0;
        *(__half2*)(Oh + off1) = hi1;
        *(__half2*)(Ol + off1) = lo1;
    }
}

// ---------------------------------------------------------------------------
// Fused residual add + LayerNorm (+ optional fp16 split output)
// ---------------------------------------------------------------------------
template <bool SPLIT>
__global__ __launch_bounds__(256)
void add_ln_kernel(const float* __restrict__ A, const float* __restrict__ Bm,
                   const float* __restrict__ g, const float* __restrict__ beta,
                   float* __restrict__ out,
                   __half* __restrict__ oh, __half* __restrict__ ol)
{
    __shared__ float red_s[8];
    __shared__ float red_q[8];
    __shared__ float stats[2];

    const int row = blockIdx.x;
    const int c = threadIdx.x * 4;
    float4 av = *(const float4*)(A + (size_t)row * D_MODEL + c);
    float4 bv = *(const float4*)(Bm + (size_t)row * D_MODEL + c);
    float v0 = av.x + bv.x, v1 = av.y + bv.y, v2 = av.z + bv.z, v3 = av.w + bv.w;

    float s = v0 + v1 + v2 + v3;
    float q = v0 * v0 + v1 * v1 + v2 * v2 + v3 * v3;
#pragma unroll
    for (int off = 16; off > 0; off >>= 1) {
        s += __shfl_xor_sync(0xffffffffu, s, off);
        q += __shfl_xor_sync(0xffffffffu, q, off);
    }
    if ((threadIdx.x & 31) == 0) {
        red_s[threadIdx.x >> 5] = s;
        red_q[threadIdx.x >> 5] = q;
    }
    __syncthreads();
    if (threadIdx.x < 32) {
        float ts = (threadIdx.x < 8) ? red_s[threadIdx.x] : 0.f;
        float tq = (threadIdx.x < 8) ? red_q[threadIdx.x] : 0.f;
#pragma unroll
        for (int off = 4; off > 0; off >>= 1) {
            ts += __shfl_xor_sync(0xffffffffu, ts, off);
            tq += __shfl_xor_sync(0xffffffffu, tq, off);
        }
        if (threadIdx.x == 0) {
            float mu = ts * (1.f / D_MODEL);
            float var = tq * (1.f / D_MODEL) - mu * mu;
            stats[0] = mu;
            stats[1] = rsqrtf(fmaxf(var, 0.f) + 1e-5f);
        }
    }
    __syncthreads();
    const float mu = stats[0];
    const float rstd = stats[1];

    float4 gv = *(const float4*)(g + c);
    float4 bev = *(const float4*)(beta + c);
    float4 ov;
    ov.x = (v0 - mu) * rstd * gv.x + bev.x;
    ov.y = (v1 - mu) * rstd * gv.y + bev.y;
    ov.z = (v2 - mu) * rstd * gv.z + bev.z;
    ov.w = (v3 - mu) * rstd * gv.w + bev.w;
    *(float4*)(out + (size_t)row * D_MODEL + c) = ov;
    if (SPLIT) {
        __half2 lo0, lo1;
        __half2 hi0 = split_hi2(ov.x, ov.y, lo0);
        __half2 hi1 = split_hi2(ov.z, ov.w, lo1);
        size_t off = (size_t)row * D_MODEL + c;
        *(__half2*)(oh + off)     = hi0;
        *(__half2*)(oh + off + 2) = hi1;
        *(__half2*)(ol + off)     = lo0;
        *(__half2*)(ol + off + 2) = lo1;
    }
}

// ---------------------------------------------------------------------------
static inline float* sym(const void* s) {
    void* p = nullptr;
    cudaGetSymbolAddress(&p, s);
    return (float*)p;
}

extern "C" void kernel_launch(void* const* d_in, const int* in_sizes, int n_in,
                              void* d_out, int out_size)
{
    const float* x   = (const float*)d_in[0];
    const float* Wq  = (const float*)d_in[1];
    const float* bq  = (const float*)d_in[2];
    const float* Wk  = (const float*)d_in[3];
    const float* bk  = (const float*)d_in[4];
    const float* Wv  = (const float*)d_in[5];
    const float* bv  = (const float*)d_in[6];
    const float* Wo  = (const float*)d_in[7];
    const float* bo  = (const float*)d_in[8];
    const float* W1  = (const float*)d_in[9];
    const float* b1  = (const float*)d_in[10];
    const float* W2  = (const float*)d_in[11];
    const float* b2  = (const float*)d_in[12];
    const float* g1  = (const float*)d_in[13];
    const float* be1 = (const float*)d_in[14];
    const float* g3  = (const float*)d_in[15];
    const float* be3 = (const float*)d_in[16];
    float* out = (float*)d_out;

    float* attn = sym(g_attn);
    float* ffn  = sym(g_ffn);
    float* h1   = sym(g_h1);
    __half* sah = (__half*)sym(g_sa_h);
    __half* sal = (__half*)sym(g_sa_l);
    __half* sbh = (__half*)sym(g_sb_h);
    __half* sbl = (__half*)sym(g_sb_l);
    __half* qh  = (__half*)sym(g_qh);
    __half* ql  = (__half*)sym(g_ql);
    __half* kh  = (__half*)sym(g_kh);
    __half* vh  = (__half*)sym(g_vh);
    __half* wq  = (__half*)sym(g_wq);
    __half* wk  = (__half*)sym(g_wk);
    __half* wv  = (__half*)sym(g_wv);
    __half* wo  = (__half*)sym(g_wo);
    __half* w1  = (__half*)sym(g_w1);
    __half* w2  = (__half*)sym(g_w2);

    cudaFuncSetAttribute(attention_mma, cudaFuncAttributeMaxDynamicSharedMemorySize, AT_SMEM);
    cudaFuncSetAttribute(gemm_mma<false, OUT_F32>,   cudaFuncAttributeMaxDynamicSharedMemorySize, GM_SMEM);
    cudaFuncSetAttribute(gemm_mma<false, OUT_SPLIT>, cudaFuncAttributeMaxDynamicSharedMemorySize, GM_SMEM);
    cudaFuncSetAttribute(gemm_mma<false, OUT_HI>,    cudaFuncAttributeMaxDynamicSharedMemorySize, GM_SMEM);
    cudaFuncSetAttribute(gemm_mma<true,  OUT_SPLIT>, cudaFuncAttributeMaxDynamicSharedMemorySize, GM_SMEM);

    dim3 tb(256);
    const int n4_x = (M_ROWS * D_MODEL) / 4;
    dim3 gProj(D_MODEL / 128, M_ROWS / 128);
    dim3 gFF1(D_FF / 128, M_ROWS / 128);
    dim3 gT(D_MODEL / 32, D_MODEL / 32);

    // launch 5 is the Q-projection gemm -> ncu (-s 5 -c 1) profiles it
    transpose_f16<<<gT, tb>>>(Wq, wq, D_MODEL, D_MODEL);                          // 0
    transpose_f16<<<gT, tb>>>(Wk, wk, D_MODEL, D_MODEL);                          // 1
    transpose_f16<<<gT, tb>>>(Wv, wv, D_MODEL, D_MODEL);                          // 2
    transpose_f16<<<gT, tb>>>(Wo, wo, D_MODEL, D_MODEL);                          // 3
    split_f16<<<n4_x / 256, tb>>>((const float4*)x, (__half2*)sah, (__half2*)sal, n4_x); // 4
    gemm_mma<false, OUT_SPLIT><<<gProj, tb, GM_SMEM>>>(sah, sal, wq, bq,
                                                       nullptr, qh, ql, M_ROWS, D_MODEL, D_MODEL); // 5
    gemm_mma<false, OUT_HI><<<gProj, tb, GM_SMEM>>>(sah, sal, wk, bk,
                                                    nullptr, kh, nullptr, M_ROWS, D_MODEL, D_MODEL);
    gemm_mma<false, OUT_HI><<<gProj, tb, GM_SMEM>>>(sah, sal, wv, bv,
                                                    nullptr, vh, nullptr, M_ROWS, D_MODEL, D_MODEL);
    transpose_f16<<<dim3(D_FF / 32, D_MODEL / 32), tb>>>(W1, w1, D_MODEL, D_FF);
    transpose_f16<<<dim3(D_MODEL / 32, D_FF / 32), tb>>>(W2, w2, D_FF, D_MODEL);

    attention_mma<<<dim3(S_LEN / 128, B_SZ * N_HEADS), tb, AT_SMEM>>>(
        qh, ql, kh, vh, sbh, sbl);

    gemm_mma<false, OUT_F32><<<gProj, tb, GM_SMEM>>>(sbh, sbl, wo, bo,
                                                     attn, nullptr, nullptr, M_ROWS, D_MODEL, D_MODEL);
    add_ln_kernel<true><<<M_ROWS, tb>>>(x, attn, g1, be1, h1, sah, sal);
    gemm_mma<true, OUT_SPLIT><<<gFF1, tb, GM_SMEM>>>(sah, sal, w1, b1,
                                                     nullptr, sbh, sbl, M_ROWS, D_FF, D_MODEL);
    gemm_mma<false, OUT_F32><<<gProj, tb, GM_SMEM>>>(sbh, sbl, w2, b2,
                                                     ffn, nullptr, nullptr, M_ROWS, D_MODEL, D_FF);
    add_ln_kernel<false><<<M_ROWS, tb>>>(h1, ffn, g3, be3, out, nullptr, nullptr);
}

// round 14
// speedup vs baseline: 4.8107x; 1.5729x over previous
#include <cuda_runtime.h>
#include <cuda_fp16.h>
#include <math.h>
#include <stdint.h>

#define B_SZ 8
#define S_LEN 1024
#define D_MODEL 1024
#define N_HEADS 16
#define D_K 64
#define D_FF 4096
#define M_ROWS (B_SZ * S_LEN)

extern __shared__ char dyn_smem[];

// ---- scratch globals ----
__device__ float g_attn[(size_t)M_ROWS * D_MODEL];
__device__ float g_ffn[(size_t)M_ROWS * D_MODEL];
__device__ float g_h1[(size_t)M_ROWS * D_MODEL];
__device__ __half g_sa[(size_t)M_ROWS * D_MODEL];    // x fp16, then h1 fp16
__device__ __half g_sb[(size_t)M_ROWS * D_FF];       // ctx fp16, then mid fp16
__device__ __half g_qh[(size_t)M_ROWS * D_MODEL];
__device__ __half g_kh[(size_t)M_ROWS * D_MODEL];
__device__ __half g_vh[(size_t)M_ROWS * D_MODEL];
__device__ __half g_wq[(size_t)D_MODEL * D_MODEL];   // weights fp16, [N,K]
__device__ __half g_wk[(size_t)D_MODEL * D_MODEL];
__device__ __half g_wv[(size_t)D_MODEL * D_MODEL];
__device__ __half g_wo[(size_t)D_MODEL * D_MODEL];
__device__ __half g_w1[(size_t)D_FF * D_MODEL];
__device__ __half g_w2[(size_t)D_MODEL * D_FF];

// ---- PTX helpers ----
static __device__ __forceinline__ uint32_t smem_u32(const void* p) {
    uint32_t a;
    asm("{ .reg .u64 t; cvta.to.shared.u64 t, %1; cvt.u32.u64 %0, t; }" : "=r"(a) : "l"(p));
    return a;
}
#define CP_ASYNC16(dst, src) \
    asm volatile("cp.async.cg.shared.global [%0], [%1], 16;" :: "r"((uint32_t)(dst)), "l"(src))
#define CP_COMMIT() asm volatile("cp.async.commit_group;" ::: "memory")
#define LDSM_X4(R0, R1, R2, R3, ADDR) \
    asm volatile("ldmatrix.sync.aligned.m8n8.x4.shared.b16 {%0,%1,%2,%3}, [%4];" \
                 : "=r"(R0), "=r"(R1), "=r"(R2), "=r"(R3) : "r"(ADDR))
#define LDSM_X4_T(R0, R1, R2, R3, ADDR) \
    asm volatile("ldmatrix.sync.aligned.m8n8.x4.trans.shared.b16 {%0,%1,%2,%3}, [%4];" \
                 : "=r"(R0), "=r"(R1), "=r"(R2), "=r"(R3) : "r"(ADDR))

// D += A * B  (m16n8k16, fp16 in, fp32 accum)
static __device__ __forceinline__ void mma16816(float* d, const uint32_t* a, uint32_t b0, uint32_t b1)
{
    asm volatile(
        "mma.sync.aligned.m16n8k16.row.col.f32.f16.f16.f32 "
        "{%0,%1,%2,%3}, {%4,%5,%6,%7}, {%8,%9}, {%0,%1,%2,%3};"
        : "+f"(d[0]), "+f"(d[1]), "+f"(d[2]), "+f"(d[3])
        : "r"(a[0]), "r"(a[1]), "r"(a[2]), "r"(a[3]), "r"(b0), "r"(b1));
}

static __device__ __forceinline__ uint32_t pack2(float a, float b)
{
    __half2 h = __floats2half2_rn(a, b);
    return *reinterpret_cast<uint32_t*>(&h);
}

// ---------------------------------------------------------------------------
// GEMM: C[M,N] = A[M,K] @ B^T (B stored [N,K]) + bias, pure fp16 inputs.
// CTA 128x128, BK=32, 8 warps (2m x 4n, warp tile 64x32), 3-stage cp.async.
// smem rows: 32 fp16 = 64B + 16 pad = 80B stride; tiles A,B = 2x10240.
// ---------------------------------------------------------------------------
#define GM_BUFSZ 20480
#define GM_SMEM  (3 * GM_BUFSZ)
#define OUT_F32 0
#define OUT_HI  1

static __device__ __forceinline__ void load_chunk(
    uint32_t sdst, const __half* aH, const __half* bH, int kb, int K, int tid)
{
#pragma unroll
    for (int j = 0; j < 2; j++) {
        int idx = tid + j * 256;
        int r = idx >> 2;
        int s = idx & 3;
        uint32_t doff = (uint32_t)(r * 80 + s * 16);
        size_t goff = (size_t)r * K + kb;
        CP_ASYNC16(sdst + doff,         (const char*)(aH + goff) + s * 16);
        CP_ASYNC16(sdst + 10240 + doff, (const char*)(bH + goff) + s * 16);
    }
}

template <bool RELU, int OUT>
__global__ __launch_bounds__(256, 1)
void gemm_mma(const __half* __restrict__ Ah, const __half* __restrict__ Bh,
              const float* __restrict__ bias, float* __restrict__ C,
              __half* __restrict__ Ch, int M, int N, int K)
{
    const uint32_t sbase = smem_u32(dyn_smem);
    const int tid = threadIdx.x;
    const int wid = tid >> 5;
    const int lane = tid & 31;
    const int gid = lane >> 2;
    const int tig = lane & 3;
    const int n0 = blockIdx.x * 128;
    const int m0 = blockIdx.y * 128;
    const int wm = (wid >> 2) * 64;
    const int wn = (wid & 3) * 32;
    const int nch = K >> 5;

    const __half* aH = Ah + (size_t)m0 * K;
    const __half* bH = Bh + (size_t)n0 * K;

    const uint32_t offA = (uint32_t)((wm + ((lane >> 3) & 1) * 8 + (lane & 7)) * 80 + (lane >> 4) * 16);
    const uint32_t offB = (uint32_t)((wn + (lane >> 4) * 8 + (lane & 7)) * 80 + ((lane >> 3) & 1) * 16);

    float acc[4][4][4];
#pragma unroll
    for (int mt = 0; mt < 4; mt++)
#pragma unroll
        for (int nt = 0; nt < 4; nt++)
#pragma unroll
            for (int u = 0; u < 4; u++) acc[mt][nt][u] = 0.f;

    load_chunk(sbase,            aH, bH, 0,  K, tid);
    CP_COMMIT();
    load_chunk(sbase + GM_BUFSZ, aH, bH, 32, K, tid);
    CP_COMMIT();

    for (int ch = 0; ch < nch; ch++) {
        if (ch == nch - 1) asm volatile("cp.async.wait_group 0;" ::: "memory");
        else               asm volatile("cp.async.wait_group 1;" ::: "memory");
        __syncthreads();

        if (ch + 2 < nch) {
            load_chunk(sbase + ((ch + 2) % 3) * GM_BUFSZ, aH, bH, (ch + 2) * 32, K, tid);
            CP_COMMIT();
        }

        const uint32_t buf = sbase + (ch % 3) * GM_BUFSZ;
        const uint32_t pA = buf + offA;
        const uint32_t pB = buf + 10240 + offB;

#pragma unroll
        for (int kk = 0; kk < 2; kk++) {
            uint32_t af[4][4], bf[4][2];
#pragma unroll
            for (int mt = 0; mt < 4; mt++)
                LDSM_X4(af[mt][0], af[mt][1], af[mt][2], af[mt][3], pA + mt * 1280 + kk * 32);
#pragma unroll
            for (int nt2 = 0; nt2 < 2; nt2++)
                LDSM_X4(bf[nt2 * 2][0], bf[nt2 * 2][1], bf[nt2 * 2 + 1][0], bf[nt2 * 2 + 1][1],
                        pB + nt2 * 1280 + kk * 32);
#pragma unroll
            for (int nt = 0; nt < 4; nt++)
#pragma unroll
                for (int mt = 0; mt < 4; mt++)
                    mma16816(acc[mt][nt], af[mt], bf[nt][0], bf[nt][1]);
        }
    }

#pragma unroll
    for (int mt = 0; mt < 4; mt++) {
        int r0 = m0 + wm + mt * 16 + gid;
#pragma unroll
        for (int nt = 0; nt < 4; nt++) {
            int c0 = n0 + wn + nt * 8 + tig * 2;
            float bb0 = bias[c0], bb1 = bias[c0 + 1];
            float v0 = acc[mt][nt][0] + bb0;
            float v1 = acc[mt][nt][1] + bb1;
            float v2 = acc[mt][nt][2] + bb0;
            float v3 = acc[mt][nt][3] + bb1;
            if (RELU) {
                v0 = fmaxf(v0, 0.f); v1 = fmaxf(v1, 0.f);
                v2 = fmaxf(v2, 0.f); v3 = fmaxf(v3, 0.f);
            }
            if (OUT == OUT_HI) {
                *(__half2*)(Ch + (size_t)r0 * N + c0)       = __floats2half2_rn(v0, v1);
                *(__half2*)(Ch + (size_t)(r0 + 8) * N + c0) = __floats2half2_rn(v2, v3);
            } else {
                *(float2*)(C + (size_t)r0 * N + c0)       = make_float2(v0, v1);
                *(float2*)(C + (size_t)(r0 + 8) * N + c0) = make_float2(v2, v3);
            }
        }
    }
}

// ---------------------------------------------------------------------------
// prep kernels
// ---------------------------------------------------------------------------
__global__ __launch_bounds__(256)
void conv_f16(const float4* __restrict__ in, __half2* __restrict__ h2, int n4)
{
    int i = blockIdx.x * 256 + threadIdx.x;
    if (i >= n4) return;
    float4 v = in[i];
    h2[2 * i]     = __floats2half2_rn(v.x, v.y);
    h2[2 * i + 1] = __floats2half2_rn(v.z, v.w);
}

// W[K,N] fp32 -> transposed fp16 [N,K]
__global__ __launch_bounds__(256)
void transpose_f16(const float* __restrict__ W, __half* __restrict__ T, int K, int N)
{
    __shared__ float tile[32][33];
    const int tx = threadIdx.x & 31;
    const int ty = threadIdx.x >> 5;
    const int n0 = blockIdx.x * 32;
    const int k0 = blockIdx.y * 32;
#pragma unroll
    for (int j = 0; j < 4; j++)
        tile[ty + 8 * j][tx] = W[(size_t)(k0 + ty + 8 * j) * N + n0 + tx];
    __syncthreads();
#pragma unroll
    for (int j = 0; j < 4; j++)
        T[(size_t)(n0 + ty + 8 * j) * K + k0 + tx] = __float2half_rn(tile[tx][ty + 8 * j]);
}

// ---------------------------------------------------------------------------
// Tensor-core causal attention, pure fp16. CTA = 128 queries x one (b,h).
// 8 warps x 16 query rows. smem: Q (18432) + 3 KV bufs (Kh 9216 + Vh 9216).
// ---------------------------------------------------------------------------
#define AT_STR  144
#define AT_QSZ  18432
#define AT_BUF  18432
#define AT_SMEM (AT_QSZ + 3 * AT_BUF)

static __device__ __forceinline__ void load_kv(
    uint32_t dst, const __half* Kh, const __half* Vh, size_t rowbase, int kb, int tid)
{
#pragma unroll
    for (int j = 0; j < 2; j++) {
        int idx = tid + j * 256;
        int r = idx >> 3;
        int s = idx & 7;
        uint32_t doff = (uint32_t)(r * AT_STR + s * 16);
        size_t g = rowbase + (size_t)(kb * 64 + r) * D_MODEL + s * 8;
        CP_ASYNC16(dst + doff,        Kh + g);
        CP_ASYNC16(dst + 9216 + doff, Vh + g);
    }
}

__global__ __launch_bounds__(256, 1)
void attention_mma(const __half* __restrict__ Qh, const __half* __restrict__ Kh,
                   const __half* __restrict__ Vh, __half* __restrict__ Oh)
{
    const uint32_t sb = smem_u32(dyn_smem);
    const int tid = threadIdx.x;
    const int wid = tid >> 5;
    const int lane = tid & 31;
    const int gid = lane >> 2;
    const int tig = lane & 3;
    const int qblk = blockIdx.x;
    const int bh = blockIdx.y;
    const int b = bh >> 4;
    const int h = bh & 15;
    const int q0 = qblk * 128;
    const size_t rowbase = (size_t)b * S_LEN * D_MODEL + h * D_K;
    const int nkb = 2 * qblk + 2;

    // stage Q
#pragma unroll
    for (int j = 0; j < 2; j++) {
        int idx = tid + j * 256;
        int r = idx >> 2;                  // 0..127
        int s2 = (idx & 3) * 2;            // two 16B segs per thread
#pragma unroll
        for (int u = 0; u < 2; u++) {
            int s = s2 + u;
            size_t g = rowbase + (size_t)(q0 + r) * D_MODEL + s * 8;
            CP_ASYNC16(sb + (uint32_t)(r * AT_STR + s * 16), Qh + g);
        }
    }
    CP_COMMIT();
    load_kv(sb + AT_QSZ,          Kh, Vh, rowbase, 0, tid); CP_COMMIT();
    load_kv(sb + AT_QSZ + AT_BUF, Kh, Vh, rowbase, 1, tid); CP_COMMIT();

    uint32_t qf[4][4];
    float m0 = -INFINITY, m1 = -INFINITY, l0 = 0.f, l1 = 0.f;
    float o[8][4];
#pragma unroll
    for (int t = 0; t < 8; t++)
#pragma unroll
        for (int u = 0; u < 4; u++) o[t][u] = 0.f;

    const uint32_t offQ = sb + (uint32_t)((wid * 16 + ((lane >> 3) & 1) * 8 + (lane & 7)) * AT_STR +
                                          (lane >> 4) * 16);
    const uint32_t offBK = (uint32_t)(((lane >> 4) * 8 + (lane & 7)) * AT_STR + ((lane >> 3) & 1) * 16);
    const uint32_t offBV = (uint32_t)((lane & 15) * AT_STR + (lane >> 4) * 16);

    for (int kb = 0; kb < nkb; kb++) {
        if (kb + 1 < nkb) asm volatile("cp.async.wait_group 1;" ::: "memory");
        else              asm volatile("cp.async.wait_group 0;" ::: "memory");
        __syncthreads();

        if (kb == 0) {
#pragma unroll
            for (int kk = 0; kk < 4; kk++)
                LDSM_X4(qf[kk][0], qf[kk][1], qf[kk][2], qf[kk][3], offQ + kk * 32);
        }
        if (kb + 2 < nkb) {
            load_kv(sb + AT_QSZ + ((kb + 2) % 3) * AT_BUF, Kh, Vh, rowbase, kb + 2, tid);
            CP_COMMIT();
        }

        const uint32_t kbuf = sb + AT_QSZ + (kb % 3) * AT_BUF;

        // S = Q @ K^T
        float sc[8][4];
#pragma unroll
        for (int t = 0; t < 8; t++)
#pragma unroll
            for (int u = 0; u < 4; u++) sc[t][u] = 0.f;
#pragma unroll
        for (int kk = 0; kk < 4; kk++) {
#pragma unroll
            for (int p = 0; p < 4; p++) {
                uint32_t a = kbuf + p * (16 * AT_STR) + offBK + kk * 32;
                uint32_t h0, h1, h2, h3;
                LDSM_X4(h0, h1, h2, h3, a);
                mma16816(sc[2 * p],     qf[kk], h0, h1);
                mma16816(sc[2 * p + 1], qf[kk], h2, h3);
            }
        }
#pragma unroll
        for (int t = 0; t < 8; t++)
#pragma unroll
            for (int u = 0; u < 4; u++) sc[t][u] *= 0.125f;
        if (kb >= 2 * qblk) {
            int r0 = q0 + wid * 16 + gid;
            int cb = kb * 64 + tig * 2;
#pragma unroll
            for (int t = 0; t < 8; t++) {
                int col = cb + t * 8;
                if (col     >= r0)     sc[t][0] = -1e30f;
                if (col + 1 >= r0)     sc[t][1] = -1e30f;
                if (col     >= r0 + 8) sc[t][2] = -1e30f;
                if (col + 1 >= r0 + 8) sc[t][3] = -1e30f;
            }
        }

        // online softmax (register-resident)
        float mx0 = -INFINITY, mx1 = -INFINITY;
#pragma unroll
        for (int t = 0; t < 8; t++) {
            mx0 = fmaxf(mx0, fmaxf(sc[t][0], sc[t][1]));
            mx1 = fmaxf(mx1, fmaxf(sc[t][2], sc[t][3]));
        }
        mx0 = fmaxf(mx0, __shfl_xor_sync(0xffffffffu, mx0, 1));
        mx0 = fmaxf(mx0, __shfl_xor_sync(0xffffffffu, mx0, 2));
        mx1 = fmaxf(mx1, __shfl_xor_sync(0xffffffffu, mx1, 1));
        mx1 = fmaxf(mx1, __shfl_xor_sync(0xffffffffu, mx1, 2));
        float mn0 = fmaxf(m0, mx0);
        float mn1 = fmaxf(m1, mx1);
        float cr0 = __expf(m0 - mn0);
        float cr1 = __expf(m1 - mn1);
        float sum0 = 0.f, sum1 = 0.f;
#pragma unroll
        for (int t = 0; t < 8; t++) {
            sc[t][0] = __expf(sc[t][0] - mn0); sum0 += sc[t][0];
            sc[t][1] = __expf(sc[t][1] - mn0); sum0 += sc[t][1];
            sc[t][2] = __expf(sc[t][2] - mn1); sum1 += sc[t][2];
            sc[t][3] = __expf(sc[t][3] - mn1); sum1 += sc[t][3];
        }
        sum0 += __shfl_xor_sync(0xffffffffu, sum0, 1);
        sum0 += __shfl_xor_sync(0xffffffffu, sum0, 2);
        sum1 += __shfl_xor_sync(0xffffffffu, sum1, 1);
        sum1 += __shfl_xor_sync(0xffffffffu, sum1, 2);
        l0 = l0 * cr0 + sum0;
        l1 = l1 * cr1 + sum1;
        m0 = mn0; m1 = mn1;
#pragma unroll
        for (int t = 0; t < 8; t++) {
            o[t][0] *= cr0; o[t][1] *= cr0;
            o[t][2] *= cr1; o[t][3] *= cr1;
        }

        // O += P @ V  (P packed to fp16 in registers)
        const uint32_t vbuf = kbuf + 9216;
#pragma unroll
        for (int kk = 0; kk < 4; kk++) {
            uint32_t pf[4];
            pf[0] = pack2(sc[2 * kk][0],     sc[2 * kk][1]);
            pf[1] = pack2(sc[2 * kk][2],     sc[2 * kk][3]);
            pf[2] = pack2(sc[2 * kk + 1][0], sc[2 * kk + 1][1]);
            pf[3] = pack2(sc[2 * kk + 1][2], sc[2 * kk + 1][3]);
#pragma unroll
            for (int dp = 0; dp < 4; dp++) {
                uint32_t a = vbuf + kk * (16 * AT_STR) + dp * 32 + offBV;
                uint32_t v0, v1, v2, v3;
                LDSM_X4_T(v0, v1, v2, v3, a);
                mma16816(o[2 * dp],     pf, v0, v1);
                mma16816(o[2 * dp + 1], pf, v2, v3);
            }
        }
    }

    // finalize: /l, zero global first query row (zero_pad), write fp16
    const int srow0 = q0 + wid * 16 + gid;
    const int srow1 = srow0 + 8;
    const float inv0 = (srow0 == 0) ? 0.f : 1.f / l0;
    const float inv1 = 1.f / l1;
#pragma unroll
    for (int t = 0; t < 8; t++) {
        int d = t * 8 + tig * 2;
        size_t off0 = rowbase + (size_t)srow0 * D_MODEL + d;
        size_t off1 = rowbase + (size_t)srow1 * D_MODEL + d;
        *(__half2*)(Oh + off0) = __floats2half2_rn(o[t][0] * inv0, o[t][1] * inv0);
        *(__half2*)(Oh + off1) = __floats2half2_rn(o[t][2] * inv1, o[t][3] * inv1);
    }
}

// ---------------------------------------------------------------------------
// Fused residual add + LayerNorm (+ optional fp16 output)
// ---------------------------------------------------------------------------
template <bool HOUT>
__global__ __launch_bounds__(256)
void add_ln_kernel(const float* __restrict__ A, const float* __restrict__ Bm,
                   const float* __restrict__ g, const float* __restrict__ beta,
                   float* __restrict__ out, __half* __restrict__ oh)
{
    __shared__ float red_s[8];
    __shared__ float red_q[8];
    __shared__ float stats[2];

    const int row = blockIdx.x;
    const int c = threadIdx.x * 4;
    float4 av = *(const float4*)(A + (size_t)row * D_MODEL + c);
    float4 bv = *(const float4*)(Bm + (size_t)row * D_MODEL + c);
    float v0 = av.x + bv.x, v1 = av.y + bv.y, v2 = av.z + bv.z, v3 = av.w + bv.w;

    float s = v0 + v1 + v2 + v3;
    float q = v0 * v0 + v1 * v1 + v2 * v2 + v3 * v3;
#pragma unroll
    for (int off = 16; off > 0; off >>= 1) {
        s += __shfl_xor_sync(0xffffffffu, s, off);
        q += __shfl_xor_sync(0xffffffffu, q, off);
    }
    if ((threadIdx.x & 31) == 0) {
        red_s[threadIdx.x >> 5] = s;
        red_q[threadIdx.x >> 5] = q;
    }
    __syncthreads();
    if (threadIdx.x < 32) {
        float ts = (threadIdx.x < 8) ? red_s[threadIdx.x] : 0.f;
        float tq = (threadIdx.x < 8) ? red_q[threadIdx.x] : 0.f;
#pragma unroll
        for (int off = 4; off > 0; off >>= 1) {
            ts += __shfl_xor_sync(0xffffffffu, ts, off);
            tq += __shfl_xor_sync(0xffffffffu, tq, off);
        }
        if (threadIdx.x == 0) {
            float mu = ts * (1.f / D_MODEL);
            float var = tq * (1.f / D_MODEL) - mu * mu;
            stats[0] = mu;
            stats[1] = rsqrtf(fmaxf(var, 0.f) + 1e-5f);
        }
    }
    __syncthreads();
    const float mu = stats[0];
    const float rstd = stats[1];

    float4 gv = *(const float4*)(g + c);
    float4 bev = *(const float4*)(beta + c);
    float4 ov;
    ov.x = (v0 - mu) * rstd * gv.x + bev.x;
    ov.y = (v1 - mu) * rstd * gv.y + bev.y;
    ov.z = (v2 - mu) * rstd * gv.z + bev.z;
    ov.w = (v3 - mu) * rstd * gv.w + bev.w;
    *(float4*)(out + (size_t)row * D_MODEL + c) = ov;
    if (HOUT) {
        size_t off = (size_t)row * D_MODEL + c;
        *(__half2*)(oh + off)     = __floats2half2_rn(ov.x, ov.y);
        *(__half2*)(oh + off + 2) = __floats2half2_rn(ov.z, ov.w);
    }
}

// ---------------------------------------------------------------------------
static inline float* sym(const void* s) {
    void* p = nullptr;
    cudaGetSymbolAddress(&p, s);
    return (float*)p;
}

extern "C" void kernel_launch(void* const* d_in, const int* in_sizes, int n_in,
                              void* d_out, int out_size)
{
    const float* x   = (const float*)d_in[0];
    const float* Wq  = (const float*)d_in[1];
    const float* bq  = (const float*)d_in[2];
    const float* Wk  = (const float*)d_in[3];
    const float* bk  = (const float*)d_in[4];
    const float* Wv  = (const float*)d_in[5];
    const float* bv  = (const float*)d_in[6];
    const float* Wo  = (const float*)d_in[7];
    const float* bo  = (const float*)d_in[8];
    const float* W1  = (const float*)d_in[9];
    const float* b1  = (const float*)d_in[10];
    const float* W2  = (const float*)d_in[11];
    const float* b2  = (const float*)d_in[12];
    const float* g1  = (const float*)d_in[13];
    const float* be1 = (const float*)d_in[14];
    const float* g3  = (const float*)d_in[15];
    const float* be3 = (const float*)d_in[16];
    float* out = (float*)d_out;

    float* attn = sym(g_attn);
    float* ffn  = sym(g_ffn);
    float* h1   = sym(g_h1);
    __half* sa = (__half*)sym(g_sa);
    __half* sb = (__half*)sym(g_sb);
    __half* qh = (__half*)sym(g_qh);
    __half* kh = (__half*)sym(g_kh);
    __half* vh = (__half*)sym(g_vh);
    __half* wq = (__half*)sym(g_wq);
    __half* wk = (__half*)sym(g_wk);
    __half* wv = (__half*)sym(g_wv);
    __half* wo = (__half*)sym(g_wo);
    __half* w1 = (__half*)sym(g_w1);
    __half* w2 = (__half*)sym(g_w2);

    cudaFuncSetAttribute(attention_mma, cudaFuncAttributeMaxDynamicSharedMemorySize, AT_SMEM);
    cudaFuncSetAttribute(gemm_mma<false, OUT_F32>, cudaFuncAttributeMaxDynamicSharedMemorySize, GM_SMEM);
    cudaFuncSetAttribute(gemm_mma<false, OUT_HI>,  cudaFuncAttributeMaxDynamicSharedMemorySize, GM_SMEM);
    cudaFuncSetAttribute(gemm_mma<true,  OUT_HI>,  cudaFuncAttributeMaxDynamicSharedMemorySize, GM_SMEM);

    dim3 tb(256);
    const int n4_x = (M_ROWS * D_MODEL) / 4;
    dim3 gProj(D_MODEL / 128, M_ROWS / 128);
    dim3 gFF1(D_FF / 128, M_ROWS / 128);
    dim3 gT(D_MODEL / 32, D_MODEL / 32);

    // launch 5 is the Q-projection gemm -> ncu (-s 5 -c 1) profiles it
    transpose_f16<<<gT, tb>>>(Wq, wq, D_MODEL, D_MODEL);                          // 0
    transpose_f16<<<gT, tb>>>(Wk, wk, D_MODEL, D_MODEL);                          // 1
    transpose_f16<<<gT, tb>>>(Wv, wv, D_MODEL, D_MODEL);                          // 2
    transpose_f16<<<gT, tb>>>(Wo, wo, D_MODEL, D_MODEL);                          // 3
    conv_f16<<<n4_x / 256, tb>>>((const float4*)x, (__half2*)sa, n4_x);           // 4
    gemm_mma<false, OUT_HI><<<gProj, tb, GM_SMEM>>>(sa, wq, bq, nullptr, qh,
                                                    M_ROWS, D_MODEL, D_MODEL);    // 5
    gemm_mma<false, OUT_HI><<<gProj, tb, GM_SMEM>>>(sa, wk, bk, nullptr, kh,
                                                    M_ROWS, D_MODEL, D_MODEL);
    gemm_mma<false, OUT_HI><<<gProj, tb, GM_SMEM>>>(sa, wv, bv, nullptr, vh,
                                                    M_ROWS, D_MODEL, D_MODEL);
    transpose_f16<<<dim3(D_FF / 32, D_MODEL / 32), tb>>>(W1, w1, D_MODEL, D_FF);
    transpose_f16<<<dim3(D_MODEL / 32, D_FF / 32), tb>>>(W2, w2, D_FF, D_MODEL);

    attention_mma<<<dim3(S_LEN / 128, B_SZ * N_HEADS), tb, AT_SMEM>>>(qh, kh, vh, sb);

    gemm_mma<false, OUT_F32><<<gProj, tb, GM_SMEM>>>(sb, wo, bo, attn, nullptr,
                                                     M_ROWS, D_MODEL, D_MODEL);
    add_ln_kernel<true><<<M_ROWS, tb>>>(x, attn, g1, be1, h1, sa);
    gemm_mma<true, OUT_HI><<<gFF1, tb, GM_SMEM>>>(sa, w1, b1, nullptr, sb,
                                                  M_ROWS, D_FF, D_MODEL);
    gemm_mma<false, OUT_F32><<<gProj, tb, GM_SMEM>>>(sb, w2, b2, ffn, nullptr,
                                                     M_ROWS, D_MODEL, D_FF);
    add_ln_kernel<false><<<M_ROWS, tb>>>(h1, ffn, g3, be3, out, nullptr);
}

// round 15
// speedup vs baseline: 5.8243x; 1.2107x over previous
#include <cuda_runtime.h>
#include <cuda_fp16.h>
#include <math.h>
#include <stdint.h>

#define B_SZ 8
#define S_LEN 1024
#define D_MODEL 1024
#define N_HEADS 16
#define D_K 64
#define D_FF 4096
#define M_ROWS (B_SZ * S_LEN)
#define D_QKV (3 * D_MODEL)

extern __shared__ char dyn_smem[];

// ---- scratch globals ----
__device__ float g_attn[(size_t)M_ROWS * D_MODEL];
__device__ float g_ffn[(size_t)M_ROWS * D_MODEL];
__device__ float g_h1[(size_t)M_ROWS * D_MODEL];
__device__ __half g_sa[(size_t)M_ROWS * D_MODEL];    // x fp16, then h1 fp16
__device__ __half g_sb[(size_t)M_ROWS * D_FF];       // ctx fp16, then mid fp16
__device__ __half g_qkv[(size_t)M_ROWS * D_QKV];     // fused q|k|v fp16
__device__ __half g_wqkv[(size_t)D_QKV * D_MODEL];   // fused weights [3072,1024] fp16
__device__ float  g_bqkv[D_QKV];                     // fused bias
__device__ __half g_wo[(size_t)D_MODEL * D_MODEL];
__device__ __half g_w1[(size_t)D_FF * D_MODEL];
__device__ __half g_w2[(size_t)D_MODEL * D_FF];

// ---- PTX helpers ----
static __device__ __forceinline__ uint32_t smem_u32(const void* p) {
    uint32_t a;
    asm("{ .reg .u64 t; cvta.to.shared.u64 t, %1; cvt.u32.u64 %0, t; }" : "=r"(a) : "l"(p));
    return a;
}
#define CP_ASYNC16(dst, src) \
    asm volatile("cp.async.cg.shared.global [%0], [%1], 16;" :: "r"((uint32_t)(dst)), "l"(src))
#define CP_COMMIT() asm volatile("cp.async.commit_group;" ::: "memory")
#define LDSM_X4(R0, R1, R2, R3, ADDR) \
    asm volatile("ldmatrix.sync.aligned.m8n8.x4.shared.b16 {%0,%1,%2,%3}, [%4];" \
                 : "=r"(R0), "=r"(R1), "=r"(R2), "=r"(R3) : "r"(ADDR))
#define LDSM_X4_T(R0, R1, R2, R3, ADDR) \
    asm volatile("ldmatrix.sync.aligned.m8n8.x4.trans.shared.b16 {%0,%1,%2,%3}, [%4];" \
                 : "=r"(R0), "=r"(R1), "=r"(R2), "=r"(R3) : "r"(ADDR))

static __device__ __forceinline__ void mma16816(float* d, const uint32_t* a, uint32_t b0, uint32_t b1)
{
    asm volatile(
        "mma.sync.aligned.m16n8k16.row.col.f32.f16.f16.f32 "
        "{%0,%1,%2,%3}, {%4,%5,%6,%7}, {%8,%9}, {%0,%1,%2,%3};"
        : "+f"(d[0]), "+f"(d[1]), "+f"(d[2]), "+f"(d[3])
        : "r"(a[0]), "r"(a[1]), "r"(a[2]), "r"(a[3]), "r"(b0), "r"(b1));
}

static __device__ __forceinline__ uint32_t pack2(float a, float b)
{
    __half2 h = __floats2half2_rn(a, b);
    return *reinterpret_cast<uint32_t*>(&h);
}

// ---------------------------------------------------------------------------
// GEMM: C[M,N] = A[M,K] @ B^T (B stored [N,K]) + bias, pure fp16 inputs.
// CTA 128x128, BK=32, 8 warps (2m x 4n), 3-stage cp.async, 2 CTAs/SM.
// ---------------------------------------------------------------------------
#define GM_BUFSZ 20480
#define GM_SMEM  (3 * GM_BUFSZ)
#define OUT_F32 0
#define OUT_HI  1

static __device__ __forceinline__ void load_chunk(
    uint32_t sdst, const __half* aH, const __half* bH, int kb, int K, int tid)
{
#pragma unroll
    for (int j = 0; j < 2; j++) {
        int idx = tid + j * 256;
        int r = idx >> 2;
        int s = idx & 3;
        uint32_t doff = (uint32_t)(r * 80 + s * 16);
        size_t goff = (size_t)r * K + kb;
        CP_ASYNC16(sdst + doff,         (const char*)(aH + goff) + s * 16);
        CP_ASYNC16(sdst + 10240 + doff, (const char*)(bH + goff) + s * 16);
    }
}

template <bool RELU, int OUT>
__global__ __launch_bounds__(256, 2)
void gemm_mma(const __half* __restrict__ Ah, const __half* __restrict__ Bh,
              const float* __restrict__ bias, float* __restrict__ C,
              __half* __restrict__ Ch, int M, int N, int K)
{
    const uint32_t sbase = smem_u32(dyn_smem);
    const int tid = threadIdx.x;
    const int wid = tid >> 5;
    const int lane = tid & 31;
    const int gid = lane >> 2;
    const int tig = lane & 3;
    const int n0 = blockIdx.x * 128;
    const int m0 = blockIdx.y * 128;
    const int wm = (wid >> 2) * 64;
    const int wn = (wid & 3) * 32;
    const int nch = K >> 5;

    const __half* aH = Ah + (size_t)m0 * K;
    const __half* bH = Bh + (size_t)n0 * K;

    const uint32_t offA = (uint32_t)((wm + ((lane >> 3) & 1) * 8 + (lane & 7)) * 80 + (lane >> 4) * 16);
    const uint32_t offB = (uint32_t)((wn + (lane >> 4) * 8 + (lane & 7)) * 80 + ((lane >> 3) & 1) * 16);

    float acc[4][4][4];
#pragma unroll
    for (int mt = 0; mt < 4; mt++)
#pragma unroll
        for (int nt = 0; nt < 4; nt++)
#pragma unroll
            for (int u = 0; u < 4; u++) acc[mt][nt][u] = 0.f;

    load_chunk(sbase,            aH, bH, 0,  K, tid);
    CP_COMMIT();
    load_chunk(sbase + GM_BUFSZ, aH, bH, 32, K, tid);
    CP_COMMIT();

    for (int ch = 0; ch < nch; ch++) {
        if (ch == nch - 1) asm volatile("cp.async.wait_group 0;" ::: "memory");
        else               asm volatile("cp.async.wait_group 1;" ::: "memory");
        __syncthreads();

        if (ch + 2 < nch) {
            load_chunk(sbase + ((ch + 2) % 3) * GM_BUFSZ, aH, bH, (ch + 2) * 32, K, tid);
            CP_COMMIT();
        }

        const uint32_t buf = sbase + (ch % 3) * GM_BUFSZ;
        const uint32_t pA = buf + offA;
        const uint32_t pB = buf + 10240 + offB;

#pragma unroll
        for (int kk = 0; kk < 2; kk++) {
            uint32_t af[4][4], bf[4][2];
#pragma unroll
            for (int mt = 0; mt < 4; mt++)
                LDSM_X4(af[mt][0], af[mt][1], af[mt][2], af[mt][3], pA + mt * 1280 + kk * 32);
#pragma unroll
            for (int nt2 = 0; nt2 < 2; nt2++)
                LDSM_X4(bf[nt2 * 2][0], bf[nt2 * 2][1], bf[nt2 * 2 + 1][0], bf[nt2 * 2 + 1][1],
                        pB + nt2 * 1280 + kk * 32);
#pragma unroll
            for (int nt = 0; nt < 4; nt++)
#pragma unroll
                for (int mt = 0; mt < 4; mt++)
                    mma16816(acc[mt][nt], af[mt], bf[nt][0], bf[nt][1]);
        }
    }

#pragma unroll
    for (int mt = 0; mt < 4; mt++) {
        int r0 = m0 + wm + mt * 16 + gid;
#pragma unroll
        for (int nt = 0; nt < 4; nt++) {
            int c0 = n0 + wn + nt * 8 + tig * 2;
            float bb0 = bias[c0], bb1 = bias[c0 + 1];
            float v0 = acc[mt][nt][0] + bb0;
            float v1 = acc[mt][nt][1] + bb1;
            float v2 = acc[mt][nt][2] + bb0;
            float v3 = acc[mt][nt][3] + bb1;
            if (RELU) {
                v0 = fmaxf(v0, 0.f); v1 = fmaxf(v1, 0.f);
                v2 = fmaxf(v2, 0.f); v3 = fmaxf(v3, 0.f);
            }
            if (OUT == OUT_HI) {
                *(__half2*)(Ch + (size_t)r0 * N + c0)       = __floats2half2_rn(v0, v1);
                *(__half2*)(Ch + (size_t)(r0 + 8) * N + c0) = __floats2half2_rn(v2, v3);
            } else {
                *(float2*)(C + (size_t)r0 * N + c0)       = make_float2(v0, v1);
                *(float2*)(C + (size_t)(r0 + 8) * N + c0) = make_float2(v2, v3);
            }
        }
    }
}

// ---------------------------------------------------------------------------
// prep kernels
// ---------------------------------------------------------------------------
__global__ __launch_bounds__(256)
void concat_bias(const float* __restrict__ bq, const float* __restrict__ bk,
                 const float* __restrict__ bv, float* __restrict__ o)
{
    int i = blockIdx.x * 256 + threadIdx.x;       // 0..3071
    const float* src = (i < 1024) ? bq : (i < 2048) ? bk : bv;
    o[i] = src[i & 1023];
}

__global__ __launch_bounds__(256)
void conv_f16(const float4* __restrict__ in, __half2* __restrict__ h2, int n4)
{
    int i = blockIdx.x * 256 + threadIdx.x;
    if (i >= n4) return;
    float4 v = in[i];
    h2[2 * i]     = __floats2half2_rn(v.x, v.y);
    h2[2 * i + 1] = __floats2half2_rn(v.z, v.w);
}

// W[K,N] fp32 -> transposed fp16 [N,K]
__global__ __launch_bounds__(256)
void transpose_f16(const float* __restrict__ W, __half* __restrict__ T, int K, int N)
{
    __shared__ float tile[32][33];
    const int tx = threadIdx.x & 31;
    const int ty = threadIdx.x >> 5;
    const int n0 = blockIdx.x * 32;
    const int k0 = blockIdx.y * 32;
#pragma unroll
    for (int j = 0; j < 4; j++)
        tile[ty + 8 * j][tx] = W[(size_t)(k0 + ty + 8 * j) * N + n0 + tx];
    __syncthreads();
#pragma unroll
    for (int j = 0; j < 4; j++)
        T[(size_t)(n0 + ty + 8 * j) * K + k0 + tx] = __float2half_rn(tile[tx][ty + 8 * j]);
}

// ---------------------------------------------------------------------------
// Tensor-core causal attention, pure fp16. CTA = 128 queries x one (b,h).
// Q/K/V read from fused qkv buffer (row stride D_QKV); output stride D_MODEL.
// ---------------------------------------------------------------------------
#define AT_STR  144
#define AT_QSZ  18432
#define AT_BUF  18432
#define AT_SMEM (AT_QSZ + 3 * AT_BUF)

static __device__ __forceinline__ void load_kv(
    uint32_t dst, const __half* Kh, const __half* Vh, int kb, int tid)
{
#pragma unroll
    for (int j = 0; j < 2; j++) {
        int idx = tid + j * 256;
        int r = idx >> 3;
        int s = idx & 7;
        uint32_t doff = (uint32_t)(r * AT_STR + s * 16);
        size_t g = (size_t)(kb * 64 + r) * D_QKV + s * 8;
        CP_ASYNC16(dst + doff,        Kh + g);
        CP_ASYNC16(dst + 9216 + doff, Vh + g);
    }
}

__global__ __launch_bounds__(256, 1)
void attention_mma(const __half* __restrict__ QKV, __half* __restrict__ Oh)
{
    const uint32_t sb = smem_u32(dyn_smem);
    const int tid = threadIdx.x;
    const int wid = tid >> 5;
    const int lane = tid & 31;
    const int gid = lane >> 2;
    const int tig = lane & 3;
    const int qblk = blockIdx.x;
    const int bh = blockIdx.y;
    const int b = bh >> 4;
    const int h = bh & 15;
    const int q0 = qblk * 128;
    const __half* Qb = QKV + (size_t)(b * S_LEN) * D_QKV + h * D_K;
    const __half* Kb = Qb + D_MODEL;
    const __half* Vb = Qb + 2 * D_MODEL;
    const size_t obase = (size_t)(b * S_LEN) * D_MODEL + h * D_K;
    const int nkb = 2 * qblk + 2;

    // stage Q
#pragma unroll
    for (int j = 0; j < 2; j++) {
        int idx = tid + j * 256;
        int r = idx >> 2;
        int s2 = (idx & 3) * 2;
#pragma unroll
        for (int u = 0; u < 2; u++) {
            int s = s2 + u;
            size_t g = (size_t)(q0 + r) * D_QKV + s * 8;
            CP_ASYNC16(sb + (uint32_t)(r * AT_STR + s * 16), Qb + g);
        }
    }
    CP_COMMIT();
    load_kv(sb + AT_QSZ,          Kb, Vb, 0, tid); CP_COMMIT();
    load_kv(sb + AT_QSZ + AT_BUF, Kb, Vb, 1, tid); CP_COMMIT();

    uint32_t qf[4][4];
    float m0 = -INFINITY, m1 = -INFINITY, l0 = 0.f, l1 = 0.f;
    float o[8][4];
#pragma unroll
    for (int t = 0; t < 8; t++)
#pragma unroll
        for (int u = 0; u < 4; u++) o[t][u] = 0.f;

    const uint32_t offQ = sb + (uint32_t)((wid * 16 + ((lane >> 3) & 1) * 8 + (lane & 7)) * AT_STR +
                                          (lane >> 4) * 16);
    const uint32_t offBK = (uint32_t)(((lane >> 4) * 8 + (lane & 7)) * AT_STR + ((lane >> 3) & 1) * 16);
    const uint32_t offBV = (uint32_t)((lane & 15) * AT_STR + (lane >> 4) * 16);

    for (int kb = 0; kb < nkb; kb++) {
        if (kb + 1 < nkb) asm volatile("cp.async.wait_group 1;" ::: "memory");
        else              asm volatile("cp.async.wait_group 0;" ::: "memory");
        __syncthreads();

        if (kb == 0) {
#pragma unroll
            for (int kk = 0; kk < 4; kk++)
                LDSM_X4(qf[kk][0], qf[kk][1], qf[kk][2], qf[kk][3], offQ + kk * 32);
        }
        if (kb + 2 < nkb) {
            load_kv(sb + AT_QSZ + ((kb + 2) % 3) * AT_BUF, Kb, Vb, kb + 2, tid);
            CP_COMMIT();
        }

        const uint32_t kbuf = sb + AT_QSZ + (kb % 3) * AT_BUF;

        float sc[8][4];
#pragma unroll
        for (int t = 0; t < 8; t++)
#pragma unroll
            for (int u = 0; u < 4; u++) sc[t][u] = 0.f;
#pragma unroll
        for (int kk = 0; kk < 4; kk++) {
#pragma unroll
            for (int p = 0; p < 4; p++) {
                uint32_t a = kbuf + p * (16 * AT_STR) + offBK + kk * 32;
                uint32_t h0, h1, h2, h3;
                LDSM_X4(h0, h1, h2, h3, a);
                mma16816(sc[2 * p],     qf[kk], h0, h1);
                mma16816(sc[2 * p + 1], qf[kk], h2, h3);
            }
        }
#pragma unroll
        for (int t = 0; t < 8; t++)
#pragma unroll
            for (int u = 0; u < 4; u++) sc[t][u] *= 0.125f;
        if (kb >= 2 * qblk) {
            int r0 = q0 + wid * 16 + gid;
            int cb = kb * 64 + tig * 2;
#pragma unroll
            for (int t = 0; t < 8; t++) {
                int col = cb + t * 8;
                if (col     >= r0)     sc[t][0] = -1e30f;
                if (col + 1 >= r0)     sc[t][1] = -1e30f;
                if (col     >= r0 + 8) sc[t][2] = -1e30f;
                if (col + 1 >= r0 + 8) sc[t][3] = -1e30f;
            }
        }

        float mx0 = -INFINITY, mx1 = -INFINITY;
#pragma unroll
        for (int t = 0; t < 8; t++) {
            mx0 = fmaxf(mx0, fmaxf(sc[t][0], sc[t][1]));
            mx1 = fmaxf(mx1, fmaxf(sc[t][2], sc[t][3]));
        }
        mx0 = fmaxf(mx0, __shfl_xor_sync(0xffffffffu, mx0, 1));
        mx0 = fmaxf(mx0, __shfl_xor_sync(0xffffffffu, mx0, 2));
        mx1 = fmaxf(mx1, __shfl_xor_sync(0xffffffffu, mx1, 1));
        mx1 = fmaxf(mx1, __shfl_xor_sync(0xffffffffu, mx1, 2));
        float mn0 = fmaxf(m0, mx0);
        float mn1 = fmaxf(m1, mx1);
        float cr0 = __expf(m0 - mn0);
        float cr1 = __expf(m1 - mn1);
        float sum0 = 0.f, sum1 = 0.f;
#pragma unroll
        for (int t = 0; t < 8; t++) {
            sc[t][0] = __expf(sc[t][0] - mn0); sum0 += sc[t][0];
            sc[t][1] = __expf(sc[t][1] - mn0); sum0 += sc[t][1];
            sc[t][2] = __expf(sc[t][2] - mn1); sum1 += sc[t][2];
            sc[t][3] = __expf(sc[t][3] - mn1); sum1 += sc[t][3];
        }
        sum0 += __shfl_xor_sync(0xffffffffu, sum0, 1);
        sum0 += __shfl_xor_sync(0xffffffffu, sum0, 2);
        sum1 += __shfl_xor_sync(0xffffffffu, sum1, 1);
        sum1 += __shfl_xor_sync(0xffffffffu, sum1, 2);
        l0 = l0 * cr0 + sum0;
        l1 = l1 * cr1 + sum1;
        m0 = mn0; m1 = mn1;
#pragma unroll
        for (int t = 0; t < 8; t++) {
            o[t][0] *= cr0; o[t][1] *= cr0;
            o[t][2] *= cr1; o[t][3] *= cr1;
        }

        const uint32_t vbuf = kbuf + 9216;
#pragma unroll
        for (int kk = 0; kk < 4; kk++) {
            uint32_t pf[4];
            pf[0] = pack2(sc[2 * kk][0],     sc[2 * kk][1]);
            pf[1] = pack2(sc[2 * kk][2],     sc[2 * kk][3]);
            pf[2] = pack2(sc[2 * kk + 1][0], sc[2 * kk + 1][1]);
            pf[3] = pack2(sc[2 * kk + 1][2], sc[2 * kk + 1][3]);
#pragma unroll
            for (int dp = 0; dp < 4; dp++) {
                uint32_t a = vbuf + kk * (16 * AT_STR) + dp * 32 + offBV;
                uint32_t v0, v1, v2, v3;
                LDSM_X4_T(v0, v1, v2, v3, a);
                mma16816(o[2 * dp],     pf, v0, v1);
                mma16816(o[2 * dp + 1], pf, v2, v3);
            }
        }
    }

    const int srow0 = q0 + wid * 16 + gid;
    const int srow1 = srow0 + 8;
    const bool z0 = (srow0 == 0) && (b == 0 ? true : true);  // global row0 of this (b,h): s==0
    const float inv0 = ((q0 + wid * 16 + gid) == 0) ? 0.f : 1.f / l0;
    const float inv1 = 1.f / l1;
#pragma unroll
    for (int t = 0; t < 8; t++) {
        int d = t * 8 + tig * 2;
        size_t off0 = obase + (size_t)srow0 * D_MODEL + d;
        size_t off1 = obase + (size_t)srow1 * D_MODEL + d;
        *(__half2*)(Oh + off0) = __floats2half2_rn(o[t][0] * inv0, o[t][1] * inv0);
        *(__half2*)(Oh + off1) = __floats2half2_rn(o[t][2] * inv1, o[t][3] * inv1);
    }
}

// ---------------------------------------------------------------------------
// Fused residual add + LayerNorm (+ optional fp16 output)
// ---------------------------------------------------------------------------
template <bool HOUT>
__global__ __launch_bounds__(256)
void add_ln_kernel(const float* __restrict__ A, const float* __restrict__ Bm,
                   const float* __restrict__ g, const float* __restrict__ beta,
                   float* __restrict__ out, __half* __restrict__ oh)
{
    __shared__ float red_s[8];
    __shared__ float red_q[8];
    __shared__ float stats[2];

    const int row = blockIdx.x;
    const int c = threadIdx.x * 4;
    float4 av = *(const float4*)(A + (size_t)row * D_MODEL + c);
    float4 bv = *(const float4*)(Bm + (size_t)row * D_MODEL + c);
    float v0 = av.x + bv.x, v1 = av.y + bv.y, v2 = av.z + bv.z, v3 = av.w + bv.w;

    float s = v0 + v1 + v2 + v3;
    float q = v0 * v0 + v1 * v1 + v2 * v2 + v3 * v3;
#pragma unroll
    for (int off = 16; off > 0; off >>= 1) {
        s += __shfl_xor_sync(0xffffffffu, s, off);
        q += __shfl_xor_sync(0xffffffffu, q, off);
    }
    if ((threadIdx.x & 31) == 0) {
        red_s[threadIdx.x >> 5] = s;
        red_q[threadIdx.x >> 5] = q;
    }
    __syncthreads();
    if (threadIdx.x < 32) {
        float ts = (threadIdx.x < 8) ? red_s[threadIdx.x] : 0.f;
        float tq = (threadIdx.x < 8) ? red_q[threadIdx.x] : 0.f;
#pragma unroll
        for (int off = 4; off > 0; off >>= 1) {
            ts += __shfl_xor_sync(0xffffffffu, ts, off);
            tq += __shfl_xor_sync(0xffffffffu, tq, off);
        }
        if (threadIdx.x == 0) {
            float mu = ts * (1.f / D_MODEL);
            float var = tq * (1.f / D_MODEL) - mu * mu;
            stats[0] = mu;
            stats[1] = rsqrtf(fmaxf(var, 0.f) + 1e-5f);
        }
    }
    __syncthreads();
    const float mu = stats[0];
    const float rstd = stats[1];

    float4 gv = *(const float4*)(g + c);
    float4 bev = *(const float4*)(beta + c);
    float4 ov;
    ov.x = (v0 - mu) * rstd * gv.x + bev.x;
    ov.y = (v1 - mu) * rstd * gv.y + bev.y;
    ov.z = (v2 - mu) * rstd * gv.z + bev.z;
    ov.w = (v3 - mu) * rstd * gv.w + bev.w;
    *(float4*)(out + (size_t)row * D_MODEL + c) = ov;
    if (HOUT) {
        size_t off = (size_t)row * D_MODEL + c;
        *(__half2*)(oh + off)     = __floats2half2_rn(ov.x, ov.y);
        *(__half2*)(oh + off + 2) = __floats2half2_rn(ov.z, ov.w);
    }
}

// ---------------------------------------------------------------------------
static inline float* sym(const void* s) {
    void* p = nullptr;
    cudaGetSymbolAddress(&p, s);
    return (float*)p;
}

extern "C" void kernel_launch(void* const* d_in, const int* in_sizes, int n_in,
                              void* d_out, int out_size)
{
    const float* x   = (const float*)d_in[0];
    const float* Wq  = (const float*)d_in[1];
    const float* bq  = (const float*)d_in[2];
    const float* Wk  = (const float*)d_in[3];
    const float* bk  = (const float*)d_in[4];
    const float* Wv  = (const float*)d_in[5];
    const float* bv  = (const float*)d_in[6];
    const float* Wo  = (const float*)d_in[7];
    const float* bo  = (const float*)d_in[8];
    const float* W1  = (const float*)d_in[9];
    const float* b1  = (const float*)d_in[10];
    const float* W2  = (const float*)d_in[11];
    const float* b2  = (const float*)d_in[12];
    const float* g1  = (const float*)d_in[13];
    const float* be1 = (const float*)d_in[14];
    const float* g3  = (const float*)d_in[15];
    const float* be3 = (const float*)d_in[16];
    float* out = (float*)d_out;

    float* attn = sym(g_attn);
    float* ffn  = sym(g_ffn);
    float* h1   = sym(g_h1);
    float* bqkv = sym(g_bqkv);
    __half* sa   = (__half*)sym(g_sa);
    __half* sb   = (__half*)sym(g_sb);
    __half* qkv  = (__half*)sym(g_qkv);
    __half* wqkv = (__half*)sym(g_wqkv);
    __half* wo = (__half*)sym(g_wo);
    __half* w1 = (__half*)sym(g_w1);
    __half* w2 = (__half*)sym(g_w2);

    cudaFuncSetAttribute(attention_mma, cudaFuncAttributeMaxDynamicSharedMemorySize, AT_SMEM);
    cudaFuncSetAttribute(gemm_mma<false, OUT_F32>, cudaFuncAttributeMaxDynamicSharedMemorySize, GM_SMEM);
    cudaFuncSetAttribute(gemm_mma<false, OUT_HI>,  cudaFuncAttributeMaxDynamicSharedMemorySize, GM_SMEM);
    cudaFuncSetAttribute(gemm_mma<true,  OUT_HI>,  cudaFuncAttributeMaxDynamicSharedMemorySize, GM_SMEM);

    dim3 tb(256);
    const int n4_x = (M_ROWS * D_MODEL) / 4;
    dim3 gProj(D_MODEL / 128, M_ROWS / 128);   // (8, 64)
    dim3 gQKV(D_QKV / 128, M_ROWS / 128);      // (24, 64)
    dim3 gFF1(D_FF / 128, M_ROWS / 128);       // (32, 64)
    dim3 gT(D_MODEL / 32, D_MODEL / 32);

    // prep; launch 5 is the fused QKV gemm (ncu -s 5 -c 1 profiles it)
    concat_bias<<<D_QKV / 256, tb>>>(bq, bk, bv, bqkv);                            // 0
    transpose_f16<<<gT, tb>>>(Wq, wqkv,                     D_MODEL, D_MODEL);     // 1
    transpose_f16<<<gT, tb>>>(Wk, wqkv + 1024 * 1024,       D_MODEL, D_MODEL);     // 2
    transpose_f16<<<gT, tb>>>(Wv, wqkv + 2 * 1024 * 1024,   D_MODEL, D_MODEL);     // 3
    conv_f16<<<n4_x / 256, tb>>>((const float4*)x, (__half2*)sa, n4_x);            // 4
    gemm_mma<false, OUT_HI><<<gQKV, tb, GM_SMEM>>>(sa, wqkv, bqkv, nullptr, qkv,
                                                   M_ROWS, D_QKV, D_MODEL);        // 5
    transpose_f16<<<gT, tb>>>(Wo, wo, D_MODEL, D_MODEL);
    transpose_f16<<<dim3(D_FF / 32, D_MODEL / 32), tb>>>(W1, w1, D_MODEL, D_FF);
    transpose_f16<<<dim3(D_MODEL / 32, D_FF / 32), tb>>>(W2, w2, D_FF, D_MODEL);

    attention_mma<<<dim3(S_LEN / 128, B_SZ * N_HEADS), tb, AT_SMEM>>>(qkv, sb);

    gemm_mma<false, OUT_F32><<<gProj, tb, GM_SMEM>>>(sb, wo, bo, attn, nullptr,
                                                     M_ROWS, D_MODEL, D_MODEL);
    add_ln_kernel<true><<<M_ROWS, tb>>>(x, attn, g1, be1, h1, sa);
    gemm_mma<true, OUT_HI><<<gFF1, tb, GM_SMEM>>>(sa, w1, b1, nullptr, sb,
                                                  M_ROWS, D_FF, D_MODEL);
    gemm_mma<false, OUT_F32><<<gProj, tb, GM_SMEM>>>(sb, w2, b2, ffn, nullptr,
                                                     M_ROWS, D_MODEL, D_FF);
    add_ln_kernel<false><<<M_ROWS, tb>>>(h1, ffn, g3, be3, out, nullptr);
}

// round 16
// speedup vs baseline: 5.8784x; 1.0093x over previous
#include <cuda_runtime.h>
#include <cuda_fp16.h>
#include <math.h>
#include <stdint.h>

#define B_SZ 8
#define S_LEN 1024
#define D_MODEL 1024
#define N_HEADS 16
#define D_K 64
#define D_FF 4096
#define M_ROWS (B_SZ * S_LEN)
#define D_QKV (3 * D_MODEL)

extern __shared__ char dyn_smem[];

// ---- scratch globals ----
__device__ float g_attn[(size_t)M_ROWS * D_MODEL];
__device__ float g_ffn[(size_t)M_ROWS * D_MODEL];
__device__ float g_h1[(size_t)M_ROWS * D_MODEL];
__device__ __half g_sa[(size_t)M_ROWS * D_MODEL];    // x fp16, then h1 fp16
__device__ __half g_sb[(size_t)M_ROWS * D_FF];       // ctx fp16, then mid fp16
__device__ __half g_qkv[(size_t)M_ROWS * D_QKV];     // fused q|k|v fp16
__device__ __half g_wqkv[(size_t)D_QKV * D_MODEL];   // fused weights [3072,1024] fp16
__device__ float  g_bqkv[D_QKV];                     // fused bias
__device__ __half g_wo[(size_t)D_MODEL * D_MODEL];
__device__ __half g_w1[(size_t)D_FF * D_MODEL];
__device__ __half g_w2[(size_t)D_MODEL * D_FF];

// ---- PTX helpers ----
static __device__ __forceinline__ uint32_t smem_u32(const void* p) {
    uint32_t a;
    asm("{ .reg .u64 t; cvta.to.shared.u64 t, %1; cvt.u32.u64 %0, t; }" : "=r"(a) : "l"(p));
    return a;
}
#define CP_ASYNC16(dst, src) \
    asm volatile("cp.async.cg.shared.global [%0], [%1], 16;" :: "r"((uint32_t)(dst)), "l"(src))
#define CP_COMMIT() asm volatile("cp.async.commit_group;" ::: "memory")
#define LDSM_X4(R0, R1, R2, R3, ADDR) \
    asm volatile("ldmatrix.sync.aligned.m8n8.x4.shared.b16 {%0,%1,%2,%3}, [%4];" \
                 : "=r"(R0), "=r"(R1), "=r"(R2), "=r"(R3) : "r"(ADDR))
#define LDSM_X4_T(R0, R1, R2, R3, ADDR) \
    asm volatile("ldmatrix.sync.aligned.m8n8.x4.trans.shared.b16 {%0,%1,%2,%3}, [%4];" \
                 : "=r"(R0), "=r"(R1), "=r"(R2), "=r"(R3) : "r"(ADDR))

static __device__ __forceinline__ void mma16816(float* d, const uint32_t* a, uint32_t b0, uint32_t b1)
{
    asm volatile(
        "mma.sync.aligned.m16n8k16.row.col.f32.f16.f16.f32 "
        "{%0,%1,%2,%3}, {%4,%5,%6,%7}, {%8,%9}, {%0,%1,%2,%3};"
        : "+f"(d[0]), "+f"(d[1]), "+f"(d[2]), "+f"(d[3])
        : "r"(a[0]), "r"(a[1]), "r"(a[2]), "r"(a[3]), "r"(b0), "r"(b1));
}

static __device__ __forceinline__ uint32_t pack2(float a, float b)
{
    __half2 h = __floats2half2_rn(a, b);
    return *reinterpret_cast<uint32_t*>(&h);
}

// ---------------------------------------------------------------------------
// GEMM (unchanged, proven): C = A @ B^T + bias, fp16 in, 2 CTAs/SM
// ---------------------------------------------------------------------------
#define GM_BUFSZ 20480
#define GM_SMEM  (3 * GM_BUFSZ)
#define OUT_F32 0
#define OUT_HI  1

static __device__ __forceinline__ void load_chunk(
    uint32_t sdst, const __half* aH, const __half* bH, int kb, int K, int tid)
{
#pragma unroll
    for (int j = 0; j < 2; j++) {
        int idx = tid + j * 256;
        int r = idx >> 2;
        int s = idx & 3;
        uint32_t doff = (uint32_t)(r * 80 + s * 16);
        size_t goff = (size_t)r * K + kb;
        CP_ASYNC16(sdst + doff,         (const char*)(aH + goff) + s * 16);
        CP_ASYNC16(sdst + 10240 + doff, (const char*)(bH + goff) + s * 16);
    }
}

template <bool RELU, int OUT>
__global__ __launch_bounds__(256, 2)
void gemm_mma(const __half* __restrict__ Ah, const __half* __restrict__ Bh,
              const float* __restrict__ bias, float* __restrict__ C,
              __half* __restrict__ Ch, int M, int N, int K)
{
    const uint32_t sbase = smem_u32(dyn_smem);
    const int tid = threadIdx.x;
    const int wid = tid >> 5;
    const int lane = tid & 31;
    const int gid = lane >> 2;
    const int tig = lane & 3;
    const int n0 = blockIdx.x * 128;
    const int m0 = blockIdx.y * 128;
    const int wm = (wid >> 2) * 64;
    const int wn = (wid & 3) * 32;
    const int nch = K >> 5;

    const __half* aH = Ah + (size_t)m0 * K;
    const __half* bH = Bh + (size_t)n0 * K;

    const uint32_t offA = (uint32_t)((wm + ((lane >> 3) & 1) * 8 + (lane & 7)) * 80 + (lane >> 4) * 16);
    const uint32_t offB = (uint32_t)((wn + (lane >> 4) * 8 + (lane & 7)) * 80 + ((lane >> 3) & 1) * 16);

    float acc[4][4][4];
#pragma unroll
    for (int mt = 0; mt < 4; mt++)
#pragma unroll
        for (int nt = 0; nt < 4; nt++)
#pragma unroll
            for (int u = 0; u < 4; u++) acc[mt][nt][u] = 0.f;

    load_chunk(sbase,            aH, bH, 0,  K, tid);
    CP_COMMIT();
    load_chunk(sbase + GM_BUFSZ, aH, bH, 32, K, tid);
    CP_COMMIT();

    for (int ch = 0; ch < nch; ch++) {
        if (ch == nch - 1) asm volatile("cp.async.wait_group 0;" ::: "memory");
        else               asm volatile("cp.async.wait_group 1;" ::: "memory");
        __syncthreads();

        if (ch + 2 < nch) {
            load_chunk(sbase + ((ch + 2) % 3) * GM_BUFSZ, aH, bH, (ch + 2) * 32, K, tid);
            CP_COMMIT();
        }

        const uint32_t buf = sbase + (ch % 3) * GM_BUFSZ;
        const uint32_t pA = buf + offA;
        const uint32_t pB = buf + 10240 + offB;

#pragma unroll
        for (int kk = 0; kk < 2; kk++) {
            uint32_t af[4][4], bf[4][2];
#pragma unroll
            for (int mt = 0; mt < 4; mt++)
                LDSM_X4(af[mt][0], af[mt][1], af[mt][2], af[mt][3], pA + mt * 1280 + kk * 32);
#pragma unroll
            for (int nt2 = 0; nt2 < 2; nt2++)
                LDSM_X4(bf[nt2 * 2][0], bf[nt2 * 2][1], bf[nt2 * 2 + 1][0], bf[nt2 * 2 + 1][1],
                        pB + nt2 * 1280 + kk * 32);
#pragma unroll
            for (int nt = 0; nt < 4; nt++)
#pragma unroll
                for (int mt = 0; mt < 4; mt++)
                    mma16816(acc[mt][nt], af[mt], bf[nt][0], bf[nt][1]);
        }
    }

#pragma unroll
    for (int mt = 0; mt < 4; mt++) {
        int r0 = m0 + wm + mt * 16 + gid;
#pragma unroll
        for (int nt = 0; nt < 4; nt++) {
            int c0 = n0 + wn + nt * 8 + tig * 2;
            float bb0 = bias[c0], bb1 = bias[c0 + 1];
            float v0 = acc[mt][nt][0] + bb0;
            float v1 = acc[mt][nt][1] + bb1;
            float v2 = acc[mt][nt][2] + bb0;
            float v3 = acc[mt][nt][3] + bb1;
            if (RELU) {
                v0 = fmaxf(v0, 0.f); v1 = fmaxf(v1, 0.f);
                v2 = fmaxf(v2, 0.f); v3 = fmaxf(v3, 0.f);
            }
            if (OUT == OUT_HI) {
                *(__half2*)(Ch + (size_t)r0 * N + c0)       = __floats2half2_rn(v0, v1);
                *(__half2*)(Ch + (size_t)(r0 + 8) * N + c0) = __floats2half2_rn(v2, v3);
            } else {
                *(float2*)(C + (size_t)r0 * N + c0)       = make_float2(v0, v1);
                *(float2*)(C + (size_t)(r0 + 8) * N + c0) = make_float2(v2, v3);
            }
        }
    }
}

// ---------------------------------------------------------------------------
// prep kernels
// ---------------------------------------------------------------------------
__global__ __launch_bounds__(256)
void concat_bias(const float* __restrict__ bq, const float* __restrict__ bk,
                 const float* __restrict__ bv, float* __restrict__ o)
{
    int i = blockIdx.x * 256 + threadIdx.x;
    const float* src = (i < 1024) ? bq : (i < 2048) ? bk : bv;
    o[i] = src[i & 1023];
}

__global__ __launch_bounds__(256)
void conv_f16(const float4* __restrict__ in, __half2* __restrict__ h2, int n4)
{
    int i = blockIdx.x * 256 + threadIdx.x;
    if (i >= n4) return;
    float4 v = in[i];
    h2[2 * i]     = __floats2half2_rn(v.x, v.y);
    h2[2 * i + 1] = __floats2half2_rn(v.z, v.w);
}

// W[K,N] fp32 -> transposed fp16 [N,K]; vectorized (float4 load, uint2 store)
__global__ __launch_bounds__(256)
void transpose_f16(const float* __restrict__ W, __half* __restrict__ T, int K, int N)
{
    __shared__ float tile[32][33];
    const int n0 = blockIdx.x * 32;
    const int k0 = blockIdx.y * 32;
    {
        int r  = threadIdx.x >> 3;          // k row 0..31
        int c4 = (threadIdx.x & 7) * 4;     // n col
        float4 v = *(const float4*)(W + (size_t)(k0 + r) * N + n0 + c4);
        tile[r][c4 + 0] = v.x; tile[r][c4 + 1] = v.y;
        tile[r][c4 + 2] = v.z; tile[r][c4 + 3] = v.w;
    }
    __syncthreads();
    {
        int n  = threadIdx.x >> 3;          // n 0..31
        int ks = (threadIdx.x & 7) * 4;     // k seg
        __half2 h0 = __floats2half2_rn(tile[ks][n],     tile[ks + 1][n]);
        __half2 h1 = __floats2half2_rn(tile[ks + 2][n], tile[ks + 3][n]);
        uint2 u;
        u.x = *reinterpret_cast<uint32_t*>(&h0);
        u.y = *reinterpret_cast<uint32_t*>(&h1);
        *(uint2*)(T + (size_t)(n0 + n) * K + k0 + ks) = u;
    }
}

// ---------------------------------------------------------------------------
// Tensor-core causal attention, pure fp16 (unchanged from R15)
// ---------------------------------------------------------------------------
#define AT_STR  144
#define AT_QSZ  18432
#define AT_BUF  18432
#define AT_SMEM (AT_QSZ + 3 * AT_BUF)

static __device__ __forceinline__ void load_kv(
    uint32_t dst, const __half* Kh, const __half* Vh, int kb, int tid)
{
#pragma unroll
    for (int j = 0; j < 2; j++) {
        int idx = tid + j * 256;
        int r = idx >> 3;
        int s = idx & 7;
        uint32_t doff = (uint32_t)(r * AT_STR + s * 16);
        size_t g = (size_t)(kb * 64 + r) * D_QKV + s * 8;
        CP_ASYNC16(dst + doff,        Kh + g);
        CP_ASYNC16(dst + 9216 + doff, Vh + g);
    }
}

__global__ __launch_bounds__(256, 1)
void attention_mma(const __half* __restrict__ QKV, __half* __restrict__ Oh)
{
    const uint32_t sb = smem_u32(dyn_smem);
    const int tid = threadIdx.x;
    const int wid = tid >> 5;
    const int lane = tid & 31;
    const int gid = lane >> 2;
    const int tig = lane & 3;
    const int qblk = blockIdx.x;
    const int bh = blockIdx.y;
    const int b = bh >> 4;
    const int h = bh & 15;
    const int q0 = qblk * 128;
    const __half* Qb = QKV + (size_t)(b * S_LEN) * D_QKV + h * D_K;
    const __half* Kb = Qb + D_MODEL;
    const __half* Vb = Qb + 2 * D_MODEL;
    const size_t obase = (size_t)(b * S_LEN) * D_MODEL + h * D_K;
    const int nkb = 2 * qblk + 2;

#pragma unroll
    for (int j = 0; j < 2; j++) {
        int idx = tid + j * 256;
        int r = idx >> 2;
        int s2 = (idx & 3) * 2;
#pragma unroll
        for (int u = 0; u < 2; u++) {
            int s = s2 + u;
            size_t g = (size_t)(q0 + r) * D_QKV + s * 8;
            CP_ASYNC16(sb + (uint32_t)(r * AT_STR + s * 16), Qb + g);
        }
    }
    CP_COMMIT();
    load_kv(sb + AT_QSZ,          Kb, Vb, 0, tid); CP_COMMIT();
    load_kv(sb + AT_QSZ + AT_BUF, Kb, Vb, 1, tid); CP_COMMIT();

    uint32_t qf[4][4];
    float m0 = -INFINITY, m1 = -INFINITY, l0 = 0.f, l1 = 0.f;
    float o[8][4];
#pragma unroll
    for (int t = 0; t < 8; t++)
#pragma unroll
        for (int u = 0; u < 4; u++) o[t][u] = 0.f;

    const uint32_t offQ = sb + (uint32_t)((wid * 16 + ((lane >> 3) & 1) * 8 + (lane & 7)) * AT_STR +
                                          (lane >> 4) * 16);
    const uint32_t offBK = (uint32_t)(((lane >> 4) * 8 + (lane & 7)) * AT_STR + ((lane >> 3) & 1) * 16);
    const uint32_t offBV = (uint32_t)((lane & 15) * AT_STR + (lane >> 4) * 16);

    for (int kb = 0; kb < nkb; kb++) {
        if (kb + 1 < nkb) asm volatile("cp.async.wait_group 1;" ::: "memory");
        else              asm volatile("cp.async.wait_group 0;" ::: "memory");
        __syncthreads();

        if (kb == 0) {
#pragma unroll
            for (int kk = 0; kk < 4; kk++)
                LDSM_X4(qf[kk][0], qf[kk][1], qf[kk][2], qf[kk][3], offQ + kk * 32);
        }
        if (kb + 2 < nkb) {
            load_kv(sb + AT_QSZ + ((kb + 2) % 3) * AT_BUF, Kb, Vb, kb + 2, tid);
            CP_COMMIT();
        }

        const uint32_t kbuf = sb + AT_QSZ + (kb % 3) * AT_BUF;

        float sc[8][4];
#pragma unroll
        for (int t = 0; t < 8; t++)
#pragma unroll
            for (int u = 0; u < 4; u++) sc[t][u] = 0.f;
#pragma unroll
        for (int kk = 0; kk < 4; kk++) {
#pragma unroll
            for (int p = 0; p < 4; p++) {
                uint32_t a = kbuf + p * (16 * AT_STR) + offBK + kk * 32;
                uint32_t h0, h1, h2, h3;
                LDSM_X4(h0, h1, h2, h3, a);
                mma16816(sc[2 * p],     qf[kk], h0, h1);
                mma16816(sc[2 * p + 1], qf[kk], h2, h3);
            }
        }
#pragma unroll
        for (int t = 0; t < 8; t++)
#pragma unroll
            for (int u = 0; u < 4; u++) sc[t][u] *= 0.125f;
        if (kb >= 2 * qblk) {
            int r0 = q0 + wid * 16 + gid;
            int cb = kb * 64 + tig * 2;
#pragma unroll
            for (int t = 0; t < 8; t++) {
                int col = cb + t * 8;
                if (col     >= r0)     sc[t][0] = -1e30f;
                if (col + 1 >= r0)     sc[t][1] = -1e30f;
                if (col     >= r0 + 8) sc[t][2] = -1e30f;
                if (col + 1 >= r0 + 8) sc[t][3] = -1e30f;
            }
        }

        float mx0 = -INFINITY, mx1 = -INFINITY;
#pragma unroll
        for (int t = 0; t < 8; t++) {
            mx0 = fmaxf(mx0, fmaxf(sc[t][0], sc[t][1]));
            mx1 = fmaxf(mx1, fmaxf(sc[t][2], sc[t][3]));
        }
        mx0 = fmaxf(mx0, __shfl_xor_sync(0xffffffffu, mx0, 1));
        mx0 = fmaxf(mx0, __shfl_xor_sync(0xffffffffu, mx0, 2));
        mx1 = fmaxf(mx1, __shfl_xor_sync(0xffffffffu, mx1, 1));
        mx1 = fmaxf(mx1, __shfl_xor_sync(0xffffffffu, mx1, 2));
        float mn0 = fmaxf(m0, mx0);
        float mn1 = fmaxf(m1, mx1);
        float cr0 = __expf(m0 - mn0);
        float cr1 = __expf(m1 - mn1);
        float sum0 = 0.f, sum1 = 0.f;
#pragma unroll
        for (int t = 0; t < 8; t++) {
            sc[t][0] = __expf(sc[t][0] - mn0); sum0 += sc[t][0];
            sc[t][1] = __expf(sc[t][1] - mn0); sum0 += sc[t][1];
            sc[t][2] = __expf(sc[t][2] - mn1); sum1 += sc[t][2];
            sc[t][3] = __expf(sc[t][3] - mn1); sum1 += sc[t][3];
        }
        sum0 += __shfl_xor_sync(0xffffffffu, sum0, 1);
        sum0 += __shfl_xor_sync(0xffffffffu, sum0, 2);
        sum1 += __shfl_xor_sync(0xffffffffu, sum1, 1);
        sum1 += __shfl_xor_sync(0xffffffffu, sum1, 2);
        l0 = l0 * cr0 + sum0;
        l1 = l1 * cr1 + sum1;
        m0 = mn0; m1 = mn1;
#pragma unroll
        for (int t = 0; t < 8; t++) {
            o[t][0] *= cr0; o[t][1] *= cr0;
            o[t][2] *= cr1; o[t][3] *= cr1;
        }

        const uint32_t vbuf = kbuf + 9216;
#pragma unroll
        for (int kk = 0; kk < 4; kk++) {
            uint32_t pf[4];
            pf[0] = pack2(sc[2 * kk][0],     sc[2 * kk][1]);
            pf[1] = pack2(sc[2 * kk][2],     sc[2 * kk][3]);
            pf[2] = pack2(sc[2 * kk + 1][0], sc[2 * kk + 1][1]);
            pf[3] = pack2(sc[2 * kk + 1][2], sc[2 * kk + 1][3]);
#pragma unroll
            for (int dp = 0; dp < 4; dp++) {
                uint32_t a = vbuf + kk * (16 * AT_STR) + dp * 32 + offBV;
                uint32_t v0, v1, v2, v3;
                LDSM_X4_T(v0, v1, v2, v3, a);
                mma16816(o[2 * dp],     pf, v0, v1);
                mma16816(o[2 * dp + 1], pf, v2, v3);
            }
        }
    }

    const int srow0 = q0 + wid * 16 + gid;
    const int srow1 = srow0 + 8;
    const float inv0 = (srow0 == 0) ? 0.f : 1.f / l0;
    const float inv1 = 1.f / l1;
#pragma unroll
    for (int t = 0; t < 8; t++) {
        int d = t * 8 + tig * 2;
        size_t off0 = obase + (size_t)srow0 * D_MODEL + d;
        size_t off1 = obase + (size_t)srow1 * D_MODEL + d;
        *(__half2*)(Oh + off0) = __floats2half2_rn(o[t][0] * inv0, o[t][1] * inv0);
        *(__half2*)(Oh + off1) = __floats2half2_rn(o[t][2] * inv1, o[t][3] * inv1);
    }
}

// ---------------------------------------------------------------------------
// Fused residual add + LayerNorm (+ optional fp16 output)
// ---------------------------------------------------------------------------
template <bool HOUT>
__global__ __launch_bounds__(256)
void add_ln_kernel(const float* __restrict__ A, const float* __restrict__ Bm,
                   const float* __restrict__ g, const float* __restrict__ beta,
                   float* __restrict__ out, __half* __restrict__ oh)
{
    __shared__ float red_s[8];
    __shared__ float red_q[8];
    __shared__ float stats[2];

    const int row = blockIdx.x;
    const int c = threadIdx.x * 4;
    float4 av = *(const float4*)(A + (size_t)row * D_MODEL + c);
    float4 bv = *(const float4*)(Bm + (size_t)row * D_MODEL + c);
    float v0 = av.x + bv.x, v1 = av.y + bv.y, v2 = av.z + bv.z, v3 = av.w + bv.w;

    float s = v0 + v1 + v2 + v3;
    float q = v0 * v0 + v1 * v1 + v2 * v2 + v3 * v3;
#pragma unroll
    for (int off = 16; off > 0; off >>= 1) {
        s += __shfl_xor_sync(0xffffffffu, s, off);
        q += __shfl_xor_sync(0xffffffffu, q, off);
    }
    if ((threadIdx.x & 31) == 0) {
        red_s[threadIdx.x >> 5] = s;
        red_q[threadIdx.x >> 5] = q;
    }
    __syncthreads();
    if (threadIdx.x < 32) {
        float ts = (threadIdx.x < 8) ? red_s[threadIdx.x] : 0.f;
        float tq = (threadIdx.x < 8) ? red_q[threadIdx.x] : 0.f;
#pragma unroll
        for (int off = 4; off > 0; off >>= 1) {
            ts += __shfl_xor_sync(0xffffffffu, ts, off);
            tq += __shfl_xor_sync(0xffffffffu, tq, off);
        }
        if (threadIdx.x == 0) {
            float mu = ts * (1.f / D_MODEL);
            float var = tq * (1.f / D_MODEL) - mu * mu;
            stats[0] = mu;
            stats[1] = rsqrtf(fmaxf(var, 0.f) + 1e-5f);
        }
    }
    __syncthreads();
    const float mu = stats[0];
    const float rstd = stats[1];

    float4 gv = *(const float4*)(g + c);
    float4 bev = *(const float4*)(beta + c);
    float4 ov;
    ov.x = (v0 - mu) * rstd * gv.x + bev.x;
    ov.y = (v1 - mu) * rstd * gv.y + bev.y;
    ov.z = (v2 - mu) * rstd * gv.z + bev.z;
    ov.w = (v3 - mu) * rstd * gv.w + bev.w;
    *(float4*)(out + (size_t)row * D_MODEL + c) = ov;
    if (HOUT) {
        size_t off = (size_t)row * D_MODEL + c;
        *(__half2*)(oh + off)     = __floats2half2_rn(ov.x, ov.y);
        *(__half2*)(oh + off + 2) = __floats2half2_rn(ov.z, ov.w);
    }
}

// ---------------------------------------------------------------------------
static inline float* sym(const void* s) {
    void* p = nullptr;
    cudaGetSymbolAddress(&p, s);
    return (float*)p;
}

extern "C" void kernel_launch(void* const* d_in, const int* in_sizes, int n_in,
                              void* d_out, int out_size)
{
    const float* x   = (const float*)d_in[0];
    const float* Wq  = (const float*)d_in[1];
    const float* bq  = (const float*)d_in[2];
    const float* Wk  = (const float*)d_in[3];
    const float* bk  = (const float*)d_in[4];
    const float* Wv  = (const float*)d_in[5];
    const float* bv  = (const float*)d_in[6];
    const float* Wo  = (const float*)d_in[7];
    const float* bo  = (const float*)d_in[8];
    const float* W1  = (const float*)d_in[9];
    const float* b1  = (const float*)d_in[10];
    const float* W2  = (const float*)d_in[11];
    const float* b2  = (const float*)d_in[12];
    const float* g1  = (const float*)d_in[13];
    const float* be1 = (const float*)d_in[14];
    const float* g3  = (const float*)d_in[15];
    const float* be3 = (const float*)d_in[16];
    float* out = (float*)d_out;

    float* attn = sym(g_attn);
    float* ffn  = sym(g_ffn);
    float* h1   = sym(g_h1);
    float* bqkv = sym(g_bqkv);
    __half* sa   = (__half*)sym(g_sa);
    __half* sb   = (__half*)sym(g_sb);
    __half* qkv  = (__half*)sym(g_qkv);
    __half* wqkv = (__half*)sym(g_wqkv);
    __half* wo = (__half*)sym(g_wo);
    __half* w1 = (__half*)sym(g_w1);
    __half* w2 = (__half*)sym(g_w2);

    cudaFuncSetAttribute(attention_mma, cudaFuncAttributeMaxDynamicSharedMemorySize, AT_SMEM);
    cudaFuncSetAttribute(gemm_mma<false, OUT_F32>, cudaFuncAttributeMaxDynamicSharedMemorySize, GM_SMEM);
    cudaFuncSetAttribute(gemm_mma<false, OUT_HI>,  cudaFuncAttributeMaxDynamicSharedMemorySize, GM_SMEM);
    cudaFuncSetAttribute(gemm_mma<true,  OUT_HI>,  cudaFuncAttributeMaxDynamicSharedMemorySize, GM_SMEM);

    // side stream + events (created once; capture-safe fork/join via events)
    static cudaStream_t s2 = nullptr;
    static cudaEvent_t evF = nullptr, evJ = nullptr;
    if (s2 == nullptr) {
        cudaStreamCreateWithFlags(&s2, cudaStreamNonBlocking);
        cudaEventCreateWithFlags(&evF, cudaEventDisableTiming);
        cudaEventCreateWithFlags(&evJ, cudaEventDisableTiming);
    }

    dim3 tb(256);
    const int n4_x = (M_ROWS * D_MODEL) / 4;
    dim3 gProj(D_MODEL / 128, M_ROWS / 128);   // (8, 64)
    dim3 gQKV(D_QKV / 128, M_ROWS / 128);      // (24, 64)
    dim3 gFF1(D_FF / 128, M_ROWS / 128);       // (32, 64)
    dim3 gT(D_MODEL / 32, D_MODEL / 32);

    // fork: Wo/W1/W2 transposes run on s2, overlapping QKV gemm + attention
    cudaEventRecord(evF, 0);
    cudaStreamWaitEvent(s2, evF, 0);
    transpose_f16<<<gT, tb, 0, s2>>>(Wo, wo, D_MODEL, D_MODEL);
    transpose_f16<<<dim3(D_FF / 32, D_MODEL / 32), tb, 0, s2>>>(W1, w1, D_MODEL, D_FF);
    transpose_f16<<<dim3(D_MODEL / 32, D_FF / 32), tb, 0, s2>>>(W2, w2, D_FF, D_MODEL);
    cudaEventRecord(evJ, s2);

    // main stream: QKV critical path
    concat_bias<<<D_QKV / 256, tb>>>(bq, bk, bv, bqkv);
    transpose_f16<<<gT, tb>>>(Wq, wqkv,                   D_MODEL, D_MODEL);
    transpose_f16<<<gT, tb>>>(Wk, wqkv + 1024 * 1024,     D_MODEL, D_MODEL);
    transpose_f16<<<gT, tb>>>(Wv, wqkv + 2 * 1024 * 1024, D_MODEL, D_MODEL);
    conv_f16<<<n4_x / 256, tb>>>((const float4*)x, (__half2*)sa, n4_x);
    gemm_mma<false, OUT_HI><<<gQKV, tb, GM_SMEM>>>(sa, wqkv, bqkv, nullptr, qkv,
                                                   M_ROWS, D_QKV, D_MODEL);

    attention_mma<<<dim3(S_LEN / 128, B_SZ * N_HEADS), tb, AT_SMEM>>>(qkv, sb);

    // join before first use of wo/w1/w2
    cudaStreamWaitEvent(0, evJ, 0);

    gemm_mma<false, OUT_F32><<<gProj, tb, GM_SMEM>>>(sb, wo, bo, attn, nullptr,
                                                     M_ROWS, D_MODEL, D_MODEL);
    add_ln_kernel<true><<<M_ROWS, tb>>>(x, attn, g1, be1, h1, sa);
    gemm_mma<true, OUT_HI><<<gFF1, tb, GM_SMEM>>>(sa, w1, b1, nullptr, sb,
                                                  M_ROWS, D_FF, D_MODEL);
    gemm_mma<false, OUT_F32><<<gProj, tb, GM_SMEM>>>(sb, w2, b2, ffn, nullptr,
                                                     M_ROWS, D_MODEL, D_FF);
    add_ln_kernel<false><<<M_ROWS, tb>>>(h1, ffn, g3, be3, out, nullptr);
}

// round 17
// speedup vs baseline: 5.9903x; 1.0190x over previous
#include <cuda_runtime.h>
#include <cuda_fp16.h>
#include <math.h>
#include <stdint.h>

#define B_SZ 8
#define S_LEN 1024
#define D_MODEL 1024
#define N_HEADS 16
#define D_K 64
#define D_FF 4096
#define M_ROWS (B_SZ * S_LEN)
#define D_QKV (3 * D_MODEL)

extern __shared__ char dyn_smem[];

// ---- scratch globals ----
__device__ float g_h1[(size_t)M_ROWS * D_MODEL];
__device__ __half g_res[(size_t)M_ROWS * D_MODEL];   // attn_out fp16, then ffn_out fp16
__device__ __half g_sa[(size_t)M_ROWS * D_MODEL];    // x fp16, then h1 fp16
__device__ __half g_sb[(size_t)M_ROWS * D_FF];       // ctx fp16, then mid fp16
__device__ __half g_qkv[(size_t)M_ROWS * D_QKV];     // fused q|k|v fp16
__device__ __half g_wqkv[(size_t)D_QKV * D_MODEL];   // fused weights [3072,1024] fp16
__device__ float  g_bqkv[D_QKV];                     // fused bias
__device__ __half g_wo[(size_t)D_MODEL * D_MODEL];
__device__ __half g_w1[(size_t)D_FF * D_MODEL];
__device__ __half g_w2[(size_t)D_MODEL * D_FF];

// ---- PTX helpers ----
static __device__ __forceinline__ uint32_t smem_u32(const void* p) {
    uint32_t a;
    asm("{ .reg .u64 t; cvta.to.shared.u64 t, %1; cvt.u32.u64 %0, t; }" : "=r"(a) : "l"(p));
    return a;
}
#define CP_ASYNC16(dst, src) \
    asm volatile("cp.async.cg.shared.global [%0], [%1], 16;" :: "r"((uint32_t)(dst)), "l"(src))
#define CP_COMMIT() asm volatile("cp.async.commit_group;" ::: "memory")
#define LDSM_X4(R0, R1, R2, R3, ADDR) \
    asm volatile("ldmatrix.sync.aligned.m8n8.x4.shared.b16 {%0,%1,%2,%3}, [%4];" \
                 : "=r"(R0), "=r"(R1), "=r"(R2), "=r"(R3) : "r"(ADDR))
#define LDSM_X4_T(R0, R1, R2, R3, ADDR) \
    asm volatile("ldmatrix.sync.aligned.m8n8.x4.trans.shared.b16 {%0,%1,%2,%3}, [%4];" \
                 : "=r"(R0), "=r"(R1), "=r"(R2), "=r"(R3) : "r"(ADDR))

static __device__ __forceinline__ void mma16816(float* d, const uint32_t* a, uint32_t b0, uint32_t b1)
{
    asm volatile(
        "mma.sync.aligned.m16n8k16.row.col.f32.f16.f16.f32 "
        "{%0,%1,%2,%3}, {%4,%5,%6,%7}, {%8,%9}, {%0,%1,%2,%3};"
        : "+f"(d[0]), "+f"(d[1]), "+f"(d[2]), "+f"(d[3])
        : "r"(a[0]), "r"(a[1]), "r"(a[2]), "r"(a[3]), "r"(b0), "r"(b1));
}

static __device__ __forceinline__ uint32_t pack2(float a, float b)
{
    __half2 h = __floats2half2_rn(a, b);
    return *reinterpret_cast<uint32_t*>(&h);
}

// ---------------------------------------------------------------------------
// GEMM (frozen core): C = A @ B^T + bias, fp16 in, 2 CTAs/SM
// ---------------------------------------------------------------------------
#define GM_BUFSZ 20480
#define GM_SMEM  (3 * GM_BUFSZ)
#define OUT_F32 0
#define OUT_HI  1

static __device__ __forceinline__ void load_chunk(
    uint32_t sdst, const __half* aH, const __half* bH, int kb, int K, int tid)
{
#pragma unroll
    for (int j = 0; j < 2; j++) {
        int idx = tid + j * 256;
        int r = idx >> 2;
        int s = idx & 3;
        uint32_t doff = (uint32_t)(r * 80 + s * 16);
        size_t goff = (size_t)r * K + kb;
        CP_ASYNC16(sdst + doff,         (const char*)(aH + goff) + s * 16);
        CP_ASYNC16(sdst + 10240 + doff, (const char*)(bH + goff) + s * 16);
    }
}

template <bool RELU, int OUT>
__global__ __launch_bounds__(256, 2)
void gemm_mma(const __half* __restrict__ Ah, const __half* __restrict__ Bh,
              const float* __restrict__ bias, float* __restrict__ C,
              __half* __restrict__ Ch, int M, int N, int K)
{
    const uint32_t sbase = smem_u32(dyn_smem);
    const int tid = threadIdx.x;
    const int wid = tid >> 5;
    const int lane = tid & 31;
    const int gid = lane >> 2;
    const int tig = lane & 3;
    const int n0 = blockIdx.x * 128;
    const int m0 = blockIdx.y * 128;
    const int wm = (wid >> 2) * 64;
    const int wn = (wid & 3) * 32;
    const int nch = K >> 5;

    const __half* aH = Ah + (size_t)m0 * K;
    const __half* bH = Bh + (size_t)n0 * K;

    const uint32_t offA = (uint32_t)((wm + ((lane >> 3) & 1) * 8 + (lane & 7)) * 80 + (lane >> 4) * 16);
    const uint32_t offB = (uint32_t)((wn + (lane >> 4) * 8 + (lane & 7)) * 80 + ((lane >> 3) & 1) * 16);

    float acc[4][4][4];
#pragma unroll
    for (int mt = 0; mt < 4; mt++)
#pragma unroll
        for (int nt = 0; nt < 4; nt++)
#pragma unroll
            for (int u = 0; u < 4; u++) acc[mt][nt][u] = 0.f;

    load_chunk(sbase,            aH, bH, 0,  K, tid);
    CP_COMMIT();
    load_chunk(sbase + GM_BUFSZ, aH, bH, 32, K, tid);
    CP_COMMIT();

    for (int ch = 0; ch < nch; ch++) {
        if (ch == nch - 1) asm volatile("cp.async.wait_group 0;" ::: "memory");
        else               asm volatile("cp.async.wait_group 1;" ::: "memory");
        __syncthreads();

        if (ch + 2 < nch) {
            load_chunk(sbase + ((ch + 2) % 3) * GM_BUFSZ, aH, bH, (ch + 2) * 32, K, tid);
            CP_COMMIT();
        }

        const uint32_t buf = sbase + (ch % 3) * GM_BUFSZ;
        const uint32_t pA = buf + offA;
        const uint32_t pB = buf + 10240 + offB;

#pragma unroll
        for (int kk = 0; kk < 2; kk++) {
            uint32_t af[4][4], bf[4][2];
#pragma unroll
            for (int mt = 0; mt < 4; mt++)
                LDSM_X4(af[mt][0], af[mt][1], af[mt][2], af[mt][3], pA + mt * 1280 + kk * 32);
#pragma unroll
            for (int nt2 = 0; nt2 < 2; nt2++)
                LDSM_X4(bf[nt2 * 2][0], bf[nt2 * 2][1], bf[nt2 * 2 + 1][0], bf[nt2 * 2 + 1][1],
                        pB + nt2 * 1280 + kk * 32);
#pragma unroll
            for (int nt = 0; nt < 4; nt++)
#pragma unroll
                for (int mt = 0; mt < 4; mt++)
                    mma16816(acc[mt][nt], af[mt], bf[nt][0], bf[nt][1]);
        }
    }

#pragma unroll
    for (int mt = 0; mt < 4; mt++) {
        int r0 = m0 + wm + mt * 16 + gid;
#pragma unroll
        for (int nt = 0; nt < 4; nt++) {
            int c0 = n0 + wn + nt * 8 + tig * 2;
            float bb0 = bias[c0], bb1 = bias[c0 + 1];
            float v0 = acc[mt][nt][0] + bb0;
            float v1 = acc[mt][nt][1] + bb1;
            float v2 = acc[mt][nt][2] + bb0;
            float v3 = acc[mt][nt][3] + bb1;
            if (RELU) {
                v0 = fmaxf(v0, 0.f); v1 = fmaxf(v1, 0.f);
                v2 = fmaxf(v2, 0.f); v3 = fmaxf(v3, 0.f);
            }
            if (OUT == OUT_HI) {
                *(__half2*)(Ch + (size_t)r0 * N + c0)       = __floats2half2_rn(v0, v1);
                *(__half2*)(Ch + (size_t)(r0 + 8) * N + c0) = __floats2half2_rn(v2, v3);
            } else {
                *(float2*)(C + (size_t)r0 * N + c0)       = make_float2(v0, v1);
                *(float2*)(C + (size_t)(r0 + 8) * N + c0) = make_float2(v2, v3);
            }
        }
    }
}

// ---------------------------------------------------------------------------
// prep kernels
// ---------------------------------------------------------------------------
__global__ __launch_bounds__(256)
void concat_bias(const float* __restrict__ bq, const float* __restrict__ bk,
                 const float* __restrict__ bv, float* __restrict__ o)
{
    int i = blockIdx.x * 256 + threadIdx.x;
    const float* src = (i < 1024) ? bq : (i < 2048) ? bk : bv;
    o[i] = src[i & 1023];
}

__global__ __launch_bounds__(256)
void conv_f16(const float4* __restrict__ in, __half2* __restrict__ h2, int n4)
{
    int i = blockIdx.x * 256 + threadIdx.x;
    if (i >= n4) return;
    float4 v = in[i];
    h2[2 * i]     = __floats2half2_rn(v.x, v.y);
    h2[2 * i + 1] = __floats2half2_rn(v.z, v.w);
}

// W[K,N] fp32 -> transposed fp16 [N,K]
__global__ __launch_bounds__(256)
void transpose_f16(const float* __restrict__ W, __half* __restrict__ T, int K, int N)
{
    __shared__ float tile[32][33];
    const int n0 = blockIdx.x * 32;
    const int k0 = blockIdx.y * 32;
    {
        int r  = threadIdx.x >> 3;
        int c4 = (threadIdx.x & 7) * 4;
        float4 v = *(const float4*)(W + (size_t)(k0 + r) * N + n0 + c4);
        tile[r][c4 + 0] = v.x; tile[r][c4 + 1] = v.y;
        tile[r][c4 + 2] = v.z; tile[r][c4 + 3] = v.w;
    }
    __syncthreads();
    {
        int n  = threadIdx.x >> 3;
        int ks = (threadIdx.x & 7) * 4;
        __half2 h0 = __floats2half2_rn(tile[ks][n],     tile[ks + 1][n]);
        __half2 h1 = __floats2half2_rn(tile[ks + 2][n], tile[ks + 3][n]);
        uint2 u;
        u.x = *reinterpret_cast<uint32_t*>(&h0);
        u.y = *reinterpret_cast<uint32_t*>(&h1);
        *(uint2*)(T + (size_t)(n0 + n) * K + k0 + ks) = u;
    }
}

// ---------------------------------------------------------------------------
// Tensor-core causal attention, pure fp16; 2 CTAs/SM, heavy-first scheduling
// ---------------------------------------------------------------------------
#define AT_STR  144
#define AT_QSZ  18432
#define AT_BUF  18432
#define AT_SMEM (AT_QSZ + 3 * AT_BUF)

static __device__ __forceinline__ void load_kv(
    uint32_t dst, const __half* Kh, const __half* Vh, int kb, int tid)
{
#pragma unroll
    for (int j = 0; j < 2; j++) {
        int idx = tid + j * 256;
        int r = idx >> 3;
        int s = idx & 7;
        uint32_t doff = (uint32_t)(r * AT_STR + s * 16);
        size_t g = (size_t)(kb * 64 + r) * D_QKV + s * 8;
        CP_ASYNC16(dst + doff,        Kh + g);
        CP_ASYNC16(dst + 9216 + doff, Vh + g);
    }
}

__global__ __launch_bounds__(256, 2)
void attention_mma(const __half* __restrict__ QKV, __half* __restrict__ Oh)
{
    const uint32_t sb = smem_u32(dyn_smem);
    const int tid = threadIdx.x;
    const int wid = tid >> 5;
    const int lane = tid & 31;
    const int gid = lane >> 2;
    const int tig = lane & 3;
    const int qblk = (int)(gridDim.x - 1 - blockIdx.x);   // heavy blocks first
    const int bh = blockIdx.y;
    const int b = bh >> 4;
    const int h = bh & 15;
    const int q0 = qblk * 128;
    const __half* Qb = QKV + (size_t)(b * S_LEN) * D_QKV + h * D_K;
    const __half* Kb = Qb + D_MODEL;
    const __half* Vb = Qb + 2 * D_MODEL;
    const size_t obase = (size_t)(b * S_LEN) * D_MODEL + h * D_K;
    const int nkb = 2 * qblk + 2;

#pragma unroll
    for (int j = 0; j < 2; j++) {
        int idx = tid + j * 256;
        int r = idx >> 2;
        int s2 = (idx & 3) * 2;
#pragma unroll
        for (int u = 0; u < 2; u++) {
            int s = s2 + u;
            size_t g = (size_t)(q0 + r) * D_QKV + s * 8;
            CP_ASYNC16(sb + (uint32_t)(r * AT_STR + s * 16), Qb + g);
        }
    }
    CP_COMMIT();
    load_kv(sb + AT_QSZ,          Kb, Vb, 0, tid); CP_COMMIT();
    load_kv(sb + AT_QSZ + AT_BUF, Kb, Vb, 1, tid); CP_COMMIT();

    uint32_t qf[4][4];
    float m0 = -INFINITY, m1 = -INFINITY, l0 = 0.f, l1 = 0.f;
    float o[8][4];
#pragma unroll
    for (int t = 0; t < 8; t++)
#pragma unroll
        for (int u = 0; u < 4; u++) o[t][u] = 0.f;

    const uint32_t offQ = sb + (uint32_t)((wid * 16 + ((lane >> 3) & 1) * 8 + (lane & 7)) * AT_STR +
                                          (lane >> 4) * 16);
    const uint32_t offBK = (uint32_t)(((lane >> 4) * 8 + (lane & 7)) * AT_STR + ((lane >> 3) & 1) * 16);
    const uint32_t offBV = (uint32_t)((lane & 15) * AT_STR + (lane >> 4) * 16);

    for (int kb = 0; kb < nkb; kb++) {
        if (kb + 1 < nkb) asm volatile("cp.async.wait_group 1;" ::: "memory");
        else              asm volatile("cp.async.wait_group 0;" ::: "memory");
        __syncthreads();

        if (kb == 0) {
#pragma unroll
            for (int kk = 0; kk < 4; kk++)
                LDSM_X4(qf[kk][0], qf[kk][1], qf[kk][2], qf[kk][3], offQ + kk * 32);
        }
        if (kb + 2 < nkb) {
            load_kv(sb + AT_QSZ + ((kb + 2) % 3) * AT_BUF, Kb, Vb, kb + 2, tid);
            CP_COMMIT();
        }

        const uint32_t kbuf = sb + AT_QSZ + (kb % 3) * AT_BUF;

        float sc[8][4];
#pragma unroll
        for (int t = 0; t < 8; t++)
#pragma unroll
            for (int u = 0; u < 4; u++) sc[t][u] = 0.f;
#pragma unroll
        for (int kk = 0; kk < 4; kk++) {
#pragma unroll
            for (int p = 0; p < 4; p++) {
                uint32_t a = kbuf + p * (16 * AT_STR) + offBK + kk * 32;
                uint32_t h0, h1, h2, h3;
                LDSM_X4(h0, h1, h2, h3, a);
                mma16816(sc[2 * p],     qf[kk], h0, h1);
                mma16816(sc[2 * p + 1], qf[kk], h2, h3);
            }
        }
#pragma unroll
        for (int t = 0; t < 8; t++)
#pragma unroll
            for (int u = 0; u < 4; u++) sc[t][u] *= 0.125f;
        if (kb >= 2 * qblk) {
            int r0 = q0 + wid * 16 + gid;
            int cb = kb * 64 + tig * 2;
#pragma unroll
            for (int t = 0; t < 8; t++) {
                int col = cb + t * 8;
                if (col     >= r0)     sc[t][0] = -1e30f;
                if (col + 1 >= r0)     sc[t][1] = -1e30f;
                if (col     >= r0 + 8) sc[t][2] = -1e30f;
                if (col + 1 >= r0 + 8) sc[t][3] = -1e30f;
            }
        }

        float mx0 = -INFINITY, mx1 = -INFINITY;
#pragma unroll
        for (int t = 0; t < 8; t++) {
            mx0 = fmaxf(mx0, fmaxf(sc[t][0], sc[t][1]));
            mx1 = fmaxf(mx1, fmaxf(sc[t][2], sc[t][3]));
        }
        mx0 = fmaxf(mx0, __shfl_xor_sync(0xffffffffu, mx0, 1));
        mx0 = fmaxf(mx0, __shfl_xor_sync(0xffffffffu, mx0, 2));
        mx1 = fmaxf(mx1, __shfl_xor_sync(0xffffffffu, mx1, 1));
        mx1 = fmaxf(mx1, __shfl_xor_sync(0xffffffffu, mx1, 2));
        float mn0 = fmaxf(m0, mx0);
        float mn1 = fmaxf(m1, mx1);
        float cr0 = __expf(m0 - mn0);
        float cr1 = __expf(m1 - mn1);
        float sum0 = 0.f, sum1 = 0.f;
#pragma unroll
        for (int t = 0; t < 8; t++) {
            sc[t][0] = __expf(sc[t][0] - mn0); sum0 += sc[t][0];
            sc[t][1] = __expf(sc[t][1] - mn0); sum0 += sc[t][1];
            sc[t][2] = __expf(sc[t][2] - mn1); sum1 += sc[t][2];
            sc[t][3] = __expf(sc[t][3] - mn1); sum1 += sc[t][3];
        }
        sum0 += __shfl_xor_sync(0xffffffffu, sum0, 1);
        sum0 += __shfl_xor_sync(0xffffffffu, sum0, 2);
        sum1 += __shfl_xor_sync(0xffffffffu, sum1, 1);
        sum1 += __shfl_xor_sync(0xffffffffu, sum1, 2);
        l0 = l0 * cr0 + sum0;
        l1 = l1 * cr1 + sum1;
        m0 = mn0; m1 = mn1;
#pragma unroll
        for (int t = 0; t < 8; t++) {
            o[t][0] *= cr0; o[t][1] *= cr0;
            o[t][2] *= cr1; o[t][3] *= cr1;
        }

        const uint32_t vbuf = kbuf + 9216;
#pragma unroll
        for (int kk = 0; kk < 4; kk++) {
            uint32_t pf[4];
            pf[0] = pack2(sc[2 * kk][0],     sc[2 * kk][1]);
            pf[1] = pack2(sc[2 * kk][2],     sc[2 * kk][3]);
            pf[2] = pack2(sc[2 * kk + 1][0], sc[2 * kk + 1][1]);
            pf[3] = pack2(sc[2 * kk + 1][2], sc[2 * kk + 1][3]);
#pragma unroll
            for (int dp = 0; dp < 4; dp++) {
                uint32_t a = vbuf + kk * (16 * AT_STR) + dp * 32 + offBV;
                uint32_t v0, v1, v2, v3;
                LDSM_X4_T(v0, v1, v2, v3, a);
                mma16816(o[2 * dp],     pf, v0, v1);
                mma16816(o[2 * dp + 1], pf, v2, v3);
            }
        }
    }

    const int srow0 = q0 + wid * 16 + gid;
    const int srow1 = srow0 + 8;
    const float inv0 = (srow0 == 0) ? 0.f : 1.f / l0;
    const float inv1 = 1.f / l1;
#pragma unroll
    for (int t = 0; t < 8; t++) {
        int d = t * 8 + tig * 2;
        size_t off0 = obase + (size_t)srow0 * D_MODEL + d;
        size_t off1 = obase + (size_t)srow1 * D_MODEL + d;
        *(__half2*)(Oh + off0) = __floats2half2_rn(o[t][0] * inv0, o[t][1] * inv0);
        *(__half2*)(Oh + off1) = __floats2half2_rn(o[t][2] * inv1, o[t][3] * inv1);
    }
}

// ---------------------------------------------------------------------------
// Fused residual add + LayerNorm; residual-add operand Bm is fp16
// ---------------------------------------------------------------------------
template <bool HOUT>
__global__ __launch_bounds__(256)
void add_ln_kernel(const float* __restrict__ A, const __half* __restrict__ Bm,
                   const float* __restrict__ g, const float* __restrict__ beta,
                   float* __restrict__ out, __half* __restrict__ oh)
{
    __shared__ float red_s[8];
    __shared__ float red_q[8];
    __shared__ float stats[2];

    const int row = blockIdx.x;
    const int c = threadIdx.x * 4;
    float4 av = *(const float4*)(A + (size_t)row * D_MODEL + c);
    uint2 bu = *(const uint2*)(Bm + (size_t)row * D_MODEL + c);
    __half2 b01 = *reinterpret_cast<__half2*>(&bu.x);
    __half2 b23 = *reinterpret_cast<__half2*>(&bu.y);
    float v0 = av.x + __low2float(b01),  v1 = av.y + __high2float(b01);
    float v2 = av.z + __low2float(b23),  v3 = av.w + __high2float(b23);

    float s = v0 + v1 + v2 + v3;
    float q = v0 * v0 + v1 * v1 + v2 * v2 + v3 * v3;
#pragma unroll
    for (int off = 16; off > 0; off >>= 1) {
        s += __shfl_xor_sync(0xffffffffu, s, off);
        q += __shfl_xor_sync(0xffffffffu, q, off);
    }
    if ((threadIdx.x & 31) == 0) {
        red_s[threadIdx.x >> 5] = s;
        red_q[threadIdx.x >> 5] = q;
    }
    __syncthreads();
    if (threadIdx.x < 32) {
        float ts = (threadIdx.x < 8) ? red_s[threadIdx.x] : 0.f;
        float tq = (threadIdx.x < 8) ? red_q[threadIdx.x] : 0.f;
#pragma unroll
        for (int off = 4; off > 0; off >>= 1) {
            ts += __shfl_xor_sync(0xffffffffu, ts, off);
            tq += __shfl_xor_sync(0xffffffffu, tq, off);
        }
        if (threadIdx.x == 0) {
            float mu = ts * (1.f / D_MODEL);
            float var = tq * (1.f / D_MODEL) - mu * mu;
            stats[0] = mu;
            stats[1] = rsqrtf(fmaxf(var, 0.f) + 1e-5f);
        }
    }
    __syncthreads();
    const float mu = stats[0];
    const float rstd = stats[1];

    float4 gv = *(const float4*)(g + c);
    float4 bev = *(const float4*)(beta + c);
    float4 ov;
    ov.x = (v0 - mu) * rstd * gv.x + bev.x;
    ov.y = (v1 - mu) * rstd * gv.y + bev.y;
    ov.z = (v2 - mu) * rstd * gv.z + bev.z;
    ov.w = (v3 - mu) * rstd * gv.w + bev.w;
    *(float4*)(out + (size_t)row * D_MODEL + c) = ov;
    if (HOUT) {
        size_t off = (size_t)row * D_MODEL + c;
        *(__half2*)(oh + off)     = __floats2half2_rn(ov.x, ov.y);
        *(__half2*)(oh + off + 2) = __floats2half2_rn(ov.z, ov.w);
    }
}

// ---------------------------------------------------------------------------
static inline float* sym(const void* s) {
    void* p = nullptr;
    cudaGetSymbolAddress(&p, s);
    return (float*)p;
}

extern "C" void kernel_launch(void* const* d_in, const int* in_sizes, int n_in,
                              void* d_out, int out_size)
{
    const float* x   = (const float*)d_in[0];
    const float* Wq  = (const float*)d_in[1];
    const float* bq  = (const float*)d_in[2];
    const float* Wk  = (const float*)d_in[3];
    const float* bk  = (const float*)d_in[4];
    const float* Wv  = (const float*)d_in[5];
    const float* bv  = (const float*)d_in[6];
    const float* Wo  = (const float*)d_in[7];
    const float* bo  = (const float*)d_in[8];
    const float* W1  = (const float*)d_in[9];
    const float* b1  = (const float*)d_in[10];
    const float* W2  = (const float*)d_in[11];
    const float* b2  = (const float*)d_in[12];
    const float* g1  = (const float*)d_in[13];
    const float* be1 = (const float*)d_in[14];
    const float* g3  = (const float*)d_in[15];
    const float* be3 = (const float*)d_in[16];
    float* out = (float*)d_out;

    float* h1   = sym(g_h1);
    float* bqkv = sym(g_bqkv);
    __half* res  = (__half*)sym(g_res);
    __half* sa   = (__half*)sym(g_sa);
    __half* sb   = (__half*)sym(g_sb);
    __half* qkv  = (__half*)sym(g_qkv);
    __half* wqkv = (__half*)sym(g_wqkv);
    __half* wo = (__half*)sym(g_wo);
    __half* w1 = (__half*)sym(g_w1);
    __half* w2 = (__half*)sym(g_w2);

    cudaFuncSetAttribute(attention_mma, cudaFuncAttributeMaxDynamicSharedMemorySize, AT_SMEM);
    cudaFuncSetAttribute(gemm_mma<false, OUT_F32>, cudaFuncAttributeMaxDynamicSharedMemorySize, GM_SMEM);
    cudaFuncSetAttribute(gemm_mma<false, OUT_HI>,  cudaFuncAttributeMaxDynamicSharedMemorySize, GM_SMEM);
    cudaFuncSetAttribute(gemm_mma<true,  OUT_HI>,  cudaFuncAttributeMaxDynamicSharedMemorySize, GM_SMEM);

    static cudaStream_t s2 = nullptr;
    static cudaEvent_t evF = nullptr, evJ = nullptr;
    if (s2 == nullptr) {
        cudaStreamCreateWithFlags(&s2, cudaStreamNonBlocking);
        cudaEventCreateWithFlags(&evF, cudaEventDisableTiming);
        cudaEventCreateWithFlags(&evJ, cudaEventDisableTiming);
    }

    dim3 tb(256);
    const int n4_x = (M_ROWS * D_MODEL) / 4;
    dim3 gProj(D_MODEL / 128, M_ROWS / 128);
    dim3 gQKV(D_QKV / 128, M_ROWS / 128);
    dim3 gFF1(D_FF / 128, M_ROWS / 128);
    dim3 gT(D_MODEL / 32, D_MODEL / 32);

    // fork: Wo/W1/W2 transposes overlap QKV gemm + attention
    cudaEventRecord(evF, 0);
    cudaStreamWaitEvent(s2, evF, 0);
    transpose_f16<<<gT, tb, 0, s2>>>(Wo, wo, D_MODEL, D_MODEL);
    transpose_f16<<<dim3(D_FF / 32, D_MODEL / 32), tb, 0, s2>>>(W1, w1, D_MODEL, D_FF);
    transpose_f16<<<dim3(D_MODEL / 32, D_FF / 32), tb, 0, s2>>>(W2, w2, D_FF, D_MODEL);
    cudaEventRecord(evJ, s2);

    // main stream: QKV critical path
    concat_bias<<<D_QKV / 256, tb>>>(bq, bk, bv, bqkv);
    transpose_f16<<<gT, tb>>>(Wq, wqkv,                   D_MODEL, D_MODEL);
    transpose_f16<<<gT, tb>>>(Wk, wqkv + 1024 * 1024,     D_MODEL, D_MODEL);
    transpose_f16<<<gT, tb>>>(Wv, wqkv + 2 * 1024 * 1024, D_MODEL, D_MODEL);
    conv_f16<<<n4_x / 256, tb>>>((const float4*)x, (__half2*)sa, n4_x);
    gemm_mma<false, OUT_HI><<<gQKV, tb, GM_SMEM>>>(sa, wqkv, bqkv, nullptr, qkv,
                                                   M_ROWS, D_QKV, D_MODEL);

    attention_mma<<<dim3(S_LEN / 128, B_SZ * N_HEADS), tb, AT_SMEM>>>(qkv, sb);

    cudaStreamWaitEvent(0, evJ, 0);

    // attn_out fp16 -> res
    gemm_mma<false, OUT_HI><<<gProj, tb, GM_SMEM>>>(sb, wo, bo, nullptr, res,
                                                    M_ROWS, D_MODEL, D_MODEL);
    add_ln_kernel<true><<<M_ROWS, tb>>>(x, res, g1, be1, h1, sa);
    gemm_mma<true, OUT_HI><<<gFF1, tb, GM_SMEM>>>(sa, w1, b1, nullptr, sb,
                                                  M_ROWS, D_FF, D_MODEL);
    // ffn_out fp16 -> res
    gemm_mma<false, OUT_HI><<<gProj, tb, GM_SMEM>>>(sb, w2, b2, nullptr, res,
                                                    M_ROWS, D_MODEL, D_FF);
    add_ln_kernel<false><<<M_ROWS, tb>>>(h1, res, g3, be3, out, nullptr);
}